// round 1
// baseline (speedup 1.0000x reference)
#include <cuda_runtime.h>

#define DIM 1536
#define HEADS 12
#define HD 128
#define NQ 16384
#define IMG 257
#define TXT 512

// ---------------- scratch (no allocations allowed) ----------------
__device__ float g_Q[(long)NQ * DIM];
__device__ float g_O[(long)NQ * DIM];
__device__ float g_K[(long)TXT * DIM];
__device__ float g_V[(long)TXT * DIM];
__device__ float g_Ki[(long)IMG * DIM];
__device__ float g_Vi[(long)IMG * DIM];

// ---------------- SGEMM: C[M,N] = A[M,K] @ B[K,N] + bias ----------------
// BM=128, BN=64, BK=16, 256 threads, 8x4 per-thread microtile.
__global__ __launch_bounds__(256)
void sgemm_bias(const float* __restrict__ A, const float* __restrict__ B,
                const float* __restrict__ bias, float* __restrict__ C,
                int M, int N, int K) {
    __shared__ float As[16 * 132];   // A^T tile, padded stride 132
    __shared__ float Bs[16 * 64];

    const int m0 = blockIdx.y * 128;
    const int n0 = blockIdx.x * 64;
    const int tid = threadIdx.x;
    const int tx = tid & 15;
    const int ty = tid >> 4;

    const int arow = tid >> 1;        // 0..127
    const int ak   = (tid & 1) * 8;   // 0 or 8
    const int brow = tid >> 4;        // 0..15
    const int bcol = (tid & 15) * 4;  // 0..60

    float acc[8][4];
#pragma unroll
    for (int i = 0; i < 8; ++i)
#pragma unroll
        for (int j = 0; j < 4; ++j) acc[i][j] = 0.f;

    const bool avalid = (m0 + arow) < M;
    const float* Aptr = A + (long)(m0 + arow) * K + ak;
    const float* Bptr = B + (long)brow * N + n0 + bcol;

    for (int k0 = 0; k0 < K; k0 += 16) {
        float4 a0 = make_float4(0.f, 0.f, 0.f, 0.f);
        float4 a1 = make_float4(0.f, 0.f, 0.f, 0.f);
        if (avalid) {
            a0 = *(const float4*)(Aptr + k0);
            a1 = *(const float4*)(Aptr + k0 + 4);
        }
        As[(ak + 0) * 132 + arow] = a0.x;
        As[(ak + 1) * 132 + arow] = a0.y;
        As[(ak + 2) * 132 + arow] = a0.z;
        As[(ak + 3) * 132 + arow] = a0.w;
        As[(ak + 4) * 132 + arow] = a1.x;
        As[(ak + 5) * 132 + arow] = a1.y;
        As[(ak + 6) * 132 + arow] = a1.z;
        As[(ak + 7) * 132 + arow] = a1.w;
        *(float4*)(Bs + brow * 64 + bcol) = *(const float4*)(Bptr + (long)k0 * N);
        __syncthreads();

#pragma unroll
        for (int kk = 0; kk < 16; ++kk) {
            float4 x0 = *(const float4*)(As + kk * 132 + ty * 8);
            float4 x1 = *(const float4*)(As + kk * 132 + ty * 8 + 4);
            float4 y  = *(const float4*)(Bs + kk * 64 + tx * 4);
            float a[8] = {x0.x, x0.y, x0.z, x0.w, x1.x, x1.y, x1.z, x1.w};
            float b[4] = {y.x, y.y, y.z, y.w};
#pragma unroll
            for (int i = 0; i < 8; ++i)
#pragma unroll
                for (int j = 0; j < 4; ++j)
                    acc[i][j] += a[i] * b[j];
        }
        __syncthreads();
    }

    float4 bv = *(const float4*)(bias + n0 + tx * 4);
    float bb[4] = {bv.x, bv.y, bv.z, bv.w};
#pragma unroll
    for (int i = 0; i < 8; ++i) {
        int m = m0 + ty * 8 + i;
        if (m < M) {
            float4 out;
            out.x = acc[i][0] + bb[0];
            out.y = acc[i][1] + bb[1];
            out.z = acc[i][2] + bb[2];
            out.w = acc[i][3] + bb[3];
            *(float4*)(C + (long)m * N + n0 + tx * 4) = out;
        }
    }
}

// ---------------- RMSNorm over DIM=1536 (in place) ----------------
__global__ __launch_bounds__(256)
void rmsnorm_kernel(float* __restrict__ X, const float* __restrict__ g) {
    const int r = blockIdx.x;
    float* x = X + (long)r * DIM;
    const int tid = threadIdx.x;
    float v[6];
    float ss = 0.f;
#pragma unroll
    for (int i = 0; i < 6; ++i) {
        v[i] = x[tid + i * 256];
        ss += v[i] * v[i];
    }
#pragma unroll
    for (int off = 16; off >= 1; off >>= 1)
        ss += __shfl_xor_sync(0xffffffffu, ss, off);
    __shared__ float red[8];
    if ((tid & 31) == 0) red[tid >> 5] = ss;
    __syncthreads();
    float tot = 0.f;
#pragma unroll
    for (int i = 0; i < 8; ++i) tot += red[i];
    const float rms = rsqrtf(tot * (1.f / (float)DIM) + 1e-6f);
#pragma unroll
    for (int i = 0; i < 6; ++i)
        x[tid + i * 256] = v[i] * rms * g[tid + i * 256];
}

// ---------------- Flash attention, two independent softmax segments ----------------
// grid: (NQ/64, HEADS), 256 threads. out = attn(Q,Ktxt,Vtxt) + attn(Q,Kimg,Vimg)
__global__ __launch_bounds__(256)
void attn_kernel(float* __restrict__ Out) {
    const int qb = blockIdx.x;
    const int h  = blockIdx.y;
    const int tid = threadIdx.x;
    const int tx = tid & 15;   // QK: 4 kv cols; PV: 8 d cols
    const int ty = tid >> 4;   // 4 q rows

    extern __shared__ float sm[];
    float* Qs = sm;               // [128][68] transposed: Qs[d*68+q]
    float* Ks = Qs + 128 * 68;    // [128][68] transposed: Ks[d*68+j]
    float* Vs = Ks + 128 * 68;    // [64][128]: Vs[j*128+d]
    float* Ps = Vs + 64 * 128;    // [64][68]:  Ps[q*68+j]

    const float* qbase = g_Q + (long)(qb * 64) * DIM + h * HD;
    for (int idx = tid; idx < 64 * 128; idx += 256) {
        int q = idx >> 7, d = idx & 127;
        Qs[d * 68 + q] = qbase[(long)q * DIM + d];
    }

    float outAcc[4][8];
#pragma unroll
    for (int i = 0; i < 4; ++i)
#pragma unroll
        for (int d = 0; d < 8; ++d) outAcc[i][d] = 0.f;

    const float scale = 0.08838834764831843f;  // 1/sqrt(128)

#pragma unroll 1
    for (int seg = 0; seg < 2; ++seg) {
        const float* Kp = seg ? g_Ki : g_K;
        const float* Vp = seg ? g_Vi : g_V;
        const int len = seg ? IMG : TXT;
        const int ntiles = (len + 63) >> 6;

        float m[4], l[4], o[4][8];
#pragma unroll
        for (int i = 0; i < 4; ++i) {
            m[i] = -1e30f;
            l[i] = 0.f;
#pragma unroll
            for (int d = 0; d < 8; ++d) o[i][d] = 0.f;
        }

        for (int t = 0; t < ntiles; ++t) {
            const int t0 = t * 64;
            __syncthreads();  // previous tile's Ks/Vs/Ps fully consumed
            for (int idx = tid; idx < 64 * 128; idx += 256) {
                int j = idx >> 7, d = idx & 127;
                int tok = t0 + j;
                float kk = 0.f, vv = 0.f;
                if (tok < len) {
                    kk = Kp[(long)tok * DIM + h * HD + d];
                    vv = Vp[(long)tok * DIM + h * HD + d];
                }
                Ks[d * 68 + j] = kk;
                Vs[j * 128 + d] = vv;
            }
            __syncthreads();

            // S = Q K^T (64x64 tile, 4x4 per thread)
            float s[4][4];
#pragma unroll
            for (int i = 0; i < 4; ++i)
#pragma unroll
                for (int j = 0; j < 4; ++j) s[i][j] = 0.f;
#pragma unroll 4
            for (int d = 0; d < 128; ++d) {
                float4 qa = *(const float4*)(Qs + d * 68 + ty * 4);
                float4 kb = *(const float4*)(Ks + d * 68 + tx * 4);
                float a[4] = {qa.x, qa.y, qa.z, qa.w};
                float b[4] = {kb.x, kb.y, kb.z, kb.w};
#pragma unroll
                for (int i = 0; i < 4; ++i)
#pragma unroll
                    for (int j = 0; j < 4; ++j)
                        s[i][j] += a[i] * b[j];
            }

            // online softmax per q row (rows owned by 16-lane groups sharing ty)
#pragma unroll
            for (int i = 0; i < 4; ++i) {
#pragma unroll
                for (int j = 0; j < 4; ++j) {
                    int tok = t0 + tx * 4 + j;
                    s[i][j] = (tok < len) ? s[i][j] * scale : -1e30f;
                }
                float mx = fmaxf(fmaxf(s[i][0], s[i][1]), fmaxf(s[i][2], s[i][3]));
#pragma unroll
                for (int off = 8; off >= 1; off >>= 1)
                    mx = fmaxf(mx, __shfl_xor_sync(0xffffffffu, mx, off, 16));
                float nm = fmaxf(m[i], mx);
                float scl = __expf(m[i] - nm);
                float rs = 0.f;
#pragma unroll
                for (int j = 0; j < 4; ++j) {
                    s[i][j] = __expf(s[i][j] - nm);
                    rs += s[i][j];
                }
#pragma unroll
                for (int off = 8; off >= 1; off >>= 1)
                    rs += __shfl_xor_sync(0xffffffffu, rs, off, 16);
                l[i] = l[i] * scl + rs;
                m[i] = nm;
#pragma unroll
                for (int d = 0; d < 8; ++d) o[i][d] *= scl;
#pragma unroll
                for (int j = 0; j < 4; ++j)
                    Ps[(ty * 4 + i) * 68 + tx * 4 + j] = s[i][j];
            }
            __syncthreads();

            // O += P @ V (each thread: 4 q rows x 8 d cols)
#pragma unroll 2
            for (int kv = 0; kv < 64; ++kv) {
                float4 v0 = *(const float4*)(Vs + kv * 128 + tx * 8);
                float4 v1 = *(const float4*)(Vs + kv * 128 + tx * 8 + 4);
#pragma unroll
                for (int i = 0; i < 4; ++i) {
                    float p = Ps[(ty * 4 + i) * 68 + kv];
                    o[i][0] += p * v0.x; o[i][1] += p * v0.y;
                    o[i][2] += p * v0.z; o[i][3] += p * v0.w;
                    o[i][4] += p * v1.x; o[i][5] += p * v1.y;
                    o[i][6] += p * v1.z; o[i][7] += p * v1.w;
                }
            }
        }

        // finalize this segment: outAcc += O / l
#pragma unroll
        for (int i = 0; i < 4; ++i) {
            float inv = 1.f / l[i];
#pragma unroll
            for (int d = 0; d < 8; ++d) outAcc[i][d] += o[i][d] * inv;
        }
    }

    float* obase = Out + (long)(qb * 64) * DIM + h * HD;
#pragma unroll
    for (int i = 0; i < 4; ++i) {
        float4 w0, w1;
        w0.x = outAcc[i][0]; w0.y = outAcc[i][1]; w0.z = outAcc[i][2]; w0.w = outAcc[i][3];
        w1.x = outAcc[i][4]; w1.y = outAcc[i][5]; w1.z = outAcc[i][6]; w1.w = outAcc[i][7];
        *(float4*)(obase + (long)(ty * 4 + i) * DIM + tx * 8)     = w0;
        *(float4*)(obase + (long)(ty * 4 + i) * DIM + tx * 8 + 4) = w1;
    }
}

// ---------------- launch ----------------
extern "C" void kernel_launch(void* const* d_in, const int* in_sizes, int n_in,
                              void* d_out, int out_size) {
    const float* x       = (const float*)d_in[0];
    const float* context = (const float*)d_in[1];
    // d_in[2] = context_lens (unused by the reference computation)
    const float* Wq  = (const float*)d_in[3];
    const float* bq  = (const float*)d_in[4];
    const float* Wk  = (const float*)d_in[5];
    const float* bk  = (const float*)d_in[6];
    const float* Wv  = (const float*)d_in[7];
    const float* bv  = (const float*)d_in[8];
    const float* Wak = (const float*)d_in[9];
    const float* bak = (const float*)d_in[10];
    const float* Wav = (const float*)d_in[11];
    const float* bav = (const float*)d_in[12];
    const float* Wo  = (const float*)d_in[13];
    const float* bo  = (const float*)d_in[14];
    const float* gq  = (const float*)d_in[15];
    const float* gk  = (const float*)d_in[16];
    const float* gak = (const float*)d_in[17];
    float* out = (float*)d_out;

    float *Qp, *Op, *Kp, *Vp, *Kip, *Vip;
    cudaGetSymbolAddress((void**)&Qp,  g_Q);
    cudaGetSymbolAddress((void**)&Op,  g_O);
    cudaGetSymbolAddress((void**)&Kp,  g_K);
    cudaGetSymbolAddress((void**)&Vp,  g_V);
    cudaGetSymbolAddress((void**)&Kip, g_Ki);
    cudaGetSymbolAddress((void**)&Vip, g_Vi);

    const float* ctx_img = context;                       // first 257 tokens
    const float* ctx_txt = context + (long)IMG * DIM;     // remaining 512 tokens

    dim3 blk(256);

    // Projections
    sgemm_bias<<<dim3(DIM / 64, NQ / 128), blk>>>(x, Wq, bq, Qp, NQ, DIM, DIM);
    sgemm_bias<<<dim3(DIM / 64, TXT / 128), blk>>>(ctx_txt, Wk, bk, Kp, TXT, DIM, DIM);
    sgemm_bias<<<dim3(DIM / 64, TXT / 128), blk>>>(ctx_txt, Wv, bv, Vp, TXT, DIM, DIM);
    sgemm_bias<<<dim3(DIM / 64, (IMG + 127) / 128), blk>>>(ctx_img, Wak, bak, Kip, IMG, DIM, DIM);
    sgemm_bias<<<dim3(DIM / 64, (IMG + 127) / 128), blk>>>(ctx_img, Wav, bav, Vip, IMG, DIM, DIM);

    // RMSNorms (full-DIM norm, before head split)
    rmsnorm_kernel<<<NQ, 256>>>(Qp, gq);
    rmsnorm_kernel<<<TXT, 256>>>(Kp, gk);
    rmsnorm_kernel<<<IMG, 256>>>(Kip, gak);

    // Attention: txt-softmax + img-softmax, summed
    size_t smem = (size_t)(128 * 68 * 2 + 64 * 128 + 64 * 68) * sizeof(float);
    cudaFuncSetAttribute(attn_kernel, cudaFuncAttributeMaxDynamicSharedMemorySize, (int)smem);
    attn_kernel<<<dim3(NQ / 64, HEADS), blk, smem>>>(Op);

    // Output projection
    sgemm_bias<<<dim3(DIM / 64, NQ / 128), blk>>>(Op, Wo, bo, out, NQ, DIM, DIM);
}

// round 4
// speedup vs baseline: 1.4198x; 1.4198x over previous
#include <cuda_runtime.h>
#include <cuda_bf16.h>
#include <cstdint>

#define DIM 1536
#define HEADS 12
#define HD 128
#define NQ 16384
#define IMG 257
#define TXT 512

typedef __nv_bfloat16 bf16;

// ---------------- scratch (no allocations allowed) ----------------
__device__ float g_Q[(long)NQ * DIM];
__device__ float g_K[(long)TXT * DIM];
__device__ float g_V[(long)TXT * DIM];
__device__ float g_Ki[(long)IMG * DIM];
__device__ float g_Vi[(long)IMG * DIM];
__device__ bf16 g_xh[(long)NQ * DIM];
__device__ bf16 g_xl[(long)NQ * DIM];
__device__ bf16 g_Oh[(long)NQ * DIM];
__device__ bf16 g_Ol[(long)NQ * DIM];
__device__ bf16 g_WqhT[(long)DIM * DIM];
__device__ bf16 g_WqlT[(long)DIM * DIM];
__device__ bf16 g_WohT[(long)DIM * DIM];
__device__ bf16 g_WolT[(long)DIM * DIM];

// ---------------- PTX helpers (baseline ISA only: cp.async/ldmatrix/mma) ----------------
__device__ __forceinline__ uint32_t s2u(const void* p) {
    return (uint32_t)__cvta_generic_to_shared(p);
}
__device__ __forceinline__ void cp16(uint32_t s, const void* g) {
    asm volatile("cp.async.cg.shared.global [%0], [%1], 16;\n" :: "r"(s), "l"(g) : "memory");
}
__device__ __forceinline__ void cp_commit() {
    asm volatile("cp.async.commit_group;\n" ::: "memory");
}
template <int N>
__device__ __forceinline__ void cp_wait() {
    asm volatile("cp.async.wait_group %0;\n" :: "n"(N) : "memory");
}
__device__ __forceinline__ void ldsm4(uint32_t* r, uint32_t a) {
    asm volatile("ldmatrix.sync.aligned.m8n8.x4.shared.b16 {%0,%1,%2,%3}, [%4];"
                 : "=r"(r[0]), "=r"(r[1]), "=r"(r[2]), "=r"(r[3]) : "r"(a));
}
__device__ __forceinline__ void mma16816(float* c, const uint32_t* a, const uint32_t* b) {
    asm volatile(
        "mma.sync.aligned.m16n8k16.row.col.f32.bf16.bf16.f32 "
        "{%0,%1,%2,%3}, {%4,%5,%6,%7}, {%8,%9}, {%0,%1,%2,%3};"
        : "+f"(c[0]), "+f"(c[1]), "+f"(c[2]), "+f"(c[3])
        : "r"(a[0]), "r"(a[1]), "r"(a[2]), "r"(a[3]), "r"(b[0]), "r"(b[1]));
}

// ---------------- bf16x3 HMMA GEMM ----------------
// C[M, DIM] = (Ah+Al)[M, DIM] @ (Bh+Bl)^T + bias.  B stored transposed [N][K].
// CTA 128x128, BK=32, 3-stage cp.async pipeline, 8 warps = 4(M) x 2(N).
#define GSTRIDE 80            // bytes per 32-col bf16 row (64B data + 16B pad)
#define TILE_B (128 * GSTRIDE)  // 10240 bytes per operand tile
#define STAGE_B (4 * TILE_B)    // Ah, Al, Bh, Bl
#define NSTAGE 3

__global__ __launch_bounds__(256, 1)
void gemm_mma_bf16x3(const bf16* __restrict__ Ah, const bf16* __restrict__ Al,
                     const bf16* __restrict__ BhT, const bf16* __restrict__ BlT,
                     const float* __restrict__ bias, float* __restrict__ C) {
    extern __shared__ char dynsm[];
    const uint32_t smem0 = s2u(dynsm);
    const int tid = threadIdx.x;
    const int lane = tid & 31;
    const int wid = tid >> 5;
    const int wm = wid & 3;        // 4 M groups of 32 rows
    const int wn = wid >> 2;       // 2 N groups of 64 cols
    const int m0 = blockIdx.y * 128;
    const int n0 = blockIdx.x * 128;

    const bf16* srcs[4] = {Ah, Al, BhT, BlT};
    const int bases[4] = {m0, m0, n0, n0};

    // issue loads for one stage at K offset k0
    auto load_stage = [&](int slot, int k0) {
        const uint32_t sb = smem0 + slot * STAGE_B;
#pragma unroll
        for (int t = 0; t < 8; ++t) {
            const int ch = tid + t * 256;       // 2048 chunks of 16B
            const int tile = ch >> 9;           // uniform per t
            const int idx = ch & 511;
            const int row = idx >> 2;
            const int cb = idx & 3;
            const uint32_t so = sb + tile * TILE_B + row * GSTRIDE + cb * 16;
            const bf16* g = srcs[tile] + (size_t)(bases[tile] + row) * DIM + k0 + cb * 8;
            cp16(so, g);
        }
        cp_commit();
    };

    for (int s = 0; s < NSTAGE; ++s) load_stage(s, s * 32);

    float acc[2][8][4];
#pragma unroll
    for (int mi = 0; mi < 2; ++mi)
#pragma unroll
        for (int nj = 0; nj < 8; ++nj)
#pragma unroll
            for (int r = 0; r < 4; ++r) acc[mi][nj][r] = 0.f;

    const int rowA = wm * 32 + (lane & 15);          // + mi*16
    const int acol = (lane >> 4) * 16;               // byte offset within k16
    const int rowB = wn * 64 + (lane >> 4) * 8 + (lane & 7);  // + ni*16
    const int bcol = ((lane >> 3) & 1) * 16;

    constexpr int NKC = DIM / 32;  // 48
    for (int i = 0; i < NKC; ++i) {
        const int slot = i % NSTAGE;
        const uint32_t sb = smem0 + slot * STAGE_B;
        cp_wait<NSTAGE - 1>();
        __syncthreads();

        const uint32_t aAh = sb + rowA * GSTRIDE + acol;
        const uint32_t aAl = aAh + TILE_B;
        const uint32_t aBh = sb + 2 * TILE_B + rowB * GSTRIDE + bcol;
        const uint32_t aBl = aBh + TILE_B;

#pragma unroll
        for (int k16 = 0; k16 < 2; ++k16) {
            const uint32_t ko = k16 * 32;  // 16 bf16 = 32 bytes
            uint32_t ah[2][4], al[2][4], bh[4][4], bl[4][4];
#pragma unroll
            for (int mi = 0; mi < 2; ++mi) {
                ldsm4(ah[mi], aAh + mi * 16 * GSTRIDE + ko);
                ldsm4(al[mi], aAl + mi * 16 * GSTRIDE + ko);
            }
#pragma unroll
            for (int ni = 0; ni < 4; ++ni) {
                ldsm4(bh[ni], aBh + ni * 16 * GSTRIDE + ko);
                ldsm4(bl[ni], aBl + ni * 16 * GSTRIDE + ko);
            }
#pragma unroll
            for (int mi = 0; mi < 2; ++mi)
#pragma unroll
                for (int nj = 0; nj < 8; ++nj) {
                    const uint32_t* bhp = &bh[nj >> 1][(nj & 1) * 2];
                    const uint32_t* blp = &bl[nj >> 1][(nj & 1) * 2];
                    mma16816(acc[mi][nj], ah[mi], bhp);
                    mma16816(acc[mi][nj], ah[mi], blp);
                    mma16816(acc[mi][nj], al[mi], bhp);
                }
        }
        __syncthreads();
        if (i + NSTAGE < NKC) load_stage(slot, (i + NSTAGE) * 32);
        else cp_commit();
    }

    // epilogue: bias + store fp32
    const int crow0 = m0 + wm * 32 + (lane >> 2);
    const int ccol0 = n0 + wn * 64 + (lane & 3) * 2;
#pragma unroll
    for (int nj = 0; nj < 8; ++nj) {
        const int col = ccol0 + nj * 8;
        const float b0 = bias[col], b1 = bias[col + 1];
#pragma unroll
        for (int mi = 0; mi < 2; ++mi) {
            float* c0 = C + (size_t)(crow0 + mi * 16) * DIM + col;
            float* c1 = c0 + 8 * DIM;
            float2 v0 = make_float2(acc[mi][nj][0] + b0, acc[mi][nj][1] + b1);
            float2 v1 = make_float2(acc[mi][nj][2] + b0, acc[mi][nj][3] + b1);
            *(float2*)c0 = v0;
            *(float2*)c1 = v1;
        }
    }
}

// ---------------- split fp32 -> bf16 hi/lo ----------------
__global__ __launch_bounds__(256)
void split_kernel(const float* __restrict__ X, bf16* __restrict__ H, bf16* __restrict__ L, long n4) {
    long i = ((long)blockIdx.x * 256 + threadIdx.x);
    if (i >= n4) return;
    float4 v = *((const float4*)X + i);
    float vv[4] = {v.x, v.y, v.z, v.w};
    bf16 hh[4], ll[4];
#pragma unroll
    for (int j = 0; j < 4; ++j) {
        hh[j] = __float2bfloat16(vv[j]);
        ll[j] = __float2bfloat16(vv[j] - __bfloat162float(hh[j]));
    }
    __nv_bfloat162* Hp = (__nv_bfloat162*)H + i * 2;
    __nv_bfloat162* Lp = (__nv_bfloat162*)L + i * 2;
    Hp[0] = __nv_bfloat162(hh[0], hh[1]);
    Hp[1] = __nv_bfloat162(hh[2], hh[3]);
    Lp[0] = __nv_bfloat162(ll[0], ll[1]);
    Lp[1] = __nv_bfloat162(ll[2], ll[3]);
}

// ---------------- transpose + split weights: Wt[n][k] = W[k][n] ----------------
__global__ __launch_bounds__(256)
void wsplitT_kernel(const float* __restrict__ W, bf16* __restrict__ Ht, bf16* __restrict__ Lt) {
    __shared__ float t[32][33];
    const int k0 = blockIdx.y * 32, n0 = blockIdx.x * 32;
    const int tx = threadIdx.x, ty = threadIdx.y;  // 32 x 8
#pragma unroll
    for (int j = 0; j < 4; ++j)
        t[ty + j * 8][tx] = W[(size_t)(k0 + ty + j * 8) * DIM + n0 + tx];
    __syncthreads();
#pragma unroll
    for (int j = 0; j < 4; ++j) {
        float v = t[tx][ty + j * 8];
        bf16 h = __float2bfloat16(v);
        bf16 l = __float2bfloat16(v - __bfloat162float(h));
        Ht[(size_t)(n0 + ty + j * 8) * DIM + k0 + tx] = h;
        Lt[(size_t)(n0 + ty + j * 8) * DIM + k0 + tx] = l;
    }
}

// ---------------- small fused SGEMM (K, V, Kimg, Vimg projections) ----------------
struct SmallJobs {
    const float* A[4];
    const float* W[4];
    const float* b[4];
    float* C[4];
    int M[4];
};

__global__ __launch_bounds__(256)
void sgemm_small(SmallJobs jobs) {
    const int z = blockIdx.z;
    const float* A = jobs.A[z];
    const float* B = jobs.W[z];
    const float* bias = jobs.b[z];
    float* C = jobs.C[z];
    const int M = jobs.M[z];
    const int N = DIM, K = DIM;

    const int m0 = blockIdx.y * 128;
    if (m0 >= M) return;
    const int n0 = blockIdx.x * 64;

    __shared__ float As[16 * 132];
    __shared__ float Bs[16 * 64];
    const int tid = threadIdx.x;
    const int tx = tid & 15;
    const int ty = tid >> 4;
    const int arow = tid >> 1;
    const int ak = (tid & 1) * 8;
    const int brow = tid >> 4;
    const int bcol = (tid & 15) * 4;

    float acc[8][4];
#pragma unroll
    for (int i = 0; i < 8; ++i)
#pragma unroll
        for (int j = 0; j < 4; ++j) acc[i][j] = 0.f;

    const bool avalid = (m0 + arow) < M;
    const float* Aptr = A + (long)(m0 + arow) * K + ak;
    const float* Bptr = B + (long)brow * N + n0 + bcol;

    for (int k0 = 0; k0 < K; k0 += 16) {
        float4 a0 = make_float4(0.f, 0.f, 0.f, 0.f);
        float4 a1 = make_float4(0.f, 0.f, 0.f, 0.f);
        if (avalid) {
            a0 = *(const float4*)(Aptr + k0);
            a1 = *(const float4*)(Aptr + k0 + 4);
        }
        As[(ak + 0) * 132 + arow] = a0.x;
        As[(ak + 1) * 132 + arow] = a0.y;
        As[(ak + 2) * 132 + arow] = a0.z;
        As[(ak + 3) * 132 + arow] = a0.w;
        As[(ak + 4) * 132 + arow] = a1.x;
        As[(ak + 5) * 132 + arow] = a1.y;
        As[(ak + 6) * 132 + arow] = a1.z;
        As[(ak + 7) * 132 + arow] = a1.w;
        *(float4*)(Bs + brow * 64 + bcol) = *(const float4*)(Bptr + (long)k0 * N);
        __syncthreads();
#pragma unroll
        for (int kk = 0; kk < 16; ++kk) {
            float4 x0 = *(const float4*)(As + kk * 132 + ty * 8);
            float4 x1 = *(const float4*)(As + kk * 132 + ty * 8 + 4);
            float4 y = *(const float4*)(Bs + kk * 64 + tx * 4);
            float a[8] = {x0.x, x0.y, x0.z, x0.w, x1.x, x1.y, x1.z, x1.w};
            float b[4] = {y.x, y.y, y.z, y.w};
#pragma unroll
            for (int i = 0; i < 8; ++i)
#pragma unroll
                for (int j = 0; j < 4; ++j) acc[i][j] += a[i] * b[j];
        }
        __syncthreads();
    }

    float4 bv = *(const float4*)(bias + n0 + tx * 4);
    float bb[4] = {bv.x, bv.y, bv.z, bv.w};
#pragma unroll
    for (int i = 0; i < 8; ++i) {
        int m = m0 + ty * 8 + i;
        if (m < M) {
            float4 out;
            out.x = acc[i][0] + bb[0];
            out.y = acc[i][1] + bb[1];
            out.z = acc[i][2] + bb[2];
            out.w = acc[i][3] + bb[3];
            *(float4*)(C + (long)m * N + n0 + tx * 4) = out;
        }
    }
}

// ---------------- RMSNorm over DIM=1536 (in place) ----------------
__global__ __launch_bounds__(256)
void rmsnorm_kernel(float* __restrict__ X, const float* __restrict__ g) {
    const int r = blockIdx.x;
    float* x = X + (long)r * DIM;
    const int tid = threadIdx.x;
    float v[6];
    float ss = 0.f;
#pragma unroll
    for (int i = 0; i < 6; ++i) {
        v[i] = x[tid + i * 256];
        ss += v[i] * v[i];
    }
#pragma unroll
    for (int off = 16; off >= 1; off >>= 1)
        ss += __shfl_xor_sync(0xffffffffu, ss, off);
    __shared__ float red[8];
    if ((tid & 31) == 0) red[tid >> 5] = ss;
    __syncthreads();
    float tot = 0.f;
#pragma unroll
    for (int i = 0; i < 8; ++i) tot += red[i];
    const float rms = rsqrtf(tot * (1.f / (float)DIM) + 1e-6f);
#pragma unroll
    for (int i = 0; i < 6; ++i)
        x[tid + i * 256] = v[i] * rms * g[tid + i * 256];
}

// ---------------- Flash attention, two softmax segments; emits bf16 hi/lo ----------------
__global__ __launch_bounds__(256)
void attn_kernel() {
    const int qb = blockIdx.x;
    const int h = blockIdx.y;
    const int tid = threadIdx.x;
    const int tx = tid & 15;
    const int ty = tid >> 4;

    extern __shared__ float sm[];
    float* Qs = sm;
    float* Ks = Qs + 128 * 68;
    float* Vs = Ks + 128 * 68;
    float* Ps = Vs + 64 * 128;

    const float* qbase = g_Q + (long)(qb * 64) * DIM + h * HD;
    for (int idx = tid; idx < 64 * 128; idx += 256) {
        int q = idx >> 7, d = idx & 127;
        Qs[d * 68 + q] = qbase[(long)q * DIM + d];
    }

    float outAcc[4][8];
#pragma unroll
    for (int i = 0; i < 4; ++i)
#pragma unroll
        for (int d = 0; d < 8; ++d) outAcc[i][d] = 0.f;

    const float scale = 0.08838834764831843f;

#pragma unroll 1
    for (int seg = 0; seg < 2; ++seg) {
        const float* Kp = seg ? g_Ki : g_K;
        const float* Vp = seg ? g_Vi : g_V;
        const int len = seg ? IMG : TXT;
        const int ntiles = (len + 63) >> 6;

        float m[4], l[4], o[4][8];
#pragma unroll
        for (int i = 0; i < 4; ++i) {
            m[i] = -1e30f;
            l[i] = 0.f;
#pragma unroll
            for (int d = 0; d < 8; ++d) o[i][d] = 0.f;
        }

        for (int t = 0; t < ntiles; ++t) {
            const int t0 = t * 64;
            __syncthreads();
            for (int idx = tid; idx < 64 * 128; idx += 256) {
                int j = idx >> 7, d = idx & 127;
                int tok = t0 + j;
                float kk = 0.f, vv = 0.f;
                if (tok < len) {
                    kk = Kp[(long)tok * DIM + h * HD + d];
                    vv = Vp[(long)tok * DIM + h * HD + d];
                }
                Ks[d * 68 + j] = kk;
                Vs[j * 128 + d] = vv;
            }
            __syncthreads();

            float s[4][4];
#pragma unroll
            for (int i = 0; i < 4; ++i)
#pragma unroll
                for (int j = 0; j < 4; ++j) s[i][j] = 0.f;
#pragma unroll 4
            for (int d = 0; d < 128; ++d) {
                float4 qa = *(const float4*)(Qs + d * 68 + ty * 4);
                float4 kb = *(const float4*)(Ks + d * 68 + tx * 4);
                float a[4] = {qa.x, qa.y, qa.z, qa.w};
                float b[4] = {kb.x, kb.y, kb.z, kb.w};
#pragma unroll
                for (int i = 0; i < 4; ++i)
#pragma unroll
                    for (int j = 0; j < 4; ++j) s[i][j] += a[i] * b[j];
            }

#pragma unroll
            for (int i = 0; i < 4; ++i) {
#pragma unroll
                for (int j = 0; j < 4; ++j) {
                    int tok = t0 + tx * 4 + j;
                    s[i][j] = (tok < len) ? s[i][j] * scale : -1e30f;
                }
                float mx = fmaxf(fmaxf(s[i][0], s[i][1]), fmaxf(s[i][2], s[i][3]));
#pragma unroll
                for (int off = 8; off >= 1; off >>= 1)
                    mx = fmaxf(mx, __shfl_xor_sync(0xffffffffu, mx, off, 16));
                float nm = fmaxf(m[i], mx);
                float scl = __expf(m[i] - nm);
                float rs = 0.f;
#pragma unroll
                for (int j = 0; j < 4; ++j) {
                    s[i][j] = __expf(s[i][j] - nm);
                    rs += s[i][j];
                }
#pragma unroll
                for (int off = 8; off >= 1; off >>= 1)
                    rs += __shfl_xor_sync(0xffffffffu, rs, off, 16);
                l[i] = l[i] * scl + rs;
                m[i] = nm;
#pragma unroll
                for (int d = 0; d < 8; ++d) o[i][d] *= scl;
#pragma unroll
                for (int j = 0; j < 4; ++j)
                    Ps[(ty * 4 + i) * 68 + tx * 4 + j] = s[i][j];
            }
            __syncthreads();

#pragma unroll 2
            for (int kv = 0; kv < 64; ++kv) {
                float4 v0 = *(const float4*)(Vs + kv * 128 + tx * 8);
                float4 v1 = *(const float4*)(Vs + kv * 128 + tx * 8 + 4);
#pragma unroll
                for (int i = 0; i < 4; ++i) {
                    float p = Ps[(ty * 4 + i) * 68 + kv];
                    o[i][0] += p * v0.x; o[i][1] += p * v0.y;
                    o[i][2] += p * v0.z; o[i][3] += p * v0.w;
                    o[i][4] += p * v1.x; o[i][5] += p * v1.y;
                    o[i][6] += p * v1.z; o[i][7] += p * v1.w;
                }
            }
        }

#pragma unroll
        for (int i = 0; i < 4; ++i) {
            float inv = 1.f / l[i];
#pragma unroll
            for (int d = 0; d < 8; ++d) outAcc[i][d] += o[i][d] * inv;
        }
    }

    // epilogue: split (txt+img) result into bf16 hi/lo for the out-projection
    const long obase = (long)(qb * 64) * DIM + h * HD;
#pragma unroll
    for (int i = 0; i < 4; ++i) {
        long rowo = obase + (long)(ty * 4 + i) * DIM + tx * 8;
        bf16 hh[8], ll[8];
#pragma unroll
        for (int d = 0; d < 8; ++d) {
            float v = outAcc[i][d];
            hh[d] = __float2bfloat16(v);
            ll[d] = __float2bfloat16(v - __bfloat162float(hh[d]));
        }
#pragma unroll
        for (int d = 0; d < 8; d += 2) {
            *(__nv_bfloat162*)(g_Oh + rowo + d) = __nv_bfloat162(hh[d], hh[d + 1]);
            *(__nv_bfloat162*)(g_Ol + rowo + d) = __nv_bfloat162(ll[d], ll[d + 1]);
        }
    }
}

// ---------------- launch ----------------
extern "C" void kernel_launch(void* const* d_in, const int* in_sizes, int n_in,
                              void* d_out, int out_size) {
    const float* x       = (const float*)d_in[0];
    const float* context = (const float*)d_in[1];
    const float* Wq  = (const float*)d_in[3];
    const float* bq  = (const float*)d_in[4];
    const float* Wk  = (const float*)d_in[5];
    const float* bk  = (const float*)d_in[6];
    const float* Wv  = (const float*)d_in[7];
    const float* bv  = (const float*)d_in[8];
    const float* Wak = (const float*)d_in[9];
    const float* bak = (const float*)d_in[10];
    const float* Wav = (const float*)d_in[11];
    const float* bav = (const float*)d_in[12];
    const float* Wo  = (const float*)d_in[13];
    const float* bo  = (const float*)d_in[14];
    const float* gq  = (const float*)d_in[15];
    const float* gk  = (const float*)d_in[16];
    const float* gak = (const float*)d_in[17];
    float* out = (float*)d_out;

    float *Qp, *Kp, *Vp, *Kip, *Vip;
    bf16 *xh, *xl, *Oh, *Ol, *WqhT, *WqlT, *WohT, *WolT;
    cudaGetSymbolAddress((void**)&Qp, g_Q);
    cudaGetSymbolAddress((void**)&Kp, g_K);
    cudaGetSymbolAddress((void**)&Vp, g_V);
    cudaGetSymbolAddress((void**)&Kip, g_Ki);
    cudaGetSymbolAddress((void**)&Vip, g_Vi);
    cudaGetSymbolAddress((void**)&xh, g_xh);
    cudaGetSymbolAddress((void**)&xl, g_xl);
    cudaGetSymbolAddress((void**)&Oh, g_Oh);
    cudaGetSymbolAddress((void**)&Ol, g_Ol);
    cudaGetSymbolAddress((void**)&WqhT, g_WqhT);
    cudaGetSymbolAddress((void**)&WqlT, g_WqlT);
    cudaGetSymbolAddress((void**)&WohT, g_WohT);
    cudaGetSymbolAddress((void**)&WolT, g_WolT);

    const float* ctx_img = context;
    const float* ctx_txt = context + (long)IMG * DIM;

    // 1. conversions
    long n4 = (long)NQ * DIM / 4;
    split_kernel<<<(unsigned)((n4 + 255) / 256), 256>>>(x, xh, xl, n4);
    wsplitT_kernel<<<dim3(DIM / 32, DIM / 32), dim3(32, 8)>>>(Wq, WqhT, WqlT);
    wsplitT_kernel<<<dim3(DIM / 32, DIM / 32), dim3(32, 8)>>>(Wo, WohT, WolT);

    // 2. Q projection on HMMA tensor cores
    const int gemm_smem = NSTAGE * STAGE_B;
    cudaFuncSetAttribute(gemm_mma_bf16x3, cudaFuncAttributeMaxDynamicSharedMemorySize, gemm_smem);
    gemm_mma_bf16x3<<<dim3(DIM / 128, NQ / 128), 256, gemm_smem>>>(xh, xl, WqhT, WqlT, bq, Qp);

    // 3. small KV projections, fused
    SmallJobs jobs;
    jobs.A[0] = ctx_txt; jobs.W[0] = Wk;  jobs.b[0] = bk;  jobs.C[0] = Kp;  jobs.M[0] = TXT;
    jobs.A[1] = ctx_txt; jobs.W[1] = Wv;  jobs.b[1] = bv;  jobs.C[1] = Vp;  jobs.M[1] = TXT;
    jobs.A[2] = ctx_img; jobs.W[2] = Wak; jobs.b[2] = bak; jobs.C[2] = Kip; jobs.M[2] = IMG;
    jobs.A[3] = ctx_img; jobs.W[3] = Wav; jobs.b[3] = bav; jobs.C[3] = Vip; jobs.M[3] = IMG;
    sgemm_small<<<dim3(DIM / 64, 4, 4), 256>>>(jobs);

    // 4. RMSNorms
    rmsnorm_kernel<<<NQ, 256>>>(Qp, gq);
    rmsnorm_kernel<<<TXT, 256>>>(Kp, gk);
    rmsnorm_kernel<<<IMG, 256>>>(Kip, gak);

    // 5. attention (writes bf16 hi/lo of summed result)
    size_t asm_sz = (size_t)(128 * 68 * 2 + 64 * 128 + 64 * 68) * sizeof(float);
    cudaFuncSetAttribute(attn_kernel, cudaFuncAttributeMaxDynamicSharedMemorySize, (int)asm_sz);
    attn_kernel<<<dim3(NQ / 64, HEADS), 256, asm_sz>>>();

    // 6. output projection on HMMA tensor cores
    gemm_mma_bf16x3<<<dim3(DIM / 128, NQ / 128), 256, gemm_smem>>>(Oh, Ol, WohT, WolT, bo, out);
}

// round 5
// speedup vs baseline: 2.9685x; 2.0909x over previous
#include <cuda_runtime.h>
#include <cuda_bf16.h>
#include <cstdint>

#define DIM 1536
#define HEADS 12
#define HD 128
#define NQ 16384
#define IMG 257
#define TXT 512
#define IMGP 320   // img rows padded to multiple of 64

typedef __nv_bfloat16 bf16;

// ---------------- scratch (no allocations allowed) ----------------
__device__ float g_Q[(long)NQ * DIM];
__device__ float g_O[(long)NQ * DIM];          // attention partial (txt segment)
__device__ float g_K[(long)TXT * DIM];
__device__ float g_V[(long)TXT * DIM];
__device__ float g_Ki[(long)IMG * DIM];
__device__ float g_Vi[(long)IMG * DIM];
__device__ bf16 g_xh[(long)NQ * DIM];
__device__ bf16 g_xl[(long)NQ * DIM];
__device__ bf16 g_Qh[(long)NQ * DIM];
__device__ bf16 g_Ql[(long)NQ * DIM];
__device__ bf16 g_Oh[(long)NQ * DIM];
__device__ bf16 g_Ol[(long)NQ * DIM];
__device__ bf16 g_Kh[(long)TXT * DIM];
__device__ bf16 g_Kl[(long)TXT * DIM];
__device__ bf16 g_Vh[(long)TXT * DIM];
__device__ bf16 g_Vl[(long)TXT * DIM];
__device__ bf16 g_Kih[(long)IMGP * DIM];
__device__ bf16 g_Kil[(long)IMGP * DIM];
__device__ bf16 g_Vih[(long)IMGP * DIM];
__device__ bf16 g_Vil[(long)IMGP * DIM];
__device__ bf16 g_WqhT[(long)DIM * DIM];
__device__ bf16 g_WqlT[(long)DIM * DIM];
__device__ bf16 g_WohT[(long)DIM * DIM];
__device__ bf16 g_WolT[(long)DIM * DIM];

// ---------------- PTX helpers ----------------
__device__ __forceinline__ uint32_t s2u(const void* p) {
    return (uint32_t)__cvta_generic_to_shared(p);
}
__device__ __forceinline__ void cp16(uint32_t s, const void* g) {
    asm volatile("cp.async.cg.shared.global [%0], [%1], 16;\n" :: "r"(s), "l"(g) : "memory");
}
__device__ __forceinline__ void cp_commit() {
    asm volatile("cp.async.commit_group;\n" ::: "memory");
}
template <int N>
__device__ __forceinline__ void cp_wait() {
    asm volatile("cp.async.wait_group %0;\n" :: "n"(N) : "memory");
}
__device__ __forceinline__ void ldsm4(uint32_t* r, uint32_t a) {
    asm volatile("ldmatrix.sync.aligned.m8n8.x4.shared.b16 {%0,%1,%2,%3}, [%4];"
                 : "=r"(r[0]), "=r"(r[1]), "=r"(r[2]), "=r"(r[3]) : "r"(a));
}
__device__ __forceinline__ void ldsm4t(uint32_t* r, uint32_t a) {
    asm volatile("ldmatrix.sync.aligned.m8n8.x4.trans.shared.b16 {%0,%1,%2,%3}, [%4];"
                 : "=r"(r[0]), "=r"(r[1]), "=r"(r[2]), "=r"(r[3]) : "r"(a));
}
__device__ __forceinline__ void mma16816(float* c, const uint32_t* a, const uint32_t* b) {
    asm volatile(
        "mma.sync.aligned.m16n8k16.row.col.f32.bf16.bf16.f32 "
        "{%0,%1,%2,%3}, {%4,%5,%6,%7}, {%8,%9}, {%0,%1,%2,%3};"
        : "+f"(c[0]), "+f"(c[1]), "+f"(c[2]), "+f"(c[3])
        : "r"(a[0]), "r"(a[1]), "r"(a[2]), "r"(a[3]), "r"(b[0]), "r"(b[1]));
}
__device__ __forceinline__ uint32_t packbf(float a, float b) {
    __nv_bfloat162 t = __floats2bfloat162_rn(a, b);
    return *(uint32_t*)&t;
}

// ---------------- bf16x3 HMMA GEMM ----------------
#define GSTRIDE 80
#define TILE_B (128 * GSTRIDE)
#define STAGE_B (4 * TILE_B)
#define NSTAGE 2

__global__ __launch_bounds__(256, 2)
void gemm_mma_bf16x3(const bf16* __restrict__ Ah, const bf16* __restrict__ Al,
                     const bf16* __restrict__ BhT, const bf16* __restrict__ BlT,
                     const float* __restrict__ bias, float* __restrict__ C) {
    extern __shared__ char dynsm[];
    const uint32_t smem0 = s2u(dynsm);
    const int tid = threadIdx.x;
    const int lane = tid & 31;
    const int wid = tid >> 5;
    const int wm = wid & 3;
    const int wn = wid >> 2;
    const int m0 = blockIdx.y * 128;
    const int n0 = blockIdx.x * 128;

    const bf16* srcs[4] = {Ah, Al, BhT, BlT};
    const int bases[4] = {m0, m0, n0, n0};

    auto load_stage = [&](int slot, int k0) {
        const uint32_t sb = smem0 + slot * STAGE_B;
#pragma unroll
        for (int t = 0; t < 8; ++t) {
            const int ch = tid + t * 256;
            const int tile = ch >> 9;
            const int idx = ch & 511;
            const int row = idx >> 2;
            const int cb = idx & 3;
            const uint32_t so = sb + tile * TILE_B + row * GSTRIDE + cb * 16;
            const bf16* g = srcs[tile] + (size_t)(bases[tile] + row) * DIM + k0 + cb * 8;
            cp16(so, g);
        }
        cp_commit();
    };

    for (int s = 0; s < NSTAGE; ++s) load_stage(s, s * 32);

    float acc[2][8][4];
#pragma unroll
    for (int mi = 0; mi < 2; ++mi)
#pragma unroll
        for (int nj = 0; nj < 8; ++nj)
#pragma unroll
            for (int r = 0; r < 4; ++r) acc[mi][nj][r] = 0.f;

    const int rowA = wm * 32 + (lane & 15);
    const int acol = (lane >> 4) * 16;
    const int rowB = wn * 64 + (lane >> 4) * 8 + (lane & 7);
    const int bcol = ((lane >> 3) & 1) * 16;

    constexpr int NKC = DIM / 32;
    for (int i = 0; i < NKC; ++i) {
        const int slot = i % NSTAGE;
        const uint32_t sb = smem0 + slot * STAGE_B;
        cp_wait<NSTAGE - 1>();
        __syncthreads();

        const uint32_t aAh = sb + rowA * GSTRIDE + acol;
        const uint32_t aAl = aAh + TILE_B;
        const uint32_t aBh = sb + 2 * TILE_B + rowB * GSTRIDE + bcol;
        const uint32_t aBl = aBh + TILE_B;

#pragma unroll
        for (int k16 = 0; k16 < 2; ++k16) {
            const uint32_t ko = k16 * 32;
            uint32_t ah[2][4], al[2][4], bh[4][4], bl[4][4];
#pragma unroll
            for (int mi = 0; mi < 2; ++mi) {
                ldsm4(ah[mi], aAh + mi * 16 * GSTRIDE + ko);
                ldsm4(al[mi], aAl + mi * 16 * GSTRIDE + ko);
            }
#pragma unroll
            for (int ni = 0; ni < 4; ++ni) {
                ldsm4(bh[ni], aBh + ni * 16 * GSTRIDE + ko);
                ldsm4(bl[ni], aBl + ni * 16 * GSTRIDE + ko);
            }
#pragma unroll
            for (int mi = 0; mi < 2; ++mi)
#pragma unroll
                for (int nj = 0; nj < 8; ++nj) {
                    const uint32_t* bhp = &bh[nj >> 1][(nj & 1) * 2];
                    const uint32_t* blp = &bl[nj >> 1][(nj & 1) * 2];
                    mma16816(acc[mi][nj], ah[mi], bhp);
                    mma16816(acc[mi][nj], ah[mi], blp);
                    mma16816(acc[mi][nj], al[mi], bhp);
                }
        }
        __syncthreads();
        if (i + NSTAGE < NKC) load_stage(slot, (i + NSTAGE) * 32);
        else cp_commit();
    }

    const int crow0 = m0 + wm * 32 + (lane >> 2);
    const int ccol0 = n0 + wn * 64 + (lane & 3) * 2;
#pragma unroll
    for (int nj = 0; nj < 8; ++nj) {
        const int col = ccol0 + nj * 8;
        const float b0 = bias[col], b1 = bias[col + 1];
#pragma unroll
        for (int mi = 0; mi < 2; ++mi) {
            float* c0 = C + (size_t)(crow0 + mi * 16) * DIM + col;
            float* c1 = c0 + 8 * DIM;
            *(float2*)c0 = make_float2(acc[mi][nj][0] + b0, acc[mi][nj][1] + b1);
            *(float2*)c1 = make_float2(acc[mi][nj][2] + b0, acc[mi][nj][3] + b1);
        }
    }
}

// ---------------- split fp32 -> bf16 hi/lo (flat) ----------------
__global__ __launch_bounds__(256)
void split_kernel(const float* __restrict__ X, bf16* __restrict__ H, bf16* __restrict__ L, long n4) {
    long i = ((long)blockIdx.x * 256 + threadIdx.x);
    if (i >= n4) return;
    float4 v = *((const float4*)X + i);
    float vv[4] = {v.x, v.y, v.z, v.w};
    bf16 hh[4], ll[4];
#pragma unroll
    for (int j = 0; j < 4; ++j) {
        hh[j] = __float2bfloat16(vv[j]);
        ll[j] = __float2bfloat16(vv[j] - __bfloat162float(hh[j]));
    }
    __nv_bfloat162* Hp = (__nv_bfloat162*)H + i * 2;
    __nv_bfloat162* Lp = (__nv_bfloat162*)L + i * 2;
    Hp[0] = __nv_bfloat162(hh[0], hh[1]);
    Hp[1] = __nv_bfloat162(hh[2], hh[3]);
    Lp[0] = __nv_bfloat162(ll[0], ll[1]);
    Lp[1] = __nv_bfloat162(ll[2], ll[3]);
}

// ---------------- transpose + split weights ----------------
__global__ __launch_bounds__(256)
void wsplitT_kernel(const float* __restrict__ W, bf16* __restrict__ Ht, bf16* __restrict__ Lt) {
    __shared__ float t[32][33];
    const int k0 = blockIdx.y * 32, n0 = blockIdx.x * 32;
    const int tx = threadIdx.x, ty = threadIdx.y;
#pragma unroll
    for (int j = 0; j < 4; ++j)
        t[ty + j * 8][tx] = W[(size_t)(k0 + ty + j * 8) * DIM + n0 + tx];
    __syncthreads();
#pragma unroll
    for (int j = 0; j < 4; ++j) {
        float v = t[tx][ty + j * 8];
        bf16 h = __float2bfloat16(v);
        bf16 l = __float2bfloat16(v - __bfloat162float(h));
        Ht[(size_t)(n0 + ty + j * 8) * DIM + k0 + tx] = h;
        Lt[(size_t)(n0 + ty + j * 8) * DIM + k0 + tx] = l;
    }
}

// ---------------- small fused SGEMM ----------------
struct SmallJobs {
    const float* A[4];
    const float* W[4];
    const float* b[4];
    float* C[4];
    int M[4];
};

__global__ __launch_bounds__(256)
void sgemm_small(SmallJobs jobs) {
    const int z = blockIdx.z;
    const float* A = jobs.A[z];
    const float* B = jobs.W[z];
    const float* bias = jobs.b[z];
    float* C = jobs.C[z];
    const int M = jobs.M[z];
    const int N = DIM, K = DIM;

    const int m0 = blockIdx.y * 128;
    if (m0 >= M) return;
    const int n0 = blockIdx.x * 64;

    __shared__ float As[16 * 132];
    __shared__ float Bs[16 * 64];
    const int tid = threadIdx.x;
    const int tx = tid & 15;
    const int ty = tid >> 4;
    const int arow = tid >> 1;
    const int ak = (tid & 1) * 8;
    const int brow = tid >> 4;
    const int bcol = (tid & 15) * 4;

    float acc[8][4];
#pragma unroll
    for (int i = 0; i < 8; ++i)
#pragma unroll
        for (int j = 0; j < 4; ++j) acc[i][j] = 0.f;

    const bool avalid = (m0 + arow) < M;
    const float* Aptr = A + (long)(m0 + arow) * K + ak;
    const float* Bptr = B + (long)brow * N + n0 + bcol;

    for (int k0 = 0; k0 < K; k0 += 16) {
        float4 a0 = make_float4(0.f, 0.f, 0.f, 0.f);
        float4 a1 = make_float4(0.f, 0.f, 0.f, 0.f);
        if (avalid) {
            a0 = *(const float4*)(Aptr + k0);
            a1 = *(const float4*)(Aptr + k0 + 4);
        }
        As[(ak + 0) * 132 + arow] = a0.x;
        As[(ak + 1) * 132 + arow] = a0.y;
        As[(ak + 2) * 132 + arow] = a0.z;
        As[(ak + 3) * 132 + arow] = a0.w;
        As[(ak + 4) * 132 + arow] = a1.x;
        As[(ak + 5) * 132 + arow] = a1.y;
        As[(ak + 6) * 132 + arow] = a1.z;
        As[(ak + 7) * 132 + arow] = a1.w;
        *(float4*)(Bs + brow * 64 + bcol) = *(const float4*)(Bptr + (long)k0 * N);
        __syncthreads();
#pragma unroll
        for (int kk = 0; kk < 16; ++kk) {
            float4 x0 = *(const float4*)(As + kk * 132 + ty * 8);
            float4 x1 = *(const float4*)(As + kk * 132 + ty * 8 + 4);
            float4 y = *(const float4*)(Bs + kk * 64 + tx * 4);
            float a[8] = {x0.x, x0.y, x0.z, x0.w, x1.x, x1.y, x1.z, x1.w};
            float b[4] = {y.x, y.y, y.z, y.w};
#pragma unroll
            for (int i = 0; i < 8; ++i)
#pragma unroll
                for (int j = 0; j < 4; ++j) acc[i][j] += a[i] * b[j];
        }
        __syncthreads();
    }

    float4 bv = *(const float4*)(bias + n0 + tx * 4);
    float bb[4] = {bv.x, bv.y, bv.z, bv.w};
#pragma unroll
    for (int i = 0; i < 8; ++i) {
        int m = m0 + ty * 8 + i;
        if (m < M) {
            float4 out;
            out.x = acc[i][0] + bb[0];
            out.y = acc[i][1] + bb[1];
            out.z = acc[i][2] + bb[2];
            out.w = acc[i][3] + bb[3];
            *(float4*)(C + (long)m * N + n0 + tx * 4) = out;
        }
    }
}

// ---------------- RMSNorm + bf16 hi/lo split (optionally scaled), zero-pad rows >= nvalid ----------------
__global__ __launch_bounds__(256)
void rmsnorm_split(const float* __restrict__ X, const float* __restrict__ g, float scale,
                   bf16* __restrict__ H, bf16* __restrict__ L, int nvalid) {
    const int r = blockIdx.x;
    const int tid = threadIdx.x;
    if (r >= nvalid) {
#pragma unroll
        for (int i = 0; i < 6; ++i) {
            H[(long)r * DIM + tid + i * 256] = __float2bfloat16(0.f);
            L[(long)r * DIM + tid + i * 256] = __float2bfloat16(0.f);
        }
        return;
    }
    const float* x = X + (long)r * DIM;
    float v[6];
    float ss = 0.f;
#pragma unroll
    for (int i = 0; i < 6; ++i) {
        v[i] = x[tid + i * 256];
        ss += v[i] * v[i];
    }
#pragma unroll
    for (int off = 16; off >= 1; off >>= 1)
        ss += __shfl_xor_sync(0xffffffffu, ss, off);
    __shared__ float red[8];
    if ((tid & 31) == 0) red[tid >> 5] = ss;
    __syncthreads();
    float tot = 0.f;
#pragma unroll
    for (int i = 0; i < 8; ++i) tot += red[i];
    const float rms = rsqrtf(tot * (1.f / (float)DIM) + 1e-6f);
#pragma unroll
    for (int i = 0; i < 6; ++i) {
        float val = v[i] * rms * g[tid + i * 256] * scale;
        bf16 h = __float2bfloat16(val);
        bf16 l = __float2bfloat16(val - __bfloat162float(h));
        H[(long)r * DIM + tid + i * 256] = h;
        L[(long)r * DIM + tid + i * 256] = l;
    }
}

// ---------------- plain row split with zero-pad ----------------
__global__ __launch_bounds__(256)
void split_pad(const float* __restrict__ X, bf16* __restrict__ H, bf16* __restrict__ L, int nvalid) {
    const int r = blockIdx.x;
    const int tid = threadIdx.x;
#pragma unroll
    for (int i = 0; i < 6; ++i) {
        float val = (r < nvalid) ? X[(long)r * DIM + tid + i * 256] : 0.f;
        bf16 h = __float2bfloat16(val);
        bf16 l = __float2bfloat16(val - __bfloat162float(h));
        H[(long)r * DIM + tid + i * 256] = h;
        L[(long)r * DIM + tid + i * 256] = l;
    }
}

// ---------------- HMMA flash attention, two softmax segments ----------------
// grid (NQ/128, HEADS), 256 threads (8 warps), each warp one m16 band.
#define AST 272  // smem row stride bytes for 128 bf16 + 16B pad

__global__ __launch_bounds__(256, 1)
void attn_mma() {
    extern __shared__ char smem[];
    const uint32_t sQh = s2u(smem);
    const uint32_t sQl = sQh + 128 * AST;
    const uint32_t sKh = sQl + 128 * AST;
    const uint32_t sKl = sKh + 64 * AST;
    const uint32_t sVh = sKl + 64 * AST;
    const uint32_t sVl = sVh + 64 * AST;

    const int tid = threadIdx.x, lane = tid & 31, wid = tid >> 5;
    const int qb = blockIdx.x, h = blockIdx.y;
    const long qrow0 = (long)qb * 128;

    // load Q hi/lo (once)
    {
        const bf16* Qhg = g_Qh + qrow0 * DIM + h * HD;
        const bf16* Qlg = g_Ql + qrow0 * DIM + h * HD;
#pragma unroll
        for (int t = 0; t < 8; ++t) {
            int c = tid + t * 256;   // 2048 chunks
            int r = c >> 4, cb = c & 15;
            cp16(sQh + r * AST + cb * 16, Qhg + (long)r * DIM + cb * 8);
            cp16(sQl + r * AST + cb * 16, Qlg + (long)r * DIM + cb * 8);
        }
        cp_commit();
    }

    // ldmatrix base offsets
    const uint32_t qoff = (uint32_t)((wid * 16 + (lane & 15)) * AST + (lane >> 4) * 16);
    const uint32_t koff = (uint32_t)((((lane >> 4) << 3) + (lane & 7)) * AST + ((lane >> 3) & 1) * 16);
    const uint32_t voff = (uint32_t)(((((lane >> 3) & 1) << 3) + (lane & 7)) * AST + (lane >> 4) * 16);

    const int r0 = lane >> 2;           // warp-local row 0..7 (and +8)
    const int colb = (lane & 3) * 2;    // col pair base within n8 tile

#pragma unroll 1
    for (int seg = 0; seg < 2; ++seg) {
        const bf16 *Khg, *Klg, *Vhg, *Vlg;
        int len, ntiles;
        if (seg == 0) {
            Khg = g_Kh; Klg = g_Kl; Vhg = g_Vh; Vlg = g_Vl;
            len = TXT; ntiles = TXT / 64;
        } else {
            Khg = g_Kih; Klg = g_Kil; Vhg = g_Vih; Vlg = g_Vil;
            len = IMG; ntiles = IMGP / 64;
        }

        float mrow0 = -1e30f, mrow1 = -1e30f, lsum0 = 0.f, lsum1 = 0.f;
        float O[16][4];
#pragma unroll
        for (int j = 0; j < 16; ++j)
#pragma unroll
            for (int e = 0; e < 4; ++e) O[j][e] = 0.f;

#pragma unroll 1
        for (int t = 0; t < ntiles; ++t) {
            __syncthreads();  // prior tile's smem reads complete
            {
                const long kvbase = (long)t * 64 * DIM + h * HD;
#pragma unroll
                for (int tt = 0; tt < 4; ++tt) {
                    int c = tid + tt * 256;   // 1024 chunks
                    int r = c >> 4, cb = c & 15;
                    long go = kvbase + (long)r * DIM + cb * 8;
                    uint32_t so = r * AST + cb * 16;
                    cp16(sKh + so, Khg + go);
                    cp16(sKl + so, Klg + go);
                    cp16(sVh + so, Vhg + go);
                    cp16(sVl + so, Vlg + go);
                }
                cp_commit();
            }
            cp_wait<0>();
            __syncthreads();

            // ---- S = Q K^T (bf16x3) ----
            float S[8][4];
#pragma unroll
            for (int j = 0; j < 8; ++j)
#pragma unroll
                for (int e = 0; e < 4; ++e) S[j][e] = 0.f;
#pragma unroll
            for (int k16 = 0; k16 < 8; ++k16) {
                uint32_t ah[4], al[4];
                ldsm4(ah, sQh + qoff + k16 * 32);
                ldsm4(al, sQl + qoff + k16 * 32);
#pragma unroll
                for (int nt2 = 0; nt2 < 4; ++nt2) {
                    uint32_t bh[4], bl[4];
                    ldsm4(bh, sKh + koff + nt2 * 16 * AST + k16 * 32);
                    ldsm4(bl, sKl + koff + nt2 * 16 * AST + k16 * 32);
                    mma16816(S[2 * nt2], ah, bh);
                    mma16816(S[2 * nt2], ah, bl);
                    mma16816(S[2 * nt2], al, bh);
                    mma16816(S[2 * nt2 + 1], ah, bh + 2);
                    mma16816(S[2 * nt2 + 1], ah, bl + 2);
                    mma16816(S[2 * nt2 + 1], al, bh + 2);
                }
            }

            // ---- online softmax ----
            const int t0 = t * 64;
            if (t0 + 64 > len) {
#pragma unroll
                for (int j = 0; j < 8; ++j) {
#pragma unroll
                    for (int e = 0; e < 2; ++e) {
                        if (t0 + j * 8 + colb + e >= len) {
                            S[j][e] = -1e30f;
                            S[j][2 + e] = -1e30f;
                        }
                    }
                }
            }
            float mx0 = -1e30f, mx1 = -1e30f;
#pragma unroll
            for (int j = 0; j < 8; ++j) {
                mx0 = fmaxf(mx0, fmaxf(S[j][0], S[j][1]));
                mx1 = fmaxf(mx1, fmaxf(S[j][2], S[j][3]));
            }
            mx0 = fmaxf(mx0, __shfl_xor_sync(0xffffffffu, mx0, 1));
            mx0 = fmaxf(mx0, __shfl_xor_sync(0xffffffffu, mx0, 2));
            mx1 = fmaxf(mx1, __shfl_xor_sync(0xffffffffu, mx1, 1));
            mx1 = fmaxf(mx1, __shfl_xor_sync(0xffffffffu, mx1, 2));
            const float nm0 = fmaxf(mrow0, mx0);
            const float nm1 = fmaxf(mrow1, mx1);
            const float sc0 = __expf(mrow0 - nm0);
            const float sc1 = __expf(mrow1 - nm1);
            mrow0 = nm0; mrow1 = nm1;

            uint32_t Ph[8][2], Pl[8][2];
            float rs0 = 0.f, rs1 = 0.f;
#pragma unroll
            for (int j = 0; j < 8; ++j) {
                float p0 = __expf(S[j][0] - nm0);
                float p1 = __expf(S[j][1] - nm0);
                float p2 = __expf(S[j][2] - nm1);
                float p3 = __expf(S[j][3] - nm1);
                rs0 += p0 + p1;
                rs1 += p2 + p3;
                Ph[j][0] = packbf(p0, p1);
                Ph[j][1] = packbf(p2, p3);
                __nv_bfloat162 h01 = *(__nv_bfloat162*)&Ph[j][0];
                __nv_bfloat162 h23 = *(__nv_bfloat162*)&Ph[j][1];
                Pl[j][0] = packbf(p0 - __bfloat162float(h01.x), p1 - __bfloat162float(h01.y));
                Pl[j][1] = packbf(p2 - __bfloat162float(h23.x), p3 - __bfloat162float(h23.y));
            }
            rs0 += __shfl_xor_sync(0xffffffffu, rs0, 1);
            rs0 += __shfl_xor_sync(0xffffffffu, rs0, 2);
            rs1 += __shfl_xor_sync(0xffffffffu, rs1, 1);
            rs1 += __shfl_xor_sync(0xffffffffu, rs1, 2);
            lsum0 = lsum0 * sc0 + rs0;
            lsum1 = lsum1 * sc1 + rs1;
#pragma unroll
            for (int j = 0; j < 16; ++j) {
                O[j][0] *= sc0; O[j][1] *= sc0;
                O[j][2] *= sc1; O[j][3] *= sc1;
            }

            // ---- O += P V (bf16x3) ----
#pragma unroll
            for (int s = 0; s < 4; ++s) {
                uint32_t pah[4] = {Ph[2 * s][0], Ph[2 * s][1], Ph[2 * s + 1][0], Ph[2 * s + 1][1]};
                uint32_t pal[4] = {Pl[2 * s][0], Pl[2 * s][1], Pl[2 * s + 1][0], Pl[2 * s + 1][1]};
#pragma unroll
                for (int d2 = 0; d2 < 8; ++d2) {
                    uint32_t vh[4], vl[4];
                    ldsm4t(vh, sVh + voff + s * 16 * AST + d2 * 32);
                    ldsm4t(vl, sVl + voff + s * 16 * AST + d2 * 32);
                    mma16816(O[2 * d2], pah, vh);
                    mma16816(O[2 * d2], pah, vl);
                    mma16816(O[2 * d2], pal, vh);
                    mma16816(O[2 * d2 + 1], pah, vh + 2);
                    mma16816(O[2 * d2 + 1], pah, vl + 2);
                    mma16816(O[2 * d2 + 1], pal, vh + 2);
                }
            }
        }

        // ---- segment epilogue ----
        const float inv0 = 1.f / lsum0;
        const float inv1 = 1.f / lsum1;
        const long grow0 = qrow0 + wid * 16 + r0;
        const long grow1 = grow0 + 8;
        if (seg == 0) {
#pragma unroll
            for (int j = 0; j < 16; ++j) {
                const int d = h * HD + j * 8 + colb;
                *(float2*)(g_O + grow0 * DIM + d) = make_float2(O[j][0] * inv0, O[j][1] * inv0);
                *(float2*)(g_O + grow1 * DIM + d) = make_float2(O[j][2] * inv1, O[j][3] * inv1);
            }
        } else {
#pragma unroll
            for (int j = 0; j < 16; ++j) {
                const int d = h * HD + j * 8 + colb;
                float2 p0 = *(float2*)(g_O + grow0 * DIM + d);
                float2 p1 = *(float2*)(g_O + grow1 * DIM + d);
                float v0 = p0.x + O[j][0] * inv0;
                float v1 = p0.y + O[j][1] * inv0;
                float v2 = p1.x + O[j][2] * inv1;
                float v3 = p1.y + O[j][3] * inv1;
                bf16 h0 = __float2bfloat16(v0), h1 = __float2bfloat16(v1);
                bf16 h2 = __float2bfloat16(v2), h3 = __float2bfloat16(v3);
                *(__nv_bfloat162*)(g_Oh + grow0 * DIM + d) = __nv_bfloat162(h0, h1);
                *(__nv_bfloat162*)(g_Oh + grow1 * DIM + d) = __nv_bfloat162(h2, h3);
                *(__nv_bfloat162*)(g_Ol + grow0 * DIM + d) =
                    __nv_bfloat162(__float2bfloat16(v0 - __bfloat162float(h0)),
                                   __float2bfloat16(v1 - __bfloat162float(h1)));
                *(__nv_bfloat162*)(g_Ol + grow1 * DIM + d) =
                    __nv_bfloat162(__float2bfloat16(v2 - __bfloat162float(h2)),
                                   __float2bfloat16(v3 - __bfloat162float(h3)));
            }
        }
    }
}

// ---------------- launch ----------------
extern "C" void kernel_launch(void* const* d_in, const int* in_sizes, int n_in,
                              void* d_out, int out_size) {
    const float* x       = (const float*)d_in[0];
    const float* context = (const float*)d_in[1];
    const float* Wq  = (const float*)d_in[3];
    const float* bq  = (const float*)d_in[4];
    const float* Wk  = (const float*)d_in[5];
    const float* bk  = (const float*)d_in[6];
    const float* Wv  = (const float*)d_in[7];
    const float* bv  = (const float*)d_in[8];
    const float* Wak = (const float*)d_in[9];
    const float* bak = (const float*)d_in[10];
    const float* Wav = (const float*)d_in[11];
    const float* bav = (const float*)d_in[12];
    const float* Wo  = (const float*)d_in[13];
    const float* bo  = (const float*)d_in[14];
    const float* gq  = (const float*)d_in[15];
    const float* gk  = (const float*)d_in[16];
    const float* gak = (const float*)d_in[17];
    float* out = (float*)d_out;

    float *Qp, *Kp, *Vp, *Kip, *Vip;
    bf16 *xh, *xl, *Oh, *Ol, *WqhT, *WqlT, *WohT, *WolT;
    bf16 *Qh, *Ql, *Kh, *Kl, *Vh, *Vl, *Kih, *Kil, *Vih, *Vil;
    cudaGetSymbolAddress((void**)&Qp, g_Q);
    cudaGetSymbolAddress((void**)&Kp, g_K);
    cudaGetSymbolAddress((void**)&Vp, g_V);
    cudaGetSymbolAddress((void**)&Kip, g_Ki);
    cudaGetSymbolAddress((void**)&Vip, g_Vi);
    cudaGetSymbolAddress((void**)&xh, g_xh);
    cudaGetSymbolAddress((void**)&xl, g_xl);
    cudaGetSymbolAddress((void**)&Oh, g_Oh);
    cudaGetSymbolAddress((void**)&Ol, g_Ol);
    cudaGetSymbolAddress((void**)&WqhT, g_WqhT);
    cudaGetSymbolAddress((void**)&WqlT, g_WqlT);
    cudaGetSymbolAddress((void**)&WohT, g_WohT);
    cudaGetSymbolAddress((void**)&WolT, g_WolT);
    cudaGetSymbolAddress((void**)&Qh, g_Qh);
    cudaGetSymbolAddress((void**)&Ql, g_Ql);
    cudaGetSymbolAddress((void**)&Kh, g_Kh);
    cudaGetSymbolAddress((void**)&Kl, g_Kl);
    cudaGetSymbolAddress((void**)&Vh, g_Vh);
    cudaGetSymbolAddress((void**)&Vl, g_Vl);
    cudaGetSymbolAddress((void**)&Kih, g_Kih);
    cudaGetSymbolAddress((void**)&Kil, g_Kil);
    cudaGetSymbolAddress((void**)&Vih, g_Vih);
    cudaGetSymbolAddress((void**)&Vil, g_Vil);

    const float* ctx_img = context;
    const float* ctx_txt = context + (long)IMG * DIM;

    // 1. input conversions
    long n4 = (long)NQ * DIM / 4;
    split_kernel<<<(unsigned)((n4 + 255) / 256), 256>>>(x, xh, xl, n4);
    wsplitT_kernel<<<dim3(DIM / 32, DIM / 32), dim3(32, 8)>>>(Wq, WqhT, WqlT);
    wsplitT_kernel<<<dim3(DIM / 32, DIM / 32), dim3(32, 8)>>>(Wo, WohT, WolT);

    // 2. Q projection (HMMA)
    const int gemm_smem = NSTAGE * STAGE_B;
    cudaFuncSetAttribute(gemm_mma_bf16x3, cudaFuncAttributeMaxDynamicSharedMemorySize, gemm_smem);
    gemm_mma_bf16x3<<<dim3(DIM / 128, NQ / 128), 256, gemm_smem>>>(xh, xl, WqhT, WqlT, bq, Qp);

    // 3. small KV projections
    SmallJobs jobs;
    jobs.A[0] = ctx_txt; jobs.W[0] = Wk;  jobs.b[0] = bk;  jobs.C[0] = Kp;  jobs.M[0] = TXT;
    jobs.A[1] = ctx_txt; jobs.W[1] = Wv;  jobs.b[1] = bv;  jobs.C[1] = Vp;  jobs.M[1] = TXT;
    jobs.A[2] = ctx_img; jobs.W[2] = Wak; jobs.b[2] = bak; jobs.C[2] = Kip; jobs.M[2] = IMG;
    jobs.A[3] = ctx_img; jobs.W[3] = Wav; jobs.b[3] = bav; jobs.C[3] = Vip; jobs.M[3] = IMG;
    sgemm_small<<<dim3(DIM / 64, 4, 4), 256>>>(jobs);

    // 4. norms + splits (scale folded into Q)
    const float scale = 0.08838834764831843f;
    rmsnorm_split<<<NQ, 256>>>(Qp, gq, scale, Qh, Ql, NQ);
    rmsnorm_split<<<TXT, 256>>>(Kp, gk, 1.f, Kh, Kl, TXT);
    rmsnorm_split<<<IMGP, 256>>>(Kip, gak, 1.f, Kih, Kil, IMG);
    split_pad<<<TXT, 256>>>(Vp, Vh, Vl, TXT);
    split_pad<<<IMGP, 256>>>(Vip, Vih, Vil, IMG);

    // 5. attention (HMMA)
    const int attn_smem = 2 * 128 * AST + 4 * 64 * AST;
    cudaFuncSetAttribute(attn_mma, cudaFuncAttributeMaxDynamicSharedMemorySize, attn_smem);
    attn_mma<<<dim3(NQ / 128, HEADS), 256, attn_smem>>>();

    // 6. output projection (HMMA)
    gemm_mma_bf16x3<<<dim3(DIM / 128, NQ / 128), 256, gemm_smem>>>(Oh, Ol, WohT, WolT, bo, out);
}

// round 6
// speedup vs baseline: 3.0852x; 1.0393x over previous
#include <cuda_runtime.h>
#include <cuda_bf16.h>
#include <cstdint>

#define DIM 1536
#define HEADS 12
#define HD 128
#define NQ 16384
#define IMG 257
#define TXT 512
#define IMGP 320   // img rows padded to multiple of 64

typedef __nv_bfloat16 bf16;

// ---------------- scratch (no allocations allowed) ----------------
__device__ float g_Q[(long)NQ * DIM];
__device__ float g_O[(long)NQ * DIM];          // attention partial (txt segment)
__device__ float g_K[(long)TXT * DIM];
__device__ float g_V[(long)TXT * DIM];
__device__ float g_Ki[(long)IMG * DIM];
__device__ float g_Vi[(long)IMG * DIM];
__device__ bf16 g_xh[(long)NQ * DIM];
__device__ bf16 g_xl[(long)NQ * DIM];
__device__ bf16 g_Qh[(long)NQ * DIM];
__device__ bf16 g_Ql[(long)NQ * DIM];
__device__ bf16 g_Oh[(long)NQ * DIM];
__device__ bf16 g_Ol[(long)NQ * DIM];
__device__ bf16 g_Kh[(long)TXT * DIM];
__device__ bf16 g_Kl[(long)TXT * DIM];
__device__ bf16 g_Vh[(long)TXT * DIM];
__device__ bf16 g_Vl[(long)TXT * DIM];
__device__ bf16 g_Kih[(long)IMGP * DIM];
__device__ bf16 g_Kil[(long)IMGP * DIM];
__device__ bf16 g_Vih[(long)IMGP * DIM];
__device__ bf16 g_Vil[(long)IMGP * DIM];
__device__ bf16 g_WqhT[(long)DIM * DIM];
__device__ bf16 g_WqlT[(long)DIM * DIM];
__device__ bf16 g_WohT[(long)DIM * DIM];
__device__ bf16 g_WolT[(long)DIM * DIM];

// ---------------- PTX helpers ----------------
__device__ __forceinline__ uint32_t s2u(const void* p) {
    return (uint32_t)__cvta_generic_to_shared(p);
}
__device__ __forceinline__ void cp16(uint32_t s, const void* g) {
    asm volatile("cp.async.cg.shared.global [%0], [%1], 16;\n" :: "r"(s), "l"(g) : "memory");
}
__device__ __forceinline__ void cp_commit() {
    asm volatile("cp.async.commit_group;\n" ::: "memory");
}
template <int N>
__device__ __forceinline__ void cp_wait() {
    asm volatile("cp.async.wait_group %0;\n" :: "n"(N) : "memory");
}
__device__ __forceinline__ void ldsm4(uint32_t* r, uint32_t a) {
    asm volatile("ldmatrix.sync.aligned.m8n8.x4.shared.b16 {%0,%1,%2,%3}, [%4];"
                 : "=r"(r[0]), "=r"(r[1]), "=r"(r[2]), "=r"(r[3]) : "r"(a));
}
__device__ __forceinline__ void ldsm4t(uint32_t* r, uint32_t a) {
    asm volatile("ldmatrix.sync.aligned.m8n8.x4.trans.shared.b16 {%0,%1,%2,%3}, [%4];"
                 : "=r"(r[0]), "=r"(r[1]), "=r"(r[2]), "=r"(r[3]) : "r"(a));
}
__device__ __forceinline__ void mma16816(float* c, const uint32_t* a, const uint32_t* b) {
    asm volatile(
        "mma.sync.aligned.m16n8k16.row.col.f32.bf16.bf16.f32 "
        "{%0,%1,%2,%3}, {%4,%5,%6,%7}, {%8,%9}, {%0,%1,%2,%3};"
        : "+f"(c[0]), "+f"(c[1]), "+f"(c[2]), "+f"(c[3])
        : "r"(a[0]), "r"(a[1]), "r"(a[2]), "r"(a[3]), "r"(b[0]), "r"(b[1]));
}
__device__ __forceinline__ uint32_t packbf(float a, float b) {
    __nv_bfloat162 t = __floats2bfloat162_rn(a, b);
    return *(uint32_t*)&t;
}

// ---------------- bf16x3 HMMA GEMM ----------------
#define GSTRIDE 80
#define TILE_B (128 * GSTRIDE)
#define STAGE_B (4 * TILE_B)
#define NSTAGE 2

__global__ __launch_bounds__(256, 2)
void gemm_mma_bf16x3(const bf16* __restrict__ Ah, const bf16* __restrict__ Al,
                     const bf16* __restrict__ BhT, const bf16* __restrict__ BlT,
                     const float* __restrict__ bias, float* __restrict__ C) {
    extern __shared__ char dynsm[];
    const uint32_t smem0 = s2u(dynsm);
    const int tid = threadIdx.x;
    const int lane = tid & 31;
    const int wid = tid >> 5;
    const int wm = wid & 3;
    const int wn = wid >> 2;
    const int m0 = blockIdx.y * 128;
    const int n0 = blockIdx.x * 128;

    const bf16* srcs[4] = {Ah, Al, BhT, BlT};
    const int bases[4] = {m0, m0, n0, n0};

    auto load_stage = [&](int slot, int k0) {
        const uint32_t sb = smem0 + slot * STAGE_B;
#pragma unroll
        for (int t = 0; t < 8; ++t) {
            const int ch = tid + t * 256;
            const int tile = ch >> 9;
            const int idx = ch & 511;
            const int row = idx >> 2;
            const int cb = idx & 3;
            const uint32_t so = sb + tile * TILE_B + row * GSTRIDE + cb * 16;
            const bf16* g = srcs[tile] + (size_t)(bases[tile] + row) * DIM + k0 + cb * 8;
            cp16(so, g);
        }
        cp_commit();
    };

    for (int s = 0; s < NSTAGE; ++s) load_stage(s, s * 32);

    float acc[2][8][4];
#pragma unroll
    for (int mi = 0; mi < 2; ++mi)
#pragma unroll
        for (int nj = 0; nj < 8; ++nj)
#pragma unroll
            for (int r = 0; r < 4; ++r) acc[mi][nj][r] = 0.f;

    const int rowA = wm * 32 + (lane & 15);
    const int acol = (lane >> 4) * 16;
    const int rowB = wn * 64 + (lane >> 4) * 8 + (lane & 7);
    const int bcol = ((lane >> 3) & 1) * 16;

    constexpr int NKC = DIM / 32;
    for (int i = 0; i < NKC; ++i) {
        const int slot = i % NSTAGE;
        const uint32_t sb = smem0 + slot * STAGE_B;
        cp_wait<NSTAGE - 1>();
        __syncthreads();

        const uint32_t aAh = sb + rowA * GSTRIDE + acol;
        const uint32_t aAl = aAh + TILE_B;
        const uint32_t aBh = sb + 2 * TILE_B + rowB * GSTRIDE + bcol;
        const uint32_t aBl = aBh + TILE_B;

#pragma unroll
        for (int k16 = 0; k16 < 2; ++k16) {
            const uint32_t ko = k16 * 32;
            uint32_t ah[2][4], al[2][4], bh[4][4], bl[4][4];
#pragma unroll
            for (int mi = 0; mi < 2; ++mi) {
                ldsm4(ah[mi], aAh + mi * 16 * GSTRIDE + ko);
                ldsm4(al[mi], aAl + mi * 16 * GSTRIDE + ko);
            }
#pragma unroll
            for (int ni = 0; ni < 4; ++ni) {
                ldsm4(bh[ni], aBh + ni * 16 * GSTRIDE + ko);
                ldsm4(bl[ni], aBl + ni * 16 * GSTRIDE + ko);
            }
#pragma unroll
            for (int mi = 0; mi < 2; ++mi)
#pragma unroll
                for (int nj = 0; nj < 8; ++nj) {
                    const uint32_t* bhp = &bh[nj >> 1][(nj & 1) * 2];
                    const uint32_t* blp = &bl[nj >> 1][(nj & 1) * 2];
                    mma16816(acc[mi][nj], ah[mi], bhp);
                    mma16816(acc[mi][nj], ah[mi], blp);
                    mma16816(acc[mi][nj], al[mi], bhp);
                }
        }
        __syncthreads();
        if (i + NSTAGE < NKC) load_stage(slot, (i + NSTAGE) * 32);
        else cp_commit();
    }

    const int crow0 = m0 + wm * 32 + (lane >> 2);
    const int ccol0 = n0 + wn * 64 + (lane & 3) * 2;
#pragma unroll
    for (int nj = 0; nj < 8; ++nj) {
        const int col = ccol0 + nj * 8;
        const float b0 = bias[col], b1 = bias[col + 1];
#pragma unroll
        for (int mi = 0; mi < 2; ++mi) {
            float* c0 = C + (size_t)(crow0 + mi * 16) * DIM + col;
            float* c1 = c0 + 8 * DIM;
            *(float2*)c0 = make_float2(acc[mi][nj][0] + b0, acc[mi][nj][1] + b1);
            *(float2*)c1 = make_float2(acc[mi][nj][2] + b0, acc[mi][nj][3] + b1);
        }
    }
}

// ---------------- split fp32 -> bf16 hi/lo (flat) ----------------
__global__ __launch_bounds__(256)
void split_kernel(const float* __restrict__ X, bf16* __restrict__ H, bf16* __restrict__ L, long n4) {
    long i = ((long)blockIdx.x * 256 + threadIdx.x);
    if (i >= n4) return;
    float4 v = *((const float4*)X + i);
    float vv[4] = {v.x, v.y, v.z, v.w};
    bf16 hh[4], ll[4];
#pragma unroll
    for (int j = 0; j < 4; ++j) {
        hh[j] = __float2bfloat16(vv[j]);
        ll[j] = __float2bfloat16(vv[j] - __bfloat162float(hh[j]));
    }
    __nv_bfloat162* Hp = (__nv_bfloat162*)H + i * 2;
    __nv_bfloat162* Lp = (__nv_bfloat162*)L + i * 2;
    Hp[0] = __nv_bfloat162(hh[0], hh[1]);
    Hp[1] = __nv_bfloat162(hh[2], hh[3]);
    Lp[0] = __nv_bfloat162(ll[0], ll[1]);
    Lp[1] = __nv_bfloat162(ll[2], ll[3]);
}

// ---------------- transpose + split weights ----------------
__global__ __launch_bounds__(256)
void wsplitT_kernel(const float* __restrict__ W, bf16* __restrict__ Ht, bf16* __restrict__ Lt) {
    __shared__ float t[32][33];
    const int k0 = blockIdx.y * 32, n0 = blockIdx.x * 32;
    const int tx = threadIdx.x, ty = threadIdx.y;
#pragma unroll
    for (int j = 0; j < 4; ++j)
        t[ty + j * 8][tx] = W[(size_t)(k0 + ty + j * 8) * DIM + n0 + tx];
    __syncthreads();
#pragma unroll
    for (int j = 0; j < 4; ++j) {
        float v = t[tx][ty + j * 8];
        bf16 h = __float2bfloat16(v);
        bf16 l = __float2bfloat16(v - __bfloat162float(h));
        Ht[(size_t)(n0 + ty + j * 8) * DIM + k0 + tx] = h;
        Lt[(size_t)(n0 + ty + j * 8) * DIM + k0 + tx] = l;
    }
}

// ---------------- small fused SGEMM ----------------
struct SmallJobs {
    const float* A[4];
    const float* W[4];
    const float* b[4];
    float* C[4];
    int M[4];
};

__global__ __launch_bounds__(256)
void sgemm_small(SmallJobs jobs) {
    const int z = blockIdx.z;
    const float* A = jobs.A[z];
    const float* B = jobs.W[z];
    const float* bias = jobs.b[z];
    float* C = jobs.C[z];
    const int M = jobs.M[z];
    const int N = DIM, K = DIM;

    const int m0 = blockIdx.y * 128;
    if (m0 >= M) return;
    const int n0 = blockIdx.x * 64;

    __shared__ float As[16 * 132];
    __shared__ float Bs[16 * 64];
    const int tid = threadIdx.x;
    const int tx = tid & 15;
    const int ty = tid >> 4;
    const int arow = tid >> 1;
    const int ak = (tid & 1) * 8;
    const int brow = tid >> 4;
    const int bcol = (tid & 15) * 4;

    float acc[8][4];
#pragma unroll
    for (int i = 0; i < 8; ++i)
#pragma unroll
        for (int j = 0; j < 4; ++j) acc[i][j] = 0.f;

    const bool avalid = (m0 + arow) < M;
    const float* Aptr = A + (long)(m0 + arow) * K + ak;
    const float* Bptr = B + (long)brow * N + n0 + bcol;

    for (int k0 = 0; k0 < K; k0 += 16) {
        float4 a0 = make_float4(0.f, 0.f, 0.f, 0.f);
        float4 a1 = make_float4(0.f, 0.f, 0.f, 0.f);
        if (avalid) {
            a0 = *(const float4*)(Aptr + k0);
            a1 = *(const float4*)(Aptr + k0 + 4);
        }
        As[(ak + 0) * 132 + arow] = a0.x;
        As[(ak + 1) * 132 + arow] = a0.y;
        As[(ak + 2) * 132 + arow] = a0.z;
        As[(ak + 3) * 132 + arow] = a0.w;
        As[(ak + 4) * 132 + arow] = a1.x;
        As[(ak + 5) * 132 + arow] = a1.y;
        As[(ak + 6) * 132 + arow] = a1.z;
        As[(ak + 7) * 132 + arow] = a1.w;
        *(float4*)(Bs + brow * 64 + bcol) = *(const float4*)(Bptr + (long)k0 * N);
        __syncthreads();
#pragma unroll
        for (int kk = 0; kk < 16; ++kk) {
            float4 x0 = *(const float4*)(As + kk * 132 + ty * 8);
            float4 x1 = *(const float4*)(As + kk * 132 + ty * 8 + 4);
            float4 y = *(const float4*)(Bs + kk * 64 + tx * 4);
            float a[8] = {x0.x, x0.y, x0.z, x0.w, x1.x, x1.y, x1.z, x1.w};
            float b[4] = {y.x, y.y, y.z, y.w};
#pragma unroll
            for (int i = 0; i < 8; ++i)
#pragma unroll
                for (int j = 0; j < 4; ++j) acc[i][j] += a[i] * b[j];
        }
        __syncthreads();
    }

    float4 bv = *(const float4*)(bias + n0 + tx * 4);
    float bb[4] = {bv.x, bv.y, bv.z, bv.w};
#pragma unroll
    for (int i = 0; i < 8; ++i) {
        int m = m0 + ty * 8 + i;
        if (m < M) {
            float4 out;
            out.x = acc[i][0] + bb[0];
            out.y = acc[i][1] + bb[1];
            out.z = acc[i][2] + bb[2];
            out.w = acc[i][3] + bb[3];
            *(float4*)(C + (long)m * N + n0 + tx * 4) = out;
        }
    }
}

// ---------------- RMSNorm + bf16 hi/lo split (optionally scaled), zero-pad rows >= nvalid ----------------
__global__ __launch_bounds__(256)
void rmsnorm_split(const float* __restrict__ X, const float* __restrict__ g, float scale,
                   bf16* __restrict__ H, bf16* __restrict__ L, int nvalid) {
    const int r = blockIdx.x;
    const int tid = threadIdx.x;
    if (r >= nvalid) {
#pragma unroll
        for (int i = 0; i < 6; ++i) {
            H[(long)r * DIM + tid + i * 256] = __float2bfloat16(0.f);
            L[(long)r * DIM + tid + i * 256] = __float2bfloat16(0.f);
        }
        return;
    }
    const float* x = X + (long)r * DIM;
    float v[6];
    float ss = 0.f;
#pragma unroll
    for (int i = 0; i < 6; ++i) {
        v[i] = x[tid + i * 256];
        ss += v[i] * v[i];
    }
#pragma unroll
    for (int off = 16; off >= 1; off >>= 1)
        ss += __shfl_xor_sync(0xffffffffu, ss, off);
    __shared__ float red[8];
    if ((tid & 31) == 0) red[tid >> 5] = ss;
    __syncthreads();
    float tot = 0.f;
#pragma unroll
    for (int i = 0; i < 8; ++i) tot += red[i];
    const float rms = rsqrtf(tot * (1.f / (float)DIM) + 1e-6f);
#pragma unroll
    for (int i = 0; i < 6; ++i) {
        float val = v[i] * rms * g[tid + i * 256] * scale;
        bf16 h = __float2bfloat16(val);
        bf16 l = __float2bfloat16(val - __bfloat162float(h));
        H[(long)r * DIM + tid + i * 256] = h;
        L[(long)r * DIM + tid + i * 256] = l;
    }
}

// ---------------- plain row split with zero-pad ----------------
__global__ __launch_bounds__(256)
void split_pad(const float* __restrict__ X, bf16* __restrict__ H, bf16* __restrict__ L, int nvalid) {
    const int r = blockIdx.x;
    const int tid = threadIdx.x;
#pragma unroll
    for (int i = 0; i < 6; ++i) {
        float val = (r < nvalid) ? X[(long)r * DIM + tid + i * 256] : 0.f;
        bf16 h = __float2bfloat16(val);
        bf16 l = __float2bfloat16(val - __bfloat162float(h));
        H[(long)r * DIM + tid + i * 256] = h;
        L[(long)r * DIM + tid + i * 256] = l;
    }
}

// ---------------- HMMA flash attention, two softmax segments ----------------
#define AST 272  // smem row stride bytes for 128 bf16 + 16B pad

__global__ __launch_bounds__(256, 1)
void attn_mma() {
    extern __shared__ char smem[];
    const uint32_t sQh = s2u(smem);
    const uint32_t sQl = sQh + 128 * AST;
    const uint32_t sKh = sQl + 128 * AST;
    const uint32_t sKl = sKh + 64 * AST;
    const uint32_t sVh = sKl + 64 * AST;
    const uint32_t sVl = sVh + 64 * AST;

    const int tid = threadIdx.x, lane = tid & 31, wid = tid >> 5;
    const int qb = blockIdx.x, h = blockIdx.y;
    const long qrow0 = (long)qb * 128;

    {
        const bf16* Qhg = g_Qh + qrow0 * DIM + h * HD;
        const bf16* Qlg = g_Ql + qrow0 * DIM + h * HD;
#pragma unroll
        for (int t = 0; t < 8; ++t) {
            int c = tid + t * 256;
            int r = c >> 4, cb = c & 15;
            cp16(sQh + r * AST + cb * 16, Qhg + (long)r * DIM + cb * 8);
            cp16(sQl + r * AST + cb * 16, Qlg + (long)r * DIM + cb * 8);
        }
        cp_commit();
    }

    const uint32_t qoff = (uint32_t)((wid * 16 + (lane & 15)) * AST + (lane >> 4) * 16);
    const uint32_t koff = (uint32_t)((((lane >> 4) << 3) + (lane & 7)) * AST + ((lane >> 3) & 1) * 16);
    const uint32_t voff = (uint32_t)(((((lane >> 3) & 1) << 3) + (lane & 7)) * AST + (lane >> 4) * 16);

    const int r0 = lane >> 2;
    const int colb = (lane & 3) * 2;

#pragma unroll 1
    for (int seg = 0; seg < 2; ++seg) {
        const bf16 *Khg, *Klg, *Vhg, *Vlg;
        int len, ntiles;
        if (seg == 0) {
            Khg = g_Kh; Klg = g_Kl; Vhg = g_Vh; Vlg = g_Vl;
            len = TXT; ntiles = TXT / 64;
        } else {
            Khg = g_Kih; Klg = g_Kil; Vhg = g_Vih; Vlg = g_Vil;
            len = IMG; ntiles = IMGP / 64;
        }

        float mrow0 = -1e30f, mrow1 = -1e30f, lsum0 = 0.f, lsum1 = 0.f;
        float O[16][4];
#pragma unroll
        for (int j = 0; j < 16; ++j)
#pragma unroll
            for (int e = 0; e < 4; ++e) O[j][e] = 0.f;

#pragma unroll 1
        for (int t = 0; t < ntiles; ++t) {
            __syncthreads();
            {
                const long kvbase = (long)t * 64 * DIM + h * HD;
#pragma unroll
                for (int tt = 0; tt < 4; ++tt) {
                    int c = tid + tt * 256;
                    int r = c >> 4, cb = c & 15;
                    long go = kvbase + (long)r * DIM + cb * 8;
                    uint32_t so = r * AST + cb * 16;
                    cp16(sKh + so, Khg + go);
                    cp16(sKl + so, Klg + go);
                    cp16(sVh + so, Vhg + go);
                    cp16(sVl + so, Vlg + go);
                }
                cp_commit();
            }
            cp_wait<0>();
            __syncthreads();

            float S[8][4];
#pragma unroll
            for (int j = 0; j < 8; ++j)
#pragma unroll
                for (int e = 0; e < 4; ++e) S[j][e] = 0.f;
#pragma unroll
            for (int k16 = 0; k16 < 8; ++k16) {
                uint32_t ah[4], al[4];
                ldsm4(ah, sQh + qoff + k16 * 32);
                ldsm4(al, sQl + qoff + k16 * 32);
#pragma unroll
                for (int nt2 = 0; nt2 < 4; ++nt2) {
                    uint32_t bh[4], bl[4];
                    ldsm4(bh, sKh + koff + nt2 * 16 * AST + k16 * 32);
                    ldsm4(bl, sKl + koff + nt2 * 16 * AST + k16 * 32);
                    mma16816(S[2 * nt2], ah, bh);
                    mma16816(S[2 * nt2], ah, bl);
                    mma16816(S[2 * nt2], al, bh);
                    mma16816(S[2 * nt2 + 1], ah, bh + 2);
                    mma16816(S[2 * nt2 + 1], ah, bl + 2);
                    mma16816(S[2 * nt2 + 1], al, bh + 2);
                }
            }

            const int t0 = t * 64;
            if (t0 + 64 > len) {
#pragma unroll
                for (int j = 0; j < 8; ++j) {
#pragma unroll
                    for (int e = 0; e < 2; ++e) {
                        if (t0 + j * 8 + colb + e >= len) {
                            S[j][e] = -1e30f;
                            S[j][2 + e] = -1e30f;
                        }
                    }
                }
            }
            float mx0 = -1e30f, mx1 = -1e30f;
#pragma unroll
            for (int j = 0; j < 8; ++j) {
                mx0 = fmaxf(mx0, fmaxf(S[j][0], S[j][1]));
                mx1 = fmaxf(mx1, fmaxf(S[j][2], S[j][3]));
            }
            mx0 = fmaxf(mx0, __shfl_xor_sync(0xffffffffu, mx0, 1));
            mx0 = fmaxf(mx0, __shfl_xor_sync(0xffffffffu, mx0, 2));
            mx1 = fmaxf(mx1, __shfl_xor_sync(0xffffffffu, mx1, 1));
            mx1 = fmaxf(mx1, __shfl_xor_sync(0xffffffffu, mx1, 2));
            const float nm0 = fmaxf(mrow0, mx0);
            const float nm1 = fmaxf(mrow1, mx1);
            const float sc0 = __expf(mrow0 - nm0);
            const float sc1 = __expf(mrow1 - nm1);
            mrow0 = nm0; mrow1 = nm1;

            uint32_t Ph[8][2], Pl[8][2];
            float rs0 = 0.f, rs1 = 0.f;
#pragma unroll
            for (int j = 0; j < 8; ++j) {
                float p0 = __expf(S[j][0] - nm0);
                float p1 = __expf(S[j][1] - nm0);
                float p2 = __expf(S[j][2] - nm1);
                float p3 = __expf(S[j][3] - nm1);
                rs0 += p0 + p1;
                rs1 += p2 + p3;
                Ph[j][0] = packbf(p0, p1);
                Ph[j][1] = packbf(p2, p3);
                __nv_bfloat162 h01 = *(__nv_bfloat162*)&Ph[j][0];
                __nv_bfloat162 h23 = *(__nv_bfloat162*)&Ph[j][1];
                Pl[j][0] = packbf(p0 - __bfloat162float(h01.x), p1 - __bfloat162float(h01.y));
                Pl[j][1] = packbf(p2 - __bfloat162float(h23.x), p3 - __bfloat162float(h23.y));
            }
            rs0 += __shfl_xor_sync(0xffffffffu, rs0, 1);
            rs0 += __shfl_xor_sync(0xffffffffu, rs0, 2);
            rs1 += __shfl_xor_sync(0xffffffffu, rs1, 1);
            rs1 += __shfl_xor_sync(0xffffffffu, rs1, 2);
            lsum0 = lsum0 * sc0 + rs0;
            lsum1 = lsum1 * sc1 + rs1;
#pragma unroll
            for (int j = 0; j < 16; ++j) {
                O[j][0] *= sc0; O[j][1] *= sc0;
                O[j][2] *= sc1; O[j][3] *= sc1;
            }

#pragma unroll
            for (int s = 0; s < 4; ++s) {
                uint32_t pah[4] = {Ph[2 * s][0], Ph[2 * s][1], Ph[2 * s + 1][0], Ph[2 * s + 1][1]};
                uint32_t pal[4] = {Pl[2 * s][0], Pl[2 * s][1], Pl[2 * s + 1][0], Pl[2 * s + 1][1]};
#pragma unroll
                for (int d2 = 0; d2 < 8; ++d2) {
                    uint32_t vh[4], vl[4];
                    ldsm4t(vh, sVh + voff + s * 16 * AST + d2 * 32);
                    ldsm4t(vl, sVl + voff + s * 16 * AST + d2 * 32);
                    mma16816(O[2 * d2], pah, vh);
                    mma16816(O[2 * d2], pah, vl);
                    mma16816(O[2 * d2], pal, vh);
                    mma16816(O[2 * d2 + 1], pah, vh + 2);
                    mma16816(O[2 * d2 + 1], pah, vl + 2);
                    mma16816(O[2 * d2 + 1], pal, vh + 2);
                }
            }
        }

        const float inv0 = 1.f / lsum0;
        const float inv1 = 1.f / lsum1;
        const long grow0 = qrow0 + wid * 16 + r0;
        const long grow1 = grow0 + 8;
        if (seg == 0) {
#pragma unroll
            for (int j = 0; j < 16; ++j) {
                const int d = h * HD + j * 8 + colb;
                *(float2*)(g_O + grow0 * DIM + d) = make_float2(O[j][0] * inv0, O[j][1] * inv0);
                *(float2*)(g_O + grow1 * DIM + d) = make_float2(O[j][2] * inv1, O[j][3] * inv1);
            }
        } else {
#pragma unroll
            for (int j = 0; j < 16; ++j) {
                const int d = h * HD + j * 8 + colb;
                float2 p0 = *(float2*)(g_O + grow0 * DIM + d);
                float2 p1 = *(float2*)(g_O + grow1 * DIM + d);
                float v0 = p0.x + O[j][0] * inv0;
                float v1 = p0.y + O[j][1] * inv0;
                float v2 = p1.x + O[j][2] * inv1;
                float v3 = p1.y + O[j][3] * inv1;
                bf16 h0 = __float2bfloat16(v0), h1 = __float2bfloat16(v1);
                bf16 h2 = __float2bfloat16(v2), h3 = __float2bfloat16(v3);
                *(__nv_bfloat162*)(g_Oh + grow0 * DIM + d) = __nv_bfloat162(h0, h1);
                *(__nv_bfloat162*)(g_Oh + grow1 * DIM + d) = __nv_bfloat162(h2, h3);
                *(__nv_bfloat162*)(g_Ol + grow0 * DIM + d) =
                    __nv_bfloat162(__float2bfloat16(v0 - __bfloat162float(h0)),
                                   __float2bfloat16(v1 - __bfloat162float(h1)));
                *(__nv_bfloat162*)(g_Ol + grow1 * DIM + d) =
                    __nv_bfloat162(__float2bfloat16(v2 - __bfloat162float(h2)),
                                   __float2bfloat16(v3 - __bfloat162float(h3)));
            }
        }
    }
}

// ---------------- launch ----------------
extern "C" void kernel_launch(void* const* d_in, const int* in_sizes, int n_in,
                              void* d_out, int out_size) {
    const float* x       = (const float*)d_in[0];
    const float* context = (const float*)d_in[1];
    const float* Wq  = (const float*)d_in[3];
    const float* bq  = (const float*)d_in[4];
    const float* Wk  = (const float*)d_in[5];
    const float* bk  = (const float*)d_in[6];
    const float* Wv  = (const float*)d_in[7];
    const float* bv  = (const float*)d_in[8];
    const float* Wak = (const float*)d_in[9];
    const float* bak = (const float*)d_in[10];
    const float* Wav = (const float*)d_in[11];
    const float* bav = (const float*)d_in[12];
    const float* Wo  = (const float*)d_in[13];
    const float* bo  = (const float*)d_in[14];
    const float* gq  = (const float*)d_in[15];
    const float* gk  = (const float*)d_in[16];
    const float* gak = (const float*)d_in[17];
    float* out = (float*)d_out;

    float *Qp, *Kp, *Vp, *Kip, *Vip;
    bf16 *xh, *xl, *Oh, *Ol, *WqhT, *WqlT, *WohT, *WolT;
    bf16 *Qh, *Ql, *Kh, *Kl, *Vh, *Vl, *Kih, *Kil, *Vih, *Vil;
    cudaGetSymbolAddress((void**)&Qp, g_Q);
    cudaGetSymbolAddress((void**)&Kp, g_K);
    cudaGetSymbolAddress((void**)&Vp, g_V);
    cudaGetSymbolAddress((void**)&Kip, g_Ki);
    cudaGetSymbolAddress((void**)&Vip, g_Vi);
    cudaGetSymbolAddress((void**)&xh, g_xh);
    cudaGetSymbolAddress((void**)&xl, g_xl);
    cudaGetSymbolAddress((void**)&Oh, g_Oh);
    cudaGetSymbolAddress((void**)&Ol, g_Ol);
    cudaGetSymbolAddress((void**)&WqhT, g_WqhT);
    cudaGetSymbolAddress((void**)&WqlT, g_WqlT);
    cudaGetSymbolAddress((void**)&WohT, g_WohT);
    cudaGetSymbolAddress((void**)&WolT, g_WolT);
    cudaGetSymbolAddress((void**)&Qh, g_Qh);
    cudaGetSymbolAddress((void**)&Ql, g_Ql);
    cudaGetSymbolAddress((void**)&Kh, g_Kh);
    cudaGetSymbolAddress((void**)&Kl, g_Kl);
    cudaGetSymbolAddress((void**)&Vh, g_Vh);
    cudaGetSymbolAddress((void**)&Vl, g_Vl);
    cudaGetSymbolAddress((void**)&Kih, g_Kih);
    cudaGetSymbolAddress((void**)&Kil, g_Kil);
    cudaGetSymbolAddress((void**)&Vih, g_Vih);
    cudaGetSymbolAddress((void**)&Vil, g_Vil);

    const float* ctx_img = context;
    const float* ctx_txt = context + (long)IMG * DIM;

    // lazily-created side stream + fork/join events (created on the first,
    // non-captured correctness call; reused verbatim inside graph capture).
    static cudaStream_t s1 = nullptr;
    static cudaEvent_t evFork = nullptr, evJoin = nullptr;
    if (s1 == nullptr) {
        cudaStreamCreateWithFlags(&s1, cudaStreamNonBlocking);
        cudaEventCreateWithFlags(&evFork, cudaEventDisableTiming);
        cudaEventCreateWithFlags(&evJoin, cudaEventDisableTiming);
    }

    const float scale = 0.08838834764831843f;
    const int gemm_smem = NSTAGE * STAGE_B;
    cudaFuncSetAttribute(gemm_mma_bf16x3, cudaFuncAttributeMaxDynamicSharedMemorySize, gemm_smem);
    const int attn_smem = 2 * 128 * AST + 4 * 64 * AST;
    cudaFuncSetAttribute(attn_mma, cudaFuncAttributeMaxDynamicSharedMemorySize, attn_smem);

    // ---- fork: side stream handles the whole KV chain + Wo prep ----
    cudaEventRecord(evFork, 0);
    cudaStreamWaitEvent(s1, evFork, 0);

    // main stream: Q chain
    long n4 = (long)NQ * DIM / 4;
    split_kernel<<<(unsigned)((n4 + 255) / 256), 256>>>(x, xh, xl, n4);
    wsplitT_kernel<<<dim3(DIM / 32, DIM / 32), dim3(32, 8)>>>(Wq, WqhT, WqlT);
    gemm_mma_bf16x3<<<dim3(DIM / 128, NQ / 128), 256, gemm_smem>>>(xh, xl, WqhT, WqlT, bq, Qp);
    rmsnorm_split<<<NQ, 256>>>(Qp, gq, scale, Qh, Ql, NQ);

    // side stream: KV projections + norms/splits + Wo transpose-split
    SmallJobs jobs;
    jobs.A[0] = ctx_txt; jobs.W[0] = Wk;  jobs.b[0] = bk;  jobs.C[0] = Kp;  jobs.M[0] = TXT;
    jobs.A[1] = ctx_txt; jobs.W[1] = Wv;  jobs.b[1] = bv;  jobs.C[1] = Vp;  jobs.M[1] = TXT;
    jobs.A[2] = ctx_img; jobs.W[2] = Wak; jobs.b[2] = bak; jobs.C[2] = Kip; jobs.M[2] = IMG;
    jobs.A[3] = ctx_img; jobs.W[3] = Wav; jobs.b[3] = bav; jobs.C[3] = Vip; jobs.M[3] = IMG;
    sgemm_small<<<dim3(DIM / 64, 4, 4), 256, 0, s1>>>(jobs);
    rmsnorm_split<<<TXT, 256, 0, s1>>>(Kp, gk, 1.f, Kh, Kl, TXT);
    rmsnorm_split<<<IMGP, 256, 0, s1>>>(Kip, gak, 1.f, Kih, Kil, IMG);
    split_pad<<<TXT, 256, 0, s1>>>(Vp, Vh, Vl, TXT);
    split_pad<<<IMGP, 256, 0, s1>>>(Vip, Vih, Vil, IMG);
    wsplitT_kernel<<<dim3(DIM / 32, DIM / 32), dim3(32, 8), 0, s1>>>(Wo, WohT, WolT);

    // ---- join ----
    cudaEventRecord(evJoin, s1);
    cudaStreamWaitEvent(0, evJoin, 0);

    // attention + output projection on main stream
    attn_mma<<<dim3(NQ / 128, HEADS), 256, attn_smem>>>();
    gemm_mma_bf16x3<<<dim3(DIM / 128, NQ / 128), 256, gemm_smem>>>(Oh, Ol, WohT, WolT, bo, out);
}

// round 8
// speedup vs baseline: 3.1554x; 1.0227x over previous
#include <cuda_runtime.h>
#include <cuda_bf16.h>
#include <cstdint>

#define DIM 1536
#define HEADS 12
#define HD 128
#define NQ 16384
#define IMG 257
#define TXT 512
#define IMGP 320   // img rows padded to multiple of 64

typedef __nv_bfloat16 bf16;

// ---------------- scratch (no allocations allowed) ----------------
__device__ float g_Q[(long)NQ * DIM];
__device__ float g_O[(long)NQ * DIM];          // attention partial (txt segment)
__device__ float g_K[(long)TXT * DIM];
__device__ float g_V[(long)TXT * DIM];
__device__ float g_Ki[(long)IMG * DIM];
__device__ float g_Vi[(long)IMG * DIM];
__device__ bf16 g_xh[(long)NQ * DIM];
__device__ bf16 g_xl[(long)NQ * DIM];
__device__ bf16 g_Qh[(long)NQ * DIM];
__device__ bf16 g_Ql[(long)NQ * DIM];
__device__ bf16 g_Oh[(long)NQ * DIM];
__device__ bf16 g_Ol[(long)NQ * DIM];
__device__ bf16 g_Kh[(long)TXT * DIM];
__device__ bf16 g_Kl[(long)TXT * DIM];
__device__ bf16 g_Vh[(long)TXT * DIM];
__device__ bf16 g_Vl[(long)TXT * DIM];
__device__ bf16 g_Kih[(long)IMGP * DIM];
__device__ bf16 g_Kil[(long)IMGP * DIM];
__device__ bf16 g_Vih[(long)IMGP * DIM];
__device__ bf16 g_Vil[(long)IMGP * DIM];
__device__ bf16 g_WqhT[(long)DIM * DIM];
__device__ bf16 g_WqlT[(long)DIM * DIM];
__device__ bf16 g_WohT[(long)DIM * DIM];
__device__ bf16 g_WolT[(long)DIM * DIM];

// ---------------- PTX helpers ----------------
__device__ __forceinline__ uint32_t s2u(const void* p) {
    return (uint32_t)__cvta_generic_to_shared(p);
}
__device__ __forceinline__ void cp16(uint32_t s, const void* g) {
    asm volatile("cp.async.cg.shared.global [%0], [%1], 16;\n" :: "r"(s), "l"(g) : "memory");
}
__device__ __forceinline__ void cp_commit() {
    asm volatile("cp.async.commit_group;\n" ::: "memory");
}
template <int N>
__device__ __forceinline__ void cp_wait() {
    asm volatile("cp.async.wait_group %0;\n" :: "n"(N) : "memory");
}
__device__ __forceinline__ void ldsm4(uint32_t* r, uint32_t a) {
    asm volatile("ldmatrix.sync.aligned.m8n8.x4.shared.b16 {%0,%1,%2,%3}, [%4];"
                 : "=r"(r[0]), "=r"(r[1]), "=r"(r[2]), "=r"(r[3]) : "r"(a));
}
__device__ __forceinline__ void ldsm4t(uint32_t* r, uint32_t a) {
    asm volatile("ldmatrix.sync.aligned.m8n8.x4.trans.shared.b16 {%0,%1,%2,%3}, [%4];"
                 : "=r"(r[0]), "=r"(r[1]), "=r"(r[2]), "=r"(r[3]) : "r"(a));
}
__device__ __forceinline__ void mma16816(float* c, const uint32_t* a, const uint32_t* b) {
    asm volatile(
        "mma.sync.aligned.m16n8k16.row.col.f32.bf16.bf16.f32 "
        "{%0,%1,%2,%3}, {%4,%5,%6,%7}, {%8,%9}, {%0,%1,%2,%3};"
        : "+f"(c[0]), "+f"(c[1]), "+f"(c[2]), "+f"(c[3])
        : "r"(a[0]), "r"(a[1]), "r"(a[2]), "r"(a[3]), "r"(b[0]), "r"(b[1]));
}
__device__ __forceinline__ uint32_t packbf(float a, float b) {
    __nv_bfloat162 t = __floats2bfloat162_rn(a, b);
    return *(uint32_t*)&t;
}

// ---------------- bf16x3 HMMA GEMM ----------------
#define GSTRIDE 80
#define TILE_B (128 * GSTRIDE)
#define STAGE_B (4 * TILE_B)
#define NSTAGE 2

__global__ __launch_bounds__(256, 2)
void gemm_mma_bf16x3(const bf16* __restrict__ Ah, const bf16* __restrict__ Al,
                     const bf16* __restrict__ BhT, const bf16* __restrict__ BlT,
                     const float* __restrict__ bias, float* __restrict__ C) {
    extern __shared__ char dynsm[];
    const uint32_t smem0 = s2u(dynsm);
    const int tid = threadIdx.x;
    const int lane = tid & 31;
    const int wid = tid >> 5;
    const int wm = wid & 3;
    const int wn = wid >> 2;
    const int m0 = blockIdx.y * 128;
    const int n0 = blockIdx.x * 128;

    const bf16* srcs[4] = {Ah, Al, BhT, BlT};
    const int bases[4] = {m0, m0, n0, n0};

    auto load_stage = [&](int slot, int k0) {
        const uint32_t sb = smem0 + slot * STAGE_B;
#pragma unroll
        for (int t = 0; t < 8; ++t) {
            const int ch = tid + t * 256;
            const int tile = ch >> 9;
            const int idx = ch & 511;
            const int row = idx >> 2;
            const int cb = idx & 3;
            const uint32_t so = sb + tile * TILE_B + row * GSTRIDE + cb * 16;
            const bf16* g = srcs[tile] + (size_t)(bases[tile] + row) * DIM + k0 + cb * 8;
            cp16(so, g);
        }
        cp_commit();
    };

    for (int s = 0; s < NSTAGE; ++s) load_stage(s, s * 32);

    float acc[2][8][4];
#pragma unroll
    for (int mi = 0; mi < 2; ++mi)
#pragma unroll
        for (int nj = 0; nj < 8; ++nj)
#pragma unroll
            for (int r = 0; r < 4; ++r) acc[mi][nj][r] = 0.f;

    const int rowA = wm * 32 + (lane & 15);
    const int acol = (lane >> 4) * 16;
    const int rowB = wn * 64 + (lane >> 4) * 8 + (lane & 7);
    const int bcol = ((lane >> 3) & 1) * 16;

    constexpr int NKC = DIM / 32;
    for (int i = 0; i < NKC; ++i) {
        const int slot = i % NSTAGE;
        const uint32_t sb = smem0 + slot * STAGE_B;
        cp_wait<NSTAGE - 1>();
        __syncthreads();

        const uint32_t aAh = sb + rowA * GSTRIDE + acol;
        const uint32_t aAl = aAh + TILE_B;
        const uint32_t aBh = sb + 2 * TILE_B + rowB * GSTRIDE + bcol;
        const uint32_t aBl = aBh + TILE_B;

#pragma unroll
        for (int k16 = 0; k16 < 2; ++k16) {
            const uint32_t ko = k16 * 32;
            uint32_t ah[2][4], al[2][4], bh[4][4], bl[4][4];
#pragma unroll
            for (int mi = 0; mi < 2; ++mi) {
                ldsm4(ah[mi], aAh + mi * 16 * GSTRIDE + ko);
                ldsm4(al[mi], aAl + mi * 16 * GSTRIDE + ko);
            }
#pragma unroll
            for (int ni = 0; ni < 4; ++ni) {
                ldsm4(bh[ni], aBh + ni * 16 * GSTRIDE + ko);
                ldsm4(bl[ni], aBl + ni * 16 * GSTRIDE + ko);
            }
#pragma unroll
            for (int mi = 0; mi < 2; ++mi)
#pragma unroll
                for (int nj = 0; nj < 8; ++nj) {
                    const uint32_t* bhp = &bh[nj >> 1][(nj & 1) * 2];
                    const uint32_t* blp = &bl[nj >> 1][(nj & 1) * 2];
                    mma16816(acc[mi][nj], ah[mi], bhp);
                    mma16816(acc[mi][nj], ah[mi], blp);
                    mma16816(acc[mi][nj], al[mi], bhp);
                }
        }
        __syncthreads();
        if (i + NSTAGE < NKC) load_stage(slot, (i + NSTAGE) * 32);
        else cp_commit();
    }

    const int crow0 = m0 + wm * 32 + (lane >> 2);
    const int ccol0 = n0 + wn * 64 + (lane & 3) * 2;
#pragma unroll
    for (int nj = 0; nj < 8; ++nj) {
        const int col = ccol0 + nj * 8;
        const float b0 = bias[col], b1 = bias[col + 1];
#pragma unroll
        for (int mi = 0; mi < 2; ++mi) {
            float* c0 = C + (size_t)(crow0 + mi * 16) * DIM + col;
            float* c1 = c0 + 8 * DIM;
            *(float2*)c0 = make_float2(acc[mi][nj][0] + b0, acc[mi][nj][1] + b1);
            *(float2*)c1 = make_float2(acc[mi][nj][2] + b0, acc[mi][nj][3] + b1);
        }
    }
}

// ---------------- split fp32 -> bf16 hi/lo (flat) ----------------
__global__ __launch_bounds__(256)
void split_kernel(const float* __restrict__ X, bf16* __restrict__ H, bf16* __restrict__ L, long n4) {
    long i = ((long)blockIdx.x * 256 + threadIdx.x);
    if (i >= n4) return;
    float4 v = *((const float4*)X + i);
    float vv[4] = {v.x, v.y, v.z, v.w};
    bf16 hh[4], ll[4];
#pragma unroll
    for (int j = 0; j < 4; ++j) {
        hh[j] = __float2bfloat16(vv[j]);
        ll[j] = __float2bfloat16(vv[j] - __bfloat162float(hh[j]));
    }
    __nv_bfloat162* Hp = (__nv_bfloat162*)H + i * 2;
    __nv_bfloat162* Lp = (__nv_bfloat162*)L + i * 2;
    Hp[0] = __nv_bfloat162(hh[0], hh[1]);
    Hp[1] = __nv_bfloat162(hh[2], hh[3]);
    Lp[0] = __nv_bfloat162(ll[0], ll[1]);
    Lp[1] = __nv_bfloat162(ll[2], ll[3]);
}

// ---------------- transpose + split weights ----------------
__global__ __launch_bounds__(256)
void wsplitT_kernel(const float* __restrict__ W, bf16* __restrict__ Ht, bf16* __restrict__ Lt) {
    __shared__ float t[32][33];
    const int k0 = blockIdx.y * 32, n0 = blockIdx.x * 32;
    const int tx = threadIdx.x, ty = threadIdx.y;
#pragma unroll
    for (int j = 0; j < 4; ++j)
        t[ty + j * 8][tx] = W[(size_t)(k0 + ty + j * 8) * DIM + n0 + tx];
    __syncthreads();
#pragma unroll
    for (int j = 0; j < 4; ++j) {
        float v = t[tx][ty + j * 8];
        bf16 h = __float2bfloat16(v);
        bf16 l = __float2bfloat16(v - __bfloat162float(h));
        Ht[(size_t)(n0 + ty + j * 8) * DIM + k0 + tx] = h;
        Lt[(size_t)(n0 + ty + j * 8) * DIM + k0 + tx] = l;
    }
}

// ---------------- small fused SGEMM ----------------
struct SmallJobs {
    const float* A[4];
    const float* W[4];
    const float* b[4];
    float* C[4];
    int M[4];
};

__global__ __launch_bounds__(256)
void sgemm_small(SmallJobs jobs) {
    const int z = blockIdx.z;
    const float* A = jobs.A[z];
    const float* B = jobs.W[z];
    const float* bias = jobs.b[z];
    float* C = jobs.C[z];
    const int M = jobs.M[z];
    const int N = DIM, K = DIM;

    const int m0 = blockIdx.y * 128;
    if (m0 >= M) return;
    const int n0 = blockIdx.x * 64;

    __shared__ float As[16 * 132];
    __shared__ float Bs[16 * 64];
    const int tid = threadIdx.x;
    const int tx = tid & 15;
    const int ty = tid >> 4;
    const int arow = tid >> 1;
    const int ak = (tid & 1) * 8;
    const int brow = tid >> 4;
    const int bcol = (tid & 15) * 4;

    float acc[8][4];
#pragma unroll
    for (int i = 0; i < 8; ++i)
#pragma unroll
        for (int j = 0; j < 4; ++j) acc[i][j] = 0.f;

    const bool avalid = (m0 + arow) < M;
    const float* Aptr = A + (long)(m0 + arow) * K + ak;
    const float* Bptr = B + (long)brow * N + n0 + bcol;

    for (int k0 = 0; k0 < K; k0 += 16) {
        float4 a0 = make_float4(0.f, 0.f, 0.f, 0.f);
        float4 a1 = make_float4(0.f, 0.f, 0.f, 0.f);
        if (avalid) {
            a0 = *(const float4*)(Aptr + k0);
            a1 = *(const float4*)(Aptr + k0 + 4);
        }
        As[(ak + 0) * 132 + arow] = a0.x;
        As[(ak + 1) * 132 + arow] = a0.y;
        As[(ak + 2) * 132 + arow] = a0.z;
        As[(ak + 3) * 132 + arow] = a0.w;
        As[(ak + 4) * 132 + arow] = a1.x;
        As[(ak + 5) * 132 + arow] = a1.y;
        As[(ak + 6) * 132 + arow] = a1.z;
        As[(ak + 7) * 132 + arow] = a1.w;
        *(float4*)(Bs + brow * 64 + bcol) = *(const float4*)(Bptr + (long)k0 * N);
        __syncthreads();
#pragma unroll
        for (int kk = 0; kk < 16; ++kk) {
            float4 x0 = *(const float4*)(As + kk * 132 + ty * 8);
            float4 x1 = *(const float4*)(As + kk * 132 + ty * 8 + 4);
            float4 y = *(const float4*)(Bs + kk * 64 + tx * 4);
            float a[8] = {x0.x, x0.y, x0.z, x0.w, x1.x, x1.y, x1.z, x1.w};
            float b[4] = {y.x, y.y, y.z, y.w};
#pragma unroll
            for (int i = 0; i < 8; ++i)
#pragma unroll
                for (int j = 0; j < 4; ++j) acc[i][j] += a[i] * b[j];
        }
        __syncthreads();
    }

    float4 bv = *(const float4*)(bias + n0 + tx * 4);
    float bb[4] = {bv.x, bv.y, bv.z, bv.w};
#pragma unroll
    for (int i = 0; i < 8; ++i) {
        int m = m0 + ty * 8 + i;
        if (m < M) {
            float4 out;
            out.x = acc[i][0] + bb[0];
            out.y = acc[i][1] + bb[1];
            out.z = acc[i][2] + bb[2];
            out.w = acc[i][3] + bb[3];
            *(float4*)(C + (long)m * N + n0 + tx * 4) = out;
        }
    }
}

// ---------------- RMSNorm + bf16 hi/lo split, zero-pad rows >= nvalid ----------------
__global__ __launch_bounds__(256)
void rmsnorm_split(const float* __restrict__ X, const float* __restrict__ g, float scale,
                   bf16* __restrict__ H, bf16* __restrict__ L, int nvalid) {
    const int r = blockIdx.x;
    const int tid = threadIdx.x;
    if (r >= nvalid) {
#pragma unroll
        for (int i = 0; i < 6; ++i) {
            H[(long)r * DIM + tid + i * 256] = __float2bfloat16(0.f);
            L[(long)r * DIM + tid + i * 256] = __float2bfloat16(0.f);
        }
        return;
    }
    const float* x = X + (long)r * DIM;
    float v[6];
    float ss = 0.f;
#pragma unroll
    for (int i = 0; i < 6; ++i) {
        v[i] = x[tid + i * 256];
        ss += v[i] * v[i];
    }
#pragma unroll
    for (int off = 16; off >= 1; off >>= 1)
        ss += __shfl_xor_sync(0xffffffffu, ss, off);
    __shared__ float red[8];
    if ((tid & 31) == 0) red[tid >> 5] = ss;
    __syncthreads();
    float tot = 0.f;
#pragma unroll
    for (int i = 0; i < 8; ++i) tot += red[i];
    const float rms = rsqrtf(tot * (1.f / (float)DIM) + 1e-6f);
#pragma unroll
    for (int i = 0; i < 6; ++i) {
        float val = v[i] * rms * g[tid + i * 256] * scale;
        bf16 h = __float2bfloat16(val);
        bf16 l = __float2bfloat16(val - __bfloat162float(h));
        H[(long)r * DIM + tid + i * 256] = h;
        L[(long)r * DIM + tid + i * 256] = l;
    }
}

// ---------------- plain row split with zero-pad ----------------
__global__ __launch_bounds__(256)
void split_pad(const float* __restrict__ X, bf16* __restrict__ H, bf16* __restrict__ L, int nvalid) {
    const int r = blockIdx.x;
    const int tid = threadIdx.x;
#pragma unroll
    for (int i = 0; i < 6; ++i) {
        float val = (r < nvalid) ? X[(long)r * DIM + tid + i * 256] : 0.f;
        bf16 h = __float2bfloat16(val);
        bf16 l = __float2bfloat16(val - __bfloat162float(h));
        H[(long)r * DIM + tid + i * 256] = h;
        L[(long)r * DIM + tid + i * 256] = l;
    }
}

// ---------------- HMMA flash attention, two softmax segments ----------------
// KV double-buffered (Kh, Kl, Vh, Vl per stage); full bf16x3 in QK and PV.
#define AST 272            // smem row stride bytes (128 bf16 + 16B pad)
#define KVROW (64 * AST)   // one 64-row array
#define KVST (4 * KVROW)   // Kh, Kl, Vh, Vl per stage

__global__ __launch_bounds__(256, 1)
void attn_mma() {
    extern __shared__ char smem[];
    const uint32_t sQh = s2u(smem);
    const uint32_t sQl = sQh + 128 * AST;
    const uint32_t sKV = sQl + 128 * AST;   // 2 stages of KVST

    const int tid = threadIdx.x, lane = tid & 31, wid = tid >> 5;
    const int qb = blockIdx.x, h = blockIdx.y;
    const long qrow0 = (long)qb * 128;

    // Q load (its own commit group)
    {
        const bf16* Qhg = g_Qh + qrow0 * DIM + h * HD;
        const bf16* Qlg = g_Ql + qrow0 * DIM + h * HD;
#pragma unroll
        for (int t = 0; t < 8; ++t) {
            int c = tid + t * 256;
            int r = c >> 4, cb = c & 15;
            cp16(sQh + r * AST + cb * 16, Qhg + (long)r * DIM + cb * 8);
            cp16(sQl + r * AST + cb * 16, Qlg + (long)r * DIM + cb * 8);
        }
        cp_commit();
    }

    const uint32_t qoff = (uint32_t)((wid * 16 + (lane & 15)) * AST + (lane >> 4) * 16);
    const uint32_t koff = (uint32_t)((((lane >> 4) << 3) + (lane & 7)) * AST + ((lane >> 3) & 1) * 16);
    const uint32_t voff = (uint32_t)(((((lane >> 3) & 1) << 3) + (lane & 7)) * AST + (lane >> 4) * 16);

    const int r0 = lane >> 2;
    const int colb = (lane & 3) * 2;

#pragma unroll 1
    for (int seg = 0; seg < 2; ++seg) {
        const bf16 *Khg, *Klg, *Vhg, *Vlg;
        int len, ntiles;
        if (seg == 0) {
            Khg = g_Kh; Klg = g_Kl; Vhg = g_Vh; Vlg = g_Vl;
            len = TXT; ntiles = TXT / 64;
        } else {
            Khg = g_Kih; Klg = g_Kil; Vhg = g_Vih; Vlg = g_Vil;
            len = IMG; ntiles = IMGP / 64;
        }

        auto load_kv = [&](int stage, int t) {
            const uint32_t sb = sKV + stage * KVST;
            const long kvbase = (long)t * 64 * DIM + h * HD;
            const bf16* arrs[4] = {Khg, Klg, Vhg, Vlg};
#pragma unroll
            for (int tt = 0; tt < 16; ++tt) {
                int c = tid + tt * 256;       // 4096 chunks
                int arr = c >> 10;
                int idx = c & 1023;
                int r = idx >> 4, cb = idx & 15;
                cp16(sb + arr * KVROW + r * AST + cb * 16,
                     arrs[arr] + kvbase + (long)r * DIM + cb * 8);
            }
            cp_commit();
        };

        load_kv(0, 0);  // prologue

        float mrow0 = -1e30f, mrow1 = -1e30f, lsum0 = 0.f, lsum1 = 0.f;
        float O[16][4];
#pragma unroll
        for (int j = 0; j < 16; ++j)
#pragma unroll
            for (int e = 0; e < 4; ++e) O[j][e] = 0.f;

#pragma unroll 1
        for (int t = 0; t < ntiles; ++t) {
            __syncthreads();   // all warps finished reading buffer (t+1)&1 (from iter t-1)
            if (t + 1 < ntiles) {
                load_kv((t + 1) & 1, t + 1);
                cp_wait<1>();
            } else {
                cp_wait<0>();
            }
            __syncthreads();   // buffer t&1 visible to all

            const uint32_t sb = sKV + (t & 1) * KVST;
            const uint32_t sKh_ = sb, sKl_ = sb + KVROW;
            const uint32_t sVh_ = sb + 2 * KVROW, sVl_ = sb + 3 * KVROW;

            // ---- S = Q K^T (bf16x3) ----
            float S[8][4];
#pragma unroll
            for (int j = 0; j < 8; ++j)
#pragma unroll
                for (int e = 0; e < 4; ++e) S[j][e] = 0.f;
#pragma unroll
            for (int k16 = 0; k16 < 8; ++k16) {
                uint32_t ah[4], al[4];
                ldsm4(ah, sQh + qoff + k16 * 32);
                ldsm4(al, sQl + qoff + k16 * 32);
#pragma unroll
                for (int nt2 = 0; nt2 < 4; ++nt2) {
                    uint32_t bh[4], bl[4];
                    ldsm4(bh, sKh_ + koff + nt2 * 16 * AST + k16 * 32);
                    ldsm4(bl, sKl_ + koff + nt2 * 16 * AST + k16 * 32);
                    mma16816(S[2 * nt2], ah, bh);
                    mma16816(S[2 * nt2], ah, bl);
                    mma16816(S[2 * nt2], al, bh);
                    mma16816(S[2 * nt2 + 1], ah, bh + 2);
                    mma16816(S[2 * nt2 + 1], ah, bl + 2);
                    mma16816(S[2 * nt2 + 1], al, bh + 2);
                }
            }

            // ---- online softmax ----
            const int t0 = t * 64;
            if (t0 + 64 > len) {
#pragma unroll
                for (int j = 0; j < 8; ++j) {
#pragma unroll
                    for (int e = 0; e < 2; ++e) {
                        if (t0 + j * 8 + colb + e >= len) {
                            S[j][e] = -1e30f;
                            S[j][2 + e] = -1e30f;
                        }
                    }
                }
            }
            float mx0 = -1e30f, mx1 = -1e30f;
#pragma unroll
            for (int j = 0; j < 8; ++j) {
                mx0 = fmaxf(mx0, fmaxf(S[j][0], S[j][1]));
                mx1 = fmaxf(mx1, fmaxf(S[j][2], S[j][3]));
            }
            mx0 = fmaxf(mx0, __shfl_xor_sync(0xffffffffu, mx0, 1));
            mx0 = fmaxf(mx0, __shfl_xor_sync(0xffffffffu, mx0, 2));
            mx1 = fmaxf(mx1, __shfl_xor_sync(0xffffffffu, mx1, 1));
            mx1 = fmaxf(mx1, __shfl_xor_sync(0xffffffffu, mx1, 2));
            const float nm0 = fmaxf(mrow0, mx0);
            const float nm1 = fmaxf(mrow1, mx1);
            const float sc0 = __expf(mrow0 - nm0);
            const float sc1 = __expf(mrow1 - nm1);
            mrow0 = nm0; mrow1 = nm1;

            uint32_t Ph[8][2], Pl[8][2];
            float rs0 = 0.f, rs1 = 0.f;
#pragma unroll
            for (int j = 0; j < 8; ++j) {
                float p0 = __expf(S[j][0] - nm0);
                float p1 = __expf(S[j][1] - nm0);
                float p2 = __expf(S[j][2] - nm1);
                float p3 = __expf(S[j][3] - nm1);
                rs0 += p0 + p1;
                rs1 += p2 + p3;
                Ph[j][0] = packbf(p0, p1);
                Ph[j][1] = packbf(p2, p3);
                __nv_bfloat162 h01 = *(__nv_bfloat162*)&Ph[j][0];
                __nv_bfloat162 h23 = *(__nv_bfloat162*)&Ph[j][1];
                Pl[j][0] = packbf(p0 - __bfloat162float(h01.x), p1 - __bfloat162float(h01.y));
                Pl[j][1] = packbf(p2 - __bfloat162float(h23.x), p3 - __bfloat162float(h23.y));
            }
            rs0 += __shfl_xor_sync(0xffffffffu, rs0, 1);
            rs0 += __shfl_xor_sync(0xffffffffu, rs0, 2);
            rs1 += __shfl_xor_sync(0xffffffffu, rs1, 1);
            rs1 += __shfl_xor_sync(0xffffffffu, rs1, 2);
            lsum0 = lsum0 * sc0 + rs0;
            lsum1 = lsum1 * sc1 + rs1;
#pragma unroll
            for (int j = 0; j < 16; ++j) {
                O[j][0] *= sc0; O[j][1] *= sc0;
                O[j][2] *= sc1; O[j][3] *= sc1;
            }

            // ---- O += P V (bf16x3) ----
#pragma unroll
            for (int s = 0; s < 4; ++s) {
                uint32_t pah[4] = {Ph[2 * s][0], Ph[2 * s][1], Ph[2 * s + 1][0], Ph[2 * s + 1][1]};
                uint32_t pal[4] = {Pl[2 * s][0], Pl[2 * s][1], Pl[2 * s + 1][0], Pl[2 * s + 1][1]};
#pragma unroll
                for (int d2 = 0; d2 < 8; ++d2) {
                    uint32_t vh[4], vl[4];
                    ldsm4t(vh, sVh_ + voff + s * 16 * AST + d2 * 32);
                    ldsm4t(vl, sVl_ + voff + s * 16 * AST + d2 * 32);
                    mma16816(O[2 * d2], pah, vh);
                    mma16816(O[2 * d2], pah, vl);
                    mma16816(O[2 * d2], pal, vh);
                    mma16816(O[2 * d2 + 1], pah, vh + 2);
                    mma16816(O[2 * d2 + 1], pah, vl + 2);
                    mma16816(O[2 * d2 + 1], pal, vh + 2);
                }
            }
        }

        const float inv0 = 1.f / lsum0;
        const float inv1 = 1.f / lsum1;
        const long grow0 = qrow0 + wid * 16 + r0;
        const long grow1 = grow0 + 8;
        if (seg == 0) {
#pragma unroll
            for (int j = 0; j < 16; ++j) {
                const int d = h * HD + j * 8 + colb;
                *(float2*)(g_O + grow0 * DIM + d) = make_float2(O[j][0] * inv0, O[j][1] * inv0);
                *(float2*)(g_O + grow1 * DIM + d) = make_float2(O[j][2] * inv1, O[j][3] * inv1);
            }
        } else {
#pragma unroll
            for (int j = 0; j < 16; ++j) {
                const int d = h * HD + j * 8 + colb;
                float2 p0 = *(float2*)(g_O + grow0 * DIM + d);
                float2 p1 = *(float2*)(g_O + grow1 * DIM + d);
                float v0 = p0.x + O[j][0] * inv0;
                float v1 = p0.y + O[j][1] * inv0;
                float v2 = p1.x + O[j][2] * inv1;
                float v3 = p1.y + O[j][3] * inv1;
                bf16 h0 = __float2bfloat16(v0), h1 = __float2bfloat16(v1);
                bf16 h2 = __float2bfloat16(v2), h3 = __float2bfloat16(v3);
                *(__nv_bfloat162*)(g_Oh + grow0 * DIM + d) = __nv_bfloat162(h0, h1);
                *(__nv_bfloat162*)(g_Oh + grow1 * DIM + d) = __nv_bfloat162(h2, h3);
                *(__nv_bfloat162*)(g_Ol + grow0 * DIM + d) =
                    __nv_bfloat162(__float2bfloat16(v0 - __bfloat162float(h0)),
                                   __float2bfloat16(v1 - __bfloat162float(h1)));
                *(__nv_bfloat162*)(g_Ol + grow1 * DIM + d) =
                    __nv_bfloat162(__float2bfloat16(v2 - __bfloat162float(h2)),
                                   __float2bfloat16(v3 - __bfloat162float(h3)));
            }
        }
    }
}

// ---------------- launch ----------------
extern "C" void kernel_launch(void* const* d_in, const int* in_sizes, int n_in,
                              void* d_out, int out_size) {
    const float* x       = (const float*)d_in[0];
    const float* context = (const float*)d_in[1];
    const float* Wq  = (const float*)d_in[3];
    const float* bq  = (const float*)d_in[4];
    const float* Wk  = (const float*)d_in[5];
    const float* bk  = (const float*)d_in[6];
    const float* Wv  = (const float*)d_in[7];
    const float* bv  = (const float*)d_in[8];
    const float* Wak = (const float*)d_in[9];
    const float* bak = (const float*)d_in[10];
    const float* Wav = (const float*)d_in[11];
    const float* bav = (const float*)d_in[12];
    const float* Wo  = (const float*)d_in[13];
    const float* bo  = (const float*)d_in[14];
    const float* gq  = (const float*)d_in[15];
    const float* gk  = (const float*)d_in[16];
    const float* gak = (const float*)d_in[17];
    float* out = (float*)d_out;

    float *Qp, *Kp, *Vp, *Kip, *Vip;
    bf16 *xh, *xl, *Oh, *Ol, *WqhT, *WqlT, *WohT, *WolT;
    bf16 *Qh, *Ql, *Kh, *Kl, *Vh, *Vl, *Kih, *Kil, *Vih, *Vil;
    cudaGetSymbolAddress((void**)&Qp, g_Q);
    cudaGetSymbolAddress((void**)&Kp, g_K);
    cudaGetSymbolAddress((void**)&Vp, g_V);
    cudaGetSymbolAddress((void**)&Kip, g_Ki);
    cudaGetSymbolAddress((void**)&Vip, g_Vi);
    cudaGetSymbolAddress((void**)&xh, g_xh);
    cudaGetSymbolAddress((void**)&xl, g_xl);
    cudaGetSymbolAddress((void**)&Oh, g_Oh);
    cudaGetSymbolAddress((void**)&Ol, g_Ol);
    cudaGetSymbolAddress((void**)&WqhT, g_WqhT);
    cudaGetSymbolAddress((void**)&WqlT, g_WqlT);
    cudaGetSymbolAddress((void**)&WohT, g_WohT);
    cudaGetSymbolAddress((void**)&WolT, g_WolT);
    cudaGetSymbolAddress((void**)&Qh, g_Qh);
    cudaGetSymbolAddress((void**)&Ql, g_Ql);
    cudaGetSymbolAddress((void**)&Kh, g_Kh);
    cudaGetSymbolAddress((void**)&Kl, g_Kl);
    cudaGetSymbolAddress((void**)&Vh, g_Vh);
    cudaGetSymbolAddress((void**)&Vl, g_Vl);
    cudaGetSymbolAddress((void**)&Kih, g_Kih);
    cudaGetSymbolAddress((void**)&Kil, g_Kil);
    cudaGetSymbolAddress((void**)&Vih, g_Vih);
    cudaGetSymbolAddress((void**)&Vil, g_Vil);

    const float* ctx_img = context;
    const float* ctx_txt = context + (long)IMG * DIM;

    static cudaStream_t s1 = nullptr;
    static cudaEvent_t evFork = nullptr, evJoin = nullptr;
    if (s1 == nullptr) {
        cudaStreamCreateWithFlags(&s1, cudaStreamNonBlocking);
        cudaEventCreateWithFlags(&evFork, cudaEventDisableTiming);
        cudaEventCreateWithFlags(&evJoin, cudaEventDisableTiming);
    }

    const float scale = 0.08838834764831843f;
    const int gemm_smem = NSTAGE * STAGE_B;
    cudaFuncSetAttribute(gemm_mma_bf16x3, cudaFuncAttributeMaxDynamicSharedMemorySize, gemm_smem);
    const int attn_smem = 2 * 128 * AST + 2 * KVST;
    cudaFuncSetAttribute(attn_mma, cudaFuncAttributeMaxDynamicSharedMemorySize, attn_smem);

    // ---- fork ----
    cudaEventRecord(evFork, 0);
    cudaStreamWaitEvent(s1, evFork, 0);

    // main stream: Q chain
    long n4 = (long)NQ * DIM / 4;
    split_kernel<<<(unsigned)((n4 + 255) / 256), 256>>>(x, xh, xl, n4);
    wsplitT_kernel<<<dim3(DIM / 32, DIM / 32), dim3(32, 8)>>>(Wq, WqhT, WqlT);
    gemm_mma_bf16x3<<<dim3(DIM / 128, NQ / 128), 256, gemm_smem>>>(xh, xl, WqhT, WqlT, bq, Qp);
    rmsnorm_split<<<NQ, 256>>>(Qp, gq, scale, Qh, Ql, NQ);

    // side stream: KV chain + Wo prep
    SmallJobs jobs;
    jobs.A[0] = ctx_txt; jobs.W[0] = Wk;  jobs.b[0] = bk;  jobs.C[0] = Kp;  jobs.M[0] = TXT;
    jobs.A[1] = ctx_txt; jobs.W[1] = Wv;  jobs.b[1] = bv;  jobs.C[1] = Vp;  jobs.M[1] = TXT;
    jobs.A[2] = ctx_img; jobs.W[2] = Wak; jobs.b[2] = bak; jobs.C[2] = Kip; jobs.M[2] = IMG;
    jobs.A[3] = ctx_img; jobs.W[3] = Wav; jobs.b[3] = bav; jobs.C[3] = Vip; jobs.M[3] = IMG;
    sgemm_small<<<dim3(DIM / 64, 4, 4), 256, 0, s1>>>(jobs);
    rmsnorm_split<<<TXT, 256, 0, s1>>>(Kp, gk, 1.f, Kh, Kl, TXT);
    rmsnorm_split<<<IMGP, 256, 0, s1>>>(Kip, gak, 1.f, Kih, Kil, IMG);
    split_pad<<<TXT, 256, 0, s1>>>(Vp, Vh, Vl, TXT);
    split_pad<<<IMGP, 256, 0, s1>>>(Vip, Vih, Vil, IMG);
    wsplitT_kernel<<<dim3(DIM / 32, DIM / 32), dim3(32, 8), 0, s1>>>(Wo, WohT, WolT);

    // ---- join ----
    cudaEventRecord(evJoin, s1);
    cudaStreamWaitEvent(0, evJoin, 0);

    attn_mma<<<dim3(NQ / 128, HEADS), 256, attn_smem>>>();
    gemm_mma_bf16x3<<<dim3(DIM / 128, NQ / 128), 256, gemm_smem>>>(Oh, Ol, WohT, WolT, bo, out);
}

// round 9
// speedup vs baseline: 3.2600x; 1.0332x over previous
#include <cuda_runtime.h>
#include <cuda_bf16.h>
#include <cstdint>

#define DIM 1536
#define HEADS 12
#define HD 128
#define NQ 16384
#define HALF (NQ / 2)
#define IMG 257
#define TXT 512
#define IMGP 320   // img rows padded to multiple of 64

typedef __nv_bfloat16 bf16;

// ---------------- scratch (no allocations allowed) ----------------
__device__ float g_Q[(long)NQ * DIM];
__device__ float g_O[(long)NQ * DIM];          // attention partial (txt segment)
__device__ float g_K[(long)TXT * DIM];
__device__ float g_V[(long)TXT * DIM];
__device__ float g_Ki[(long)IMG * DIM];
__device__ float g_Vi[(long)IMG * DIM];
__device__ bf16 g_xh[(long)NQ * DIM];
__device__ bf16 g_xl[(long)NQ * DIM];
__device__ bf16 g_Qh[(long)NQ * DIM];
__device__ bf16 g_Ql[(long)NQ * DIM];
__device__ bf16 g_Oh[(long)NQ * DIM];
__device__ bf16 g_Ol[(long)NQ * DIM];
__device__ bf16 g_Kh[(long)TXT * DIM];
__device__ bf16 g_Kl[(long)TXT * DIM];
__device__ bf16 g_Vh[(long)TXT * DIM];
__device__ bf16 g_Vl[(long)TXT * DIM];
__device__ bf16 g_Kih[(long)IMGP * DIM];
__device__ bf16 g_Kil[(long)IMGP * DIM];
__device__ bf16 g_Vih[(long)IMGP * DIM];
__device__ bf16 g_Vil[(long)IMGP * DIM];
__device__ bf16 g_WqhT[(long)DIM * DIM];
__device__ bf16 g_WqlT[(long)DIM * DIM];
__device__ bf16 g_WohT[(long)DIM * DIM];
__device__ bf16 g_WolT[(long)DIM * DIM];

// ---------------- PTX helpers ----------------
__device__ __forceinline__ uint32_t s2u(const void* p) {
    return (uint32_t)__cvta_generic_to_shared(p);
}
__device__ __forceinline__ void cp16(uint32_t s, const void* g) {
    asm volatile("cp.async.cg.shared.global [%0], [%1], 16;\n" :: "r"(s), "l"(g) : "memory");
}
__device__ __forceinline__ void cp_commit() {
    asm volatile("cp.async.commit_group;\n" ::: "memory");
}
template <int N>
__device__ __forceinline__ void cp_wait() {
    asm volatile("cp.async.wait_group %0;\n" :: "n"(N) : "memory");
}
__device__ __forceinline__ void ldsm4(uint32_t* r, uint32_t a) {
    asm volatile("ldmatrix.sync.aligned.m8n8.x4.shared.b16 {%0,%1,%2,%3}, [%4];"
                 : "=r"(r[0]), "=r"(r[1]), "=r"(r[2]), "=r"(r[3]) : "r"(a));
}
__device__ __forceinline__ void ldsm4t(uint32_t* r, uint32_t a) {
    asm volatile("ldmatrix.sync.aligned.m8n8.x4.trans.shared.b16 {%0,%1,%2,%3}, [%4];"
                 : "=r"(r[0]), "=r"(r[1]), "=r"(r[2]), "=r"(r[3]) : "r"(a));
}
__device__ __forceinline__ void mma16816(float* c, const uint32_t* a, const uint32_t* b) {
    asm volatile(
        "mma.sync.aligned.m16n8k16.row.col.f32.bf16.bf16.f32 "
        "{%0,%1,%2,%3}, {%4,%5,%6,%7}, {%8,%9}, {%0,%1,%2,%3};"
        : "+f"(c[0]), "+f"(c[1]), "+f"(c[2]), "+f"(c[3])
        : "r"(a[0]), "r"(a[1]), "r"(a[2]), "r"(a[3]), "r"(b[0]), "r"(b[1]));
}
__device__ __forceinline__ uint32_t packbf(float a, float b) {
    __nv_bfloat162 t = __floats2bfloat162_rn(a, b);
    return *(uint32_t*)&t;
}

// ---------------- bf16x3 HMMA GEMM ----------------
#define GSTRIDE 80
#define TILE_B (128 * GSTRIDE)
#define STAGE_B (4 * TILE_B)
#define NSTAGE 2

__global__ __launch_bounds__(256, 2)
void gemm_mma_bf16x3(const bf16* __restrict__ Ah, const bf16* __restrict__ Al,
                     const bf16* __restrict__ BhT, const bf16* __restrict__ BlT,
                     const float* __restrict__ bias, float* __restrict__ C) {
    extern __shared__ char dynsm[];
    const uint32_t smem0 = s2u(dynsm);
    const int tid = threadIdx.x;
    const int lane = tid & 31;
    const int wid = tid >> 5;
    const int wm = wid & 3;
    const int wn = wid >> 2;
    const int m0 = blockIdx.y * 128;
    const int n0 = blockIdx.x * 128;

    const bf16* srcs[4] = {Ah, Al, BhT, BlT};
    const int bases[4] = {m0, m0, n0, n0};

    auto load_stage = [&](int slot, int k0) {
        const uint32_t sb = smem0 + slot * STAGE_B;
#pragma unroll
        for (int t = 0; t < 8; ++t) {
            const int ch = tid + t * 256;
            const int tile = ch >> 9;
            const int idx = ch & 511;
            const int row = idx >> 2;
            const int cb = idx & 3;
            const uint32_t so = sb + tile * TILE_B + row * GSTRIDE + cb * 16;
            const bf16* g = srcs[tile] + (size_t)(bases[tile] + row) * DIM + k0 + cb * 8;
            cp16(so, g);
        }
        cp_commit();
    };

    for (int s = 0; s < NSTAGE; ++s) load_stage(s, s * 32);

    float acc[2][8][4];
#pragma unroll
    for (int mi = 0; mi < 2; ++mi)
#pragma unroll
        for (int nj = 0; nj < 8; ++nj)
#pragma unroll
            for (int r = 0; r < 4; ++r) acc[mi][nj][r] = 0.f;

    const int rowA = wm * 32 + (lane & 15);
    const int acol = (lane >> 4) * 16;
    const int rowB = wn * 64 + (lane >> 4) * 8 + (lane & 7);
    const int bcol = ((lane >> 3) & 1) * 16;

    constexpr int NKC = DIM / 32;
    for (int i = 0; i < NKC; ++i) {
        const int slot = i % NSTAGE;
        const uint32_t sb = smem0 + slot * STAGE_B;
        cp_wait<NSTAGE - 1>();
        __syncthreads();

        const uint32_t aAh = sb + rowA * GSTRIDE + acol;
        const uint32_t aAl = aAh + TILE_B;
        const uint32_t aBh = sb + 2 * TILE_B + rowB * GSTRIDE + bcol;
        const uint32_t aBl = aBh + TILE_B;

#pragma unroll
        for (int k16 = 0; k16 < 2; ++k16) {
            const uint32_t ko = k16 * 32;
            uint32_t ah[2][4], al[2][4], bh[4][4], bl[4][4];
#pragma unroll
            for (int mi = 0; mi < 2; ++mi) {
                ldsm4(ah[mi], aAh + mi * 16 * GSTRIDE + ko);
                ldsm4(al[mi], aAl + mi * 16 * GSTRIDE + ko);
            }
#pragma unroll
            for (int ni = 0; ni < 4; ++ni) {
                ldsm4(bh[ni], aBh + ni * 16 * GSTRIDE + ko);
                ldsm4(bl[ni], aBl + ni * 16 * GSTRIDE + ko);
            }
#pragma unroll
            for (int mi = 0; mi < 2; ++mi)
#pragma unroll
                for (int nj = 0; nj < 8; ++nj) {
                    const uint32_t* bhp = &bh[nj >> 1][(nj & 1) * 2];
                    const uint32_t* blp = &bl[nj >> 1][(nj & 1) * 2];
                    mma16816(acc[mi][nj], ah[mi], bhp);
                    mma16816(acc[mi][nj], ah[mi], blp);
                    mma16816(acc[mi][nj], al[mi], bhp);
                }
        }
        __syncthreads();
        if (i + NSTAGE < NKC) load_stage(slot, (i + NSTAGE) * 32);
        else cp_commit();
    }

    const int crow0 = m0 + wm * 32 + (lane >> 2);
    const int ccol0 = n0 + wn * 64 + (lane & 3) * 2;
#pragma unroll
    for (int nj = 0; nj < 8; ++nj) {
        const int col = ccol0 + nj * 8;
        const float b0 = bias[col], b1 = bias[col + 1];
#pragma unroll
        for (int mi = 0; mi < 2; ++mi) {
            float* c0 = C + (size_t)(crow0 + mi * 16) * DIM + col;
            float* c1 = c0 + 8 * DIM;
            *(float2*)c0 = make_float2(acc[mi][nj][0] + b0, acc[mi][nj][1] + b1);
            *(float2*)c1 = make_float2(acc[mi][nj][2] + b0, acc[mi][nj][3] + b1);
        }
    }
}

// ---------------- split fp32 -> bf16 hi/lo (flat) ----------------
__global__ __launch_bounds__(256)
void split_kernel(const float* __restrict__ X, bf16* __restrict__ H, bf16* __restrict__ L, long n4) {
    long i = ((long)blockIdx.x * 256 + threadIdx.x);
    if (i >= n4) return;
    float4 v = *((const float4*)X + i);
    float vv[4] = {v.x, v.y, v.z, v.w};
    bf16 hh[4], ll[4];
#pragma unroll
    for (int j = 0; j < 4; ++j) {
        hh[j] = __float2bfloat16(vv[j]);
        ll[j] = __float2bfloat16(vv[j] - __bfloat162float(hh[j]));
    }
    __nv_bfloat162* Hp = (__nv_bfloat162*)H + i * 2;
    __nv_bfloat162* Lp = (__nv_bfloat162*)L + i * 2;
    Hp[0] = __nv_bfloat162(hh[0], hh[1]);
    Hp[1] = __nv_bfloat162(hh[2], hh[3]);
    Lp[0] = __nv_bfloat162(ll[0], ll[1]);
    Lp[1] = __nv_bfloat162(ll[2], ll[3]);
}

// ---------------- transpose + split weights ----------------
__global__ __launch_bounds__(256)
void wsplitT_kernel(const float* __restrict__ W, bf16* __restrict__ Ht, bf16* __restrict__ Lt) {
    __shared__ float t[32][33];
    const int k0 = blockIdx.y * 32, n0 = blockIdx.x * 32;
    const int tx = threadIdx.x, ty = threadIdx.y;
#pragma unroll
    for (int j = 0; j < 4; ++j)
        t[ty + j * 8][tx] = W[(size_t)(k0 + ty + j * 8) * DIM + n0 + tx];
    __syncthreads();
#pragma unroll
    for (int j = 0; j < 4; ++j) {
        float v = t[tx][ty + j * 8];
        bf16 h = __float2bfloat16(v);
        bf16 l = __float2bfloat16(v - __bfloat162float(h));
        Ht[(size_t)(n0 + ty + j * 8) * DIM + k0 + tx] = h;
        Lt[(size_t)(n0 + ty + j * 8) * DIM + k0 + tx] = l;
    }
}

// ---------------- small fused SGEMM ----------------
struct SmallJobs {
    const float* A[4];
    const float* W[4];
    const float* b[4];
    float* C[4];
    int M[4];
};

__global__ __launch_bounds__(256)
void sgemm_small(SmallJobs jobs) {
    const int z = blockIdx.z;
    const float* A = jobs.A[z];
    const float* B = jobs.W[z];
    const float* bias = jobs.b[z];
    float* C = jobs.C[z];
    const int M = jobs.M[z];
    const int N = DIM, K = DIM;

    const int m0 = blockIdx.y * 128;
    if (m0 >= M) return;
    const int n0 = blockIdx.x * 64;

    __shared__ float As[16 * 132];
    __shared__ float Bs[16 * 64];
    const int tid = threadIdx.x;
    const int tx = tid & 15;
    const int ty = tid >> 4;
    const int arow = tid >> 1;
    const int ak = (tid & 1) * 8;
    const int brow = tid >> 4;
    const int bcol = (tid & 15) * 4;

    float acc[8][4];
#pragma unroll
    for (int i = 0; i < 8; ++i)
#pragma unroll
        for (int j = 0; j < 4; ++j) acc[i][j] = 0.f;

    const bool avalid = (m0 + arow) < M;
    const float* Aptr = A + (long)(m0 + arow) * K + ak;
    const float* Bptr = B + (long)brow * N + n0 + bcol;

    for (int k0 = 0; k0 < K; k0 += 16) {
        float4 a0 = make_float4(0.f, 0.f, 0.f, 0.f);
        float4 a1 = make_float4(0.f, 0.f, 0.f, 0.f);
        if (avalid) {
            a0 = *(const float4*)(Aptr + k0);
            a1 = *(const float4*)(Aptr + k0 + 4);
        }
        As[(ak + 0) * 132 + arow] = a0.x;
        As[(ak + 1) * 132 + arow] = a0.y;
        As[(ak + 2) * 132 + arow] = a0.z;
        As[(ak + 3) * 132 + arow] = a0.w;
        As[(ak + 4) * 132 + arow] = a1.x;
        As[(ak + 5) * 132 + arow] = a1.y;
        As[(ak + 6) * 132 + arow] = a1.z;
        As[(ak + 7) * 132 + arow] = a1.w;
        *(float4*)(Bs + brow * 64 + bcol) = *(const float4*)(Bptr + (long)k0 * N);
        __syncthreads();
#pragma unroll
        for (int kk = 0; kk < 16; ++kk) {
            float4 x0 = *(const float4*)(As + kk * 132 + ty * 8);
            float4 x1 = *(const float4*)(As + kk * 132 + ty * 8 + 4);
            float4 y = *(const float4*)(Bs + kk * 64 + tx * 4);
            float a[8] = {x0.x, x0.y, x0.z, x0.w, x1.x, x1.y, x1.z, x1.w};
            float b[4] = {y.x, y.y, y.z, y.w};
#pragma unroll
            for (int i = 0; i < 8; ++i)
#pragma unroll
                for (int j = 0; j < 4; ++j) acc[i][j] += a[i] * b[j];
        }
        __syncthreads();
    }

    float4 bv = *(const float4*)(bias + n0 + tx * 4);
    float bb[4] = {bv.x, bv.y, bv.z, bv.w};
#pragma unroll
    for (int i = 0; i < 8; ++i) {
        int m = m0 + ty * 8 + i;
        if (m < M) {
            float4 out;
            out.x = acc[i][0] + bb[0];
            out.y = acc[i][1] + bb[1];
            out.z = acc[i][2] + bb[2];
            out.w = acc[i][3] + bb[3];
            *(float4*)(C + (long)m * N + n0 + tx * 4) = out;
        }
    }
}

// ---------------- RMSNorm + bf16 hi/lo split, zero-pad rows >= nvalid ----------------
__global__ __launch_bounds__(256)
void rmsnorm_split(const float* __restrict__ X, const float* __restrict__ g, float scale,
                   bf16* __restrict__ H, bf16* __restrict__ L, int nvalid) {
    const int r = blockIdx.x;
    const int tid = threadIdx.x;
    if (r >= nvalid) {
#pragma unroll
        for (int i = 0; i < 6; ++i) {
            H[(long)r * DIM + tid + i * 256] = __float2bfloat16(0.f);
            L[(long)r * DIM + tid + i * 256] = __float2bfloat16(0.f);
        }
        return;
    }
    const float* x = X + (long)r * DIM;
    float v[6];
    float ss = 0.f;
#pragma unroll
    for (int i = 0; i < 6; ++i) {
        v[i] = x[tid + i * 256];
        ss += v[i] * v[i];
    }
#pragma unroll
    for (int off = 16; off >= 1; off >>= 1)
        ss += __shfl_xor_sync(0xffffffffu, ss, off);
    __shared__ float red[8];
    if ((tid & 31) == 0) red[tid >> 5] = ss;
    __syncthreads();
    float tot = 0.f;
#pragma unroll
    for (int i = 0; i < 8; ++i) tot += red[i];
    const float rms = rsqrtf(tot * (1.f / (float)DIM) + 1e-6f);
#pragma unroll
    for (int i = 0; i < 6; ++i) {
        float val = v[i] * rms * g[tid + i * 256] * scale;
        bf16 h = __float2bfloat16(val);
        bf16 l = __float2bfloat16(val - __bfloat162float(h));
        H[(long)r * DIM + tid + i * 256] = h;
        L[(long)r * DIM + tid + i * 256] = l;
    }
}

// ---------------- plain row split with zero-pad ----------------
__global__ __launch_bounds__(256)
void split_pad(const float* __restrict__ X, bf16* __restrict__ H, bf16* __restrict__ L, int nvalid) {
    const int r = blockIdx.x;
    const int tid = threadIdx.x;
#pragma unroll
    for (int i = 0; i < 6; ++i) {
        float val = (r < nvalid) ? X[(long)r * DIM + tid + i * 256] : 0.f;
        bf16 h = __float2bfloat16(val);
        bf16 l = __float2bfloat16(val - __bfloat162float(h));
        H[(long)r * DIM + tid + i * 256] = h;
        L[(long)r * DIM + tid + i * 256] = l;
    }
}

// ---------------- HMMA flash attention, two softmax segments ----------------
// KV double-buffered (Kh, Kl, Vh, Vl per stage); full bf16x3 in QK and PV.
#define AST 272            // smem row stride bytes (128 bf16 + 16B pad)
#define KVROW (64 * AST)   // one 64-row array
#define KVST (4 * KVROW)   // Kh, Kl, Vh, Vl per stage

__global__ __launch_bounds__(256, 1)
void attn_mma(int qb0) {
    extern __shared__ char smem[];
    const uint32_t sQh = s2u(smem);
    const uint32_t sQl = sQh + 128 * AST;
    const uint32_t sKV = sQl + 128 * AST;   // 2 stages of KVST

    const int tid = threadIdx.x, lane = tid & 31, wid = tid >> 5;
    const int qb = blockIdx.x + qb0, h = blockIdx.y;
    const long qrow0 = (long)qb * 128;

    // Q load (its own commit group)
    {
        const bf16* Qhg = g_Qh + qrow0 * DIM + h * HD;
        const bf16* Qlg = g_Ql + qrow0 * DIM + h * HD;
#pragma unroll
        for (int t = 0; t < 8; ++t) {
            int c = tid + t * 256;
            int r = c >> 4, cb = c & 15;
            cp16(sQh + r * AST + cb * 16, Qhg + (long)r * DIM + cb * 8);
            cp16(sQl + r * AST + cb * 16, Qlg + (long)r * DIM + cb * 8);
        }
        cp_commit();
    }

    const uint32_t qoff = (uint32_t)((wid * 16 + (lane & 15)) * AST + (lane >> 4) * 16);
    const uint32_t koff = (uint32_t)((((lane >> 4) << 3) + (lane & 7)) * AST + ((lane >> 3) & 1) * 16);
    const uint32_t voff = (uint32_t)(((((lane >> 3) & 1) << 3) + (lane & 7)) * AST + (lane >> 4) * 16);

    const int r0 = lane >> 2;
    const int colb = (lane & 3) * 2;

#pragma unroll 1
    for (int seg = 0; seg < 2; ++seg) {
        const bf16 *Khg, *Klg, *Vhg, *Vlg;
        int len, ntiles;
        if (seg == 0) {
            Khg = g_Kh; Klg = g_Kl; Vhg = g_Vh; Vlg = g_Vl;
            len = TXT; ntiles = TXT / 64;
        } else {
            Khg = g_Kih; Klg = g_Kil; Vhg = g_Vih; Vlg = g_Vil;
            len = IMG; ntiles = IMGP / 64;
        }

        auto load_kv = [&](int stage, int t) {
            const uint32_t sb = sKV + stage * KVST;
            const long kvbase = (long)t * 64 * DIM + h * HD;
            const bf16* arrs[4] = {Khg, Klg, Vhg, Vlg};
#pragma unroll
            for (int tt = 0; tt < 16; ++tt) {
                int c = tid + tt * 256;       // 4096 chunks
                int arr = c >> 10;
                int idx = c & 1023;
                int r = idx >> 4, cb = idx & 15;
                cp16(sb + arr * KVROW + r * AST + cb * 16,
                     arrs[arr] + kvbase + (long)r * DIM + cb * 8);
            }
            cp_commit();
        };

        load_kv(0, 0);  // prologue

        float mrow0 = -1e30f, mrow1 = -1e30f, lsum0 = 0.f, lsum1 = 0.f;
        float O[16][4];
#pragma unroll
        for (int j = 0; j < 16; ++j)
#pragma unroll
            for (int e = 0; e < 4; ++e) O[j][e] = 0.f;

#pragma unroll 1
        for (int t = 0; t < ntiles; ++t) {
            __syncthreads();   // all warps finished reading buffer (t+1)&1 (from iter t-1)
            if (t + 1 < ntiles) {
                load_kv((t + 1) & 1, t + 1);
                cp_wait<1>();
            } else {
                cp_wait<0>();
            }
            __syncthreads();   // buffer t&1 visible to all

            const uint32_t sb = sKV + (t & 1) * KVST;
            const uint32_t sKh_ = sb, sKl_ = sb + KVROW;
            const uint32_t sVh_ = sb + 2 * KVROW, sVl_ = sb + 3 * KVROW;

            // ---- S = Q K^T (bf16x3) ----
            float S[8][4];
#pragma unroll
            for (int j = 0; j < 8; ++j)
#pragma unroll
                for (int e = 0; e < 4; ++e) S[j][e] = 0.f;
#pragma unroll
            for (int k16 = 0; k16 < 8; ++k16) {
                uint32_t ah[4], al[4];
                ldsm4(ah, sQh + qoff + k16 * 32);
                ldsm4(al, sQl + qoff + k16 * 32);
#pragma unroll
                for (int nt2 = 0; nt2 < 4; ++nt2) {
                    uint32_t bh[4], bl[4];
                    ldsm4(bh, sKh_ + koff + nt2 * 16 * AST + k16 * 32);
                    ldsm4(bl, sKl_ + koff + nt2 * 16 * AST + k16 * 32);
                    mma16816(S[2 * nt2], ah, bh);
                    mma16816(S[2 * nt2], ah, bl);
                    mma16816(S[2 * nt2], al, bh);
                    mma16816(S[2 * nt2 + 1], ah, bh + 2);
                    mma16816(S[2 * nt2 + 1], ah, bl + 2);
                    mma16816(S[2 * nt2 + 1], al, bh + 2);
                }
            }

            // ---- online softmax ----
            const int t0 = t * 64;
            if (t0 + 64 > len) {
#pragma unroll
                for (int j = 0; j < 8; ++j) {
#pragma unroll
                    for (int e = 0; e < 2; ++e) {
                        if (t0 + j * 8 + colb + e >= len) {
                            S[j][e] = -1e30f;
                            S[j][2 + e] = -1e30f;
                        }
                    }
                }
            }
            float mx0 = -1e30f, mx1 = -1e30f;
#pragma unroll
            for (int j = 0; j < 8; ++j) {
                mx0 = fmaxf(mx0, fmaxf(S[j][0], S[j][1]));
                mx1 = fmaxf(mx1, fmaxf(S[j][2], S[j][3]));
            }
            mx0 = fmaxf(mx0, __shfl_xor_sync(0xffffffffu, mx0, 1));
            mx0 = fmaxf(mx0, __shfl_xor_sync(0xffffffffu, mx0, 2));
            mx1 = fmaxf(mx1, __shfl_xor_sync(0xffffffffu, mx1, 1));
            mx1 = fmaxf(mx1, __shfl_xor_sync(0xffffffffu, mx1, 2));
            const float nm0 = fmaxf(mrow0, mx0);
            const float nm1 = fmaxf(mrow1, mx1);
            const float sc0 = __expf(mrow0 - nm0);
            const float sc1 = __expf(mrow1 - nm1);
            mrow0 = nm0; mrow1 = nm1;

            uint32_t Ph[8][2], Pl[8][2];
            float rs0 = 0.f, rs1 = 0.f;
#pragma unroll
            for (int j = 0; j < 8; ++j) {
                float p0 = __expf(S[j][0] - nm0);
                float p1 = __expf(S[j][1] - nm0);
                float p2 = __expf(S[j][2] - nm1);
                float p3 = __expf(S[j][3] - nm1);
                rs0 += p0 + p1;
                rs1 += p2 + p3;
                Ph[j][0] = packbf(p0, p1);
                Ph[j][1] = packbf(p2, p3);
                __nv_bfloat162 h01 = *(__nv_bfloat162*)&Ph[j][0];
                __nv_bfloat162 h23 = *(__nv_bfloat162*)&Ph[j][1];
                Pl[j][0] = packbf(p0 - __bfloat162float(h01.x), p1 - __bfloat162float(h01.y));
                Pl[j][1] = packbf(p2 - __bfloat162float(h23.x), p3 - __bfloat162float(h23.y));
            }
            rs0 += __shfl_xor_sync(0xffffffffu, rs0, 1);
            rs0 += __shfl_xor_sync(0xffffffffu, rs0, 2);
            rs1 += __shfl_xor_sync(0xffffffffu, rs1, 1);
            rs1 += __shfl_xor_sync(0xffffffffu, rs1, 2);
            lsum0 = lsum0 * sc0 + rs0;
            lsum1 = lsum1 * sc1 + rs1;
#pragma unroll
            for (int j = 0; j < 16; ++j) {
                O[j][0] *= sc0; O[j][1] *= sc0;
                O[j][2] *= sc1; O[j][3] *= sc1;
            }

            // ---- O += P V (bf16x3) ----
#pragma unroll
            for (int s = 0; s < 4; ++s) {
                uint32_t pah[4] = {Ph[2 * s][0], Ph[2 * s][1], Ph[2 * s + 1][0], Ph[2 * s + 1][1]};
                uint32_t pal[4] = {Pl[2 * s][0], Pl[2 * s][1], Pl[2 * s + 1][0], Pl[2 * s + 1][1]};
#pragma unroll
                for (int d2 = 0; d2 < 8; ++d2) {
                    uint32_t vh[4], vl[4];
                    ldsm4t(vh, sVh_ + voff + s * 16 * AST + d2 * 32);
                    ldsm4t(vl, sVl_ + voff + s * 16 * AST + d2 * 32);
                    mma16816(O[2 * d2], pah, vh);
                    mma16816(O[2 * d2], pah, vl);
                    mma16816(O[2 * d2], pal, vh);
                    mma16816(O[2 * d2 + 1], pah, vh + 2);
                    mma16816(O[2 * d2 + 1], pah, vl + 2);
                    mma16816(O[2 * d2 + 1], pal, vh + 2);
                }
            }
        }

        const float inv0 = 1.f / lsum0;
        const float inv1 = 1.f / lsum1;
        const long grow0 = qrow0 + wid * 16 + r0;
        const long grow1 = grow0 + 8;
        if (seg == 0) {
#pragma unroll
            for (int j = 0; j < 16; ++j) {
                const int d = h * HD + j * 8 + colb;
                *(float2*)(g_O + grow0 * DIM + d) = make_float2(O[j][0] * inv0, O[j][1] * inv0);
                *(float2*)(g_O + grow1 * DIM + d) = make_float2(O[j][2] * inv1, O[j][3] * inv1);
            }
        } else {
#pragma unroll
            for (int j = 0; j < 16; ++j) {
                const int d = h * HD + j * 8 + colb;
                float2 p0 = *(float2*)(g_O + grow0 * DIM + d);
                float2 p1 = *(float2*)(g_O + grow1 * DIM + d);
                float v0 = p0.x + O[j][0] * inv0;
                float v1 = p0.y + O[j][1] * inv0;
                float v2 = p1.x + O[j][2] * inv1;
                float v3 = p1.y + O[j][3] * inv1;
                bf16 h0 = __float2bfloat16(v0), h1 = __float2bfloat16(v1);
                bf16 h2 = __float2bfloat16(v2), h3 = __float2bfloat16(v3);
                *(__nv_bfloat162*)(g_Oh + grow0 * DIM + d) = __nv_bfloat162(h0, h1);
                *(__nv_bfloat162*)(g_Oh + grow1 * DIM + d) = __nv_bfloat162(h2, h3);
                *(__nv_bfloat162*)(g_Ol + grow0 * DIM + d) =
                    __nv_bfloat162(__float2bfloat16(v0 - __bfloat162float(h0)),
                                   __float2bfloat16(v1 - __bfloat162float(h1)));
                *(__nv_bfloat162*)(g_Ol + grow1 * DIM + d) =
                    __nv_bfloat162(__float2bfloat16(v2 - __bfloat162float(h2)),
                                   __float2bfloat16(v3 - __bfloat162float(h3)));
            }
        }
    }
}

// ---------------- launch ----------------
extern "C" void kernel_launch(void* const* d_in, const int* in_sizes, int n_in,
                              void* d_out, int out_size) {
    const float* x       = (const float*)d_in[0];
    const float* context = (const float*)d_in[1];
    const float* Wq  = (const float*)d_in[3];
    const float* bq  = (const float*)d_in[4];
    const float* Wk  = (const float*)d_in[5];
    const float* bk  = (const float*)d_in[6];
    const float* Wv  = (const float*)d_in[7];
    const float* bv  = (const float*)d_in[8];
    const float* Wak = (const float*)d_in[9];
    const float* bak = (const float*)d_in[10];
    const float* Wav = (const float*)d_in[11];
    const float* bav = (const float*)d_in[12];
    const float* Wo  = (const float*)d_in[13];
    const float* bo  = (const float*)d_in[14];
    const float* gq  = (const float*)d_in[15];
    const float* gk  = (const float*)d_in[16];
    const float* gak = (const float*)d_in[17];
    float* out = (float*)d_out;

    float *Qp, *Kp, *Vp, *Kip, *Vip;
    bf16 *xh, *xl, *Oh, *Ol, *WqhT, *WqlT, *WohT, *WolT;
    bf16 *Qh, *Ql, *Kh, *Kl, *Vh, *Vl, *Kih, *Kil, *Vih, *Vil;
    cudaGetSymbolAddress((void**)&Qp, g_Q);
    cudaGetSymbolAddress((void**)&Kp, g_K);
    cudaGetSymbolAddress((void**)&Vp, g_V);
    cudaGetSymbolAddress((void**)&Kip, g_Ki);
    cudaGetSymbolAddress((void**)&Vip, g_Vi);
    cudaGetSymbolAddress((void**)&xh, g_xh);
    cudaGetSymbolAddress((void**)&xl, g_xl);
    cudaGetSymbolAddress((void**)&Oh, g_Oh);
    cudaGetSymbolAddress((void**)&Ol, g_Ol);
    cudaGetSymbolAddress((void**)&WqhT, g_WqhT);
    cudaGetSymbolAddress((void**)&WqlT, g_WqlT);
    cudaGetSymbolAddress((void**)&WohT, g_WohT);
    cudaGetSymbolAddress((void**)&WolT, g_WolT);
    cudaGetSymbolAddress((void**)&Qh, g_Qh);
    cudaGetSymbolAddress((void**)&Ql, g_Ql);
    cudaGetSymbolAddress((void**)&Kh, g_Kh);
    cudaGetSymbolAddress((void**)&Kl, g_Kl);
    cudaGetSymbolAddress((void**)&Vh, g_Vh);
    cudaGetSymbolAddress((void**)&Vl, g_Vl);
    cudaGetSymbolAddress((void**)&Kih, g_Kih);
    cudaGetSymbolAddress((void**)&Kil, g_Kil);
    cudaGetSymbolAddress((void**)&Vih, g_Vih);
    cudaGetSymbolAddress((void**)&Vil, g_Vil);

    const float* ctx_img = context;
    const float* ctx_txt = context + (long)IMG * DIM;

    static cudaStream_t s1 = nullptr, s2 = nullptr;
    static cudaEvent_t evFork = nullptr, evKV = nullptr, evA = nullptr, evS1 = nullptr;
    if (s1 == nullptr) {
        cudaStreamCreateWithFlags(&s1, cudaStreamNonBlocking);
        cudaStreamCreateWithFlags(&s2, cudaStreamNonBlocking);
        cudaEventCreateWithFlags(&evFork, cudaEventDisableTiming);
        cudaEventCreateWithFlags(&evKV, cudaEventDisableTiming);
        cudaEventCreateWithFlags(&evA, cudaEventDisableTiming);
        cudaEventCreateWithFlags(&evS1, cudaEventDisableTiming);
    }

    const float scale = 0.08838834764831843f;
    const int gemm_smem = NSTAGE * STAGE_B;
    cudaFuncSetAttribute(gemm_mma_bf16x3, cudaFuncAttributeMaxDynamicSharedMemorySize, gemm_smem);
    const int attn_smem = 2 * 128 * AST + 2 * KVST;
    cudaFuncSetAttribute(attn_mma, cudaFuncAttributeMaxDynamicSharedMemorySize, attn_smem);

    // ---- fork ----
    cudaEventRecord(evFork, 0);
    cudaStreamWaitEvent(s1, evFork, 0);
    cudaStreamWaitEvent(s2, evFork, 0);

    // s2: KV chain + Wo prep
    SmallJobs jobs;
    jobs.A[0] = ctx_txt; jobs.W[0] = Wk;  jobs.b[0] = bk;  jobs.C[0] = Kp;  jobs.M[0] = TXT;
    jobs.A[1] = ctx_txt; jobs.W[1] = Wv;  jobs.b[1] = bv;  jobs.C[1] = Vp;  jobs.M[1] = TXT;
    jobs.A[2] = ctx_img; jobs.W[2] = Wak; jobs.b[2] = bak; jobs.C[2] = Kip; jobs.M[2] = IMG;
    jobs.A[3] = ctx_img; jobs.W[3] = Wav; jobs.b[3] = bav; jobs.C[3] = Vip; jobs.M[3] = IMG;
    sgemm_small<<<dim3(DIM / 64, 4, 4), 256, 0, s2>>>(jobs);
    rmsnorm_split<<<TXT, 256, 0, s2>>>(Kp, gk, 1.f, Kh, Kl, TXT);
    rmsnorm_split<<<IMGP, 256, 0, s2>>>(Kip, gak, 1.f, Kih, Kil, IMG);
    split_pad<<<TXT, 256, 0, s2>>>(Vp, Vh, Vl, TXT);
    split_pad<<<IMGP, 256, 0, s2>>>(Vip, Vih, Vil, IMG);
    wsplitT_kernel<<<dim3(DIM / 32, DIM / 32), dim3(32, 8), 0, s2>>>(Wo, WohT, WolT);
    cudaEventRecord(evKV, s2);

    // main: input conversions + Q projection half 0
    long n4 = (long)NQ * DIM / 4;
    split_kernel<<<(unsigned)((n4 + 255) / 256), 256>>>(x, xh, xl, n4);
    wsplitT_kernel<<<dim3(DIM / 32, DIM / 32), dim3(32, 8)>>>(Wq, WqhT, WqlT);
    gemm_mma_bf16x3<<<dim3(DIM / 128, HALF / 128), 256, gemm_smem>>>(xh, xl, WqhT, WqlT, bq, Qp);
    cudaEventRecord(evA, 0);

    // s1: half-0 tail — rmsnorm(h0) -> attn(h0) -> outproj(h0)
    cudaStreamWaitEvent(s1, evA, 0);
    rmsnorm_split<<<HALF, 256, 0, s1>>>(Qp, gq, scale, Qh, Ql, HALF);
    cudaStreamWaitEvent(s1, evKV, 0);
    attn_mma<<<dim3(HALF / 128, HEADS), 256, attn_smem, s1>>>(0);
    gemm_mma_bf16x3<<<dim3(DIM / 128, HALF / 128), 256, gemm_smem, s1>>>(Oh, Ol, WohT, WolT, bo, out);
    cudaEventRecord(evS1, s1);

    // main: half-1 chain
    gemm_mma_bf16x3<<<dim3(DIM / 128, HALF / 128), 256, gemm_smem>>>(
        xh + (long)HALF * DIM, xl + (long)HALF * DIM, WqhT, WqlT, bq, Qp + (long)HALF * DIM);
    rmsnorm_split<<<HALF, 256>>>(Qp + (long)HALF * DIM, gq, scale,
                                 Qh + (long)HALF * DIM, Ql + (long)HALF * DIM, HALF);
    cudaStreamWaitEvent(0, evKV, 0);
    attn_mma<<<dim3(HALF / 128, HEADS), 256, attn_smem>>>(HALF / 128);
    gemm_mma_bf16x3<<<dim3(DIM / 128, HALF / 128), 256, gemm_smem>>>(
        Oh + (long)HALF * DIM, Ol + (long)HALF * DIM, WohT, WolT, bo, out + (long)HALF * DIM);

    // join
    cudaStreamWaitEvent(0, evS1, 0);
}

// round 10
// speedup vs baseline: 4.3555x; 1.3360x over previous
#include <cuda_runtime.h>
#include <cuda_fp16.h>
#include <cstdint>

#define DIM 1536
#define HEADS 12
#define HD 128
#define NQ 16384
#define HALF (NQ / 2)
#define IMG 257
#define TXT 512
#define IMGP 320   // img rows padded to multiple of 64

typedef __half h16;

// ---------------- scratch (no allocations allowed) ----------------
__device__ float g_Q[(long)NQ * DIM];
__device__ float g_O[(long)NQ * DIM];          // attention partial (txt segment)
__device__ float g_K[(long)TXT * DIM];
__device__ float g_V[(long)TXT * DIM];
__device__ float g_Ki[(long)IMG * DIM];
__device__ float g_Vi[(long)IMG * DIM];
__device__ h16 g_xh[(long)NQ * DIM];
__device__ h16 g_xl[(long)NQ * DIM];
__device__ h16 g_Qh[(long)NQ * DIM];
__device__ h16 g_Ql[(long)NQ * DIM];
__device__ h16 g_Oh[(long)NQ * DIM];
__device__ h16 g_Ol[(long)NQ * DIM];
__device__ h16 g_Kh[(long)TXT * DIM];
__device__ h16 g_Kl[(long)TXT * DIM];
__device__ h16 g_Vh[(long)TXT * DIM];
__device__ h16 g_Kih[(long)IMGP * DIM];
__device__ h16 g_Kil[(long)IMGP * DIM];
__device__ h16 g_Vih[(long)IMGP * DIM];
__device__ h16 g_WqT[(long)DIM * DIM];
__device__ h16 g_WoT[(long)DIM * DIM];

// ---------------- PTX helpers ----------------
__device__ __forceinline__ uint32_t s2u(const void* p) {
    return (uint32_t)__cvta_generic_to_shared(p);
}
__device__ __forceinline__ void cp16(uint32_t s, const void* g) {
    asm volatile("cp.async.cg.shared.global [%0], [%1], 16;\n" :: "r"(s), "l"(g) : "memory");
}
__device__ __forceinline__ void cp_commit() {
    asm volatile("cp.async.commit_group;\n" ::: "memory");
}
template <int N>
__device__ __forceinline__ void cp_wait() {
    asm volatile("cp.async.wait_group %0;\n" :: "n"(N) : "memory");
}
__device__ __forceinline__ void ldsm4(uint32_t* r, uint32_t a) {
    asm volatile("ldmatrix.sync.aligned.m8n8.x4.shared.b16 {%0,%1,%2,%3}, [%4];"
                 : "=r"(r[0]), "=r"(r[1]), "=r"(r[2]), "=r"(r[3]) : "r"(a));
}
__device__ __forceinline__ void ldsm4t(uint32_t* r, uint32_t a) {
    asm volatile("ldmatrix.sync.aligned.m8n8.x4.trans.shared.b16 {%0,%1,%2,%3}, [%4];"
                 : "=r"(r[0]), "=r"(r[1]), "=r"(r[2]), "=r"(r[3]) : "r"(a));
}
__device__ __forceinline__ void mma16816(float* c, const uint32_t* a, const uint32_t* b) {
    asm volatile(
        "mma.sync.aligned.m16n8k16.row.col.f32.f16.f16.f32 "
        "{%0,%1,%2,%3}, {%4,%5,%6,%7}, {%8,%9}, {%0,%1,%2,%3};"
        : "+f"(c[0]), "+f"(c[1]), "+f"(c[2]), "+f"(c[3])
        : "r"(a[0]), "r"(a[1]), "r"(a[2]), "r"(a[3]), "r"(b[0]), "r"(b[1]));
}
__device__ __forceinline__ uint32_t packh(float a, float b) {
    __half2 t = __floats2half2_rn(a, b);
    return *(uint32_t*)&t;
}

// ---------------- fp16x2 HMMA GEMM: C = (Ah+Al) @ BT^T + bias ----------------
#define GSTRIDE 80
#define TILE_B (128 * GSTRIDE)
#define STAGE_B (3 * TILE_B)   // Ah, Al, Bh
#define NSTAGE 3

__global__ __launch_bounds__(256, 2)
void gemm_mma_f16x2(const h16* __restrict__ Ah, const h16* __restrict__ Al,
                    const h16* __restrict__ BT,
                    const float* __restrict__ bias, float* __restrict__ C) {
    extern __shared__ char dynsm[];
    const uint32_t smem0 = s2u(dynsm);
    const int tid = threadIdx.x;
    const int lane = tid & 31;
    const int wid = tid >> 5;
    const int wm = wid & 3;
    const int wn = wid >> 2;
    const int m0 = blockIdx.y * 128;
    const int n0 = blockIdx.x * 128;

    const h16* srcs[3] = {Ah, Al, BT};
    const int bases[3] = {m0, m0, n0};

    auto load_stage = [&](int slot, int k0) {
        const uint32_t sb = smem0 + slot * STAGE_B;
#pragma unroll
        for (int t = 0; t < 6; ++t) {
            const int ch = tid + t * 256;      // 1536 chunks
            const int tile = ch >> 9;
            const int idx = ch & 511;
            const int row = idx >> 2;
            const int cb = idx & 3;
            const uint32_t so = sb + tile * TILE_B + row * GSTRIDE + cb * 16;
            const h16* g = srcs[tile] + (size_t)(bases[tile] + row) * DIM + k0 + cb * 8;
            cp16(so, g);
        }
        cp_commit();
    };

    for (int s = 0; s < NSTAGE; ++s) load_stage(s, s * 32);

    float acc[2][8][4];
#pragma unroll
    for (int mi = 0; mi < 2; ++mi)
#pragma unroll
        for (int nj = 0; nj < 8; ++nj)
#pragma unroll
            for (int r = 0; r < 4; ++r) acc[mi][nj][r] = 0.f;

    const int rowA = wm * 32 + (lane & 15);
    const int acol = (lane >> 4) * 16;
    const int rowB = wn * 64 + (lane >> 4) * 8 + (lane & 7);
    const int bcol = ((lane >> 3) & 1) * 16;

    constexpr int NKC = DIM / 32;
    for (int i = 0; i < NKC; ++i) {
        const int slot = i % NSTAGE;
        const uint32_t sb = smem0 + slot * STAGE_B;
        cp_wait<NSTAGE - 1>();
        __syncthreads();

        const uint32_t aAh = sb + rowA * GSTRIDE + acol;
        const uint32_t aAl = aAh + TILE_B;
        const uint32_t aBh = sb + 2 * TILE_B + rowB * GSTRIDE + bcol;

#pragma unroll
        for (int k16 = 0; k16 < 2; ++k16) {
            const uint32_t ko = k16 * 32;
            uint32_t ah[2][4], al[2][4], bh[4][4];
#pragma unroll
            for (int mi = 0; mi < 2; ++mi) {
                ldsm4(ah[mi], aAh + mi * 16 * GSTRIDE + ko);
                ldsm4(al[mi], aAl + mi * 16 * GSTRIDE + ko);
            }
#pragma unroll
            for (int ni = 0; ni < 4; ++ni)
                ldsm4(bh[ni], aBh + ni * 16 * GSTRIDE + ko);
#pragma unroll
            for (int mi = 0; mi < 2; ++mi)
#pragma unroll
                for (int nj = 0; nj < 8; ++nj) {
                    const uint32_t* bhp = &bh[nj >> 1][(nj & 1) * 2];
                    mma16816(acc[mi][nj], ah[mi], bhp);
                    mma16816(acc[mi][nj], al[mi], bhp);
                }
        }
        __syncthreads();
        if (i + NSTAGE < NKC) load_stage(slot, (i + NSTAGE) * 32);
        else cp_commit();
    }

    const int crow0 = m0 + wm * 32 + (lane >> 2);
    const int ccol0 = n0 + wn * 64 + (lane & 3) * 2;
#pragma unroll
    for (int nj = 0; nj < 8; ++nj) {
        const int col = ccol0 + nj * 8;
        const float b0 = bias[col], b1 = bias[col + 1];
#pragma unroll
        for (int mi = 0; mi < 2; ++mi) {
            float* c0 = C + (size_t)(crow0 + mi * 16) * DIM + col;
            float* c1 = c0 + 8 * DIM;
            *(float2*)c0 = make_float2(acc[mi][nj][0] + b0, acc[mi][nj][1] + b1);
            *(float2*)c1 = make_float2(acc[mi][nj][2] + b0, acc[mi][nj][3] + b1);
        }
    }
}

// ---------------- split fp32 -> fp16 hi/lo (flat) ----------------
__global__ __launch_bounds__(256)
void split_kernel(const float* __restrict__ X, h16* __restrict__ H, h16* __restrict__ L, long n4) {
    long i = ((long)blockIdx.x * 256 + threadIdx.x);
    if (i >= n4) return;
    float4 v = *((const float4*)X + i);
    float vv[4] = {v.x, v.y, v.z, v.w};
    h16 hh[4], ll[4];
#pragma unroll
    for (int j = 0; j < 4; ++j) {
        hh[j] = __float2half(vv[j]);
        ll[j] = __float2half(vv[j] - __half2float(hh[j]));
    }
    __half2* Hp = (__half2*)H + i * 2;
    __half2* Lp = (__half2*)L + i * 2;
    Hp[0] = __half2(hh[0], hh[1]);
    Hp[1] = __half2(hh[2], hh[3]);
    Lp[0] = __half2(ll[0], ll[1]);
    Lp[1] = __half2(ll[2], ll[3]);
}

// ---------------- transpose weights to single fp16 ----------------
__global__ __launch_bounds__(256)
void wT_kernel(const float* __restrict__ W, h16* __restrict__ Ht) {
    __shared__ float t[32][33];
    const int k0 = blockIdx.y * 32, n0 = blockIdx.x * 32;
    const int tx = threadIdx.x, ty = threadIdx.y;
#pragma unroll
    for (int j = 0; j < 4; ++j)
        t[ty + j * 8][tx] = W[(size_t)(k0 + ty + j * 8) * DIM + n0 + tx];
    __syncthreads();
#pragma unroll
    for (int j = 0; j < 4; ++j)
        Ht[(size_t)(n0 + ty + j * 8) * DIM + k0 + tx] = __float2half(t[tx][ty + j * 8]);
}

// ---------------- small fused SGEMM ----------------
struct SmallJobs {
    const float* A[4];
    const float* W[4];
    const float* b[4];
    float* C[4];
    int M[4];
};

__global__ __launch_bounds__(256)
void sgemm_small(SmallJobs jobs) {
    const int z = blockIdx.z;
    const float* A = jobs.A[z];
    const float* B = jobs.W[z];
    const float* bias = jobs.b[z];
    float* C = jobs.C[z];
    const int M = jobs.M[z];
    const int N = DIM, K = DIM;

    const int m0 = blockIdx.y * 128;
    if (m0 >= M) return;
    const int n0 = blockIdx.x * 64;

    __shared__ float As[16 * 132];
    __shared__ float Bs[16 * 64];
    const int tid = threadIdx.x;
    const int tx = tid & 15;
    const int ty = tid >> 4;
    const int arow = tid >> 1;
    const int ak = (tid & 1) * 8;
    const int brow = tid >> 4;
    const int bcol = (tid & 15) * 4;

    float acc[8][4];
#pragma unroll
    for (int i = 0; i < 8; ++i)
#pragma unroll
        for (int j = 0; j < 4; ++j) acc[i][j] = 0.f;

    const bool avalid = (m0 + arow) < M;
    const float* Aptr = A + (long)(m0 + arow) * K + ak;
    const float* Bptr = B + (long)brow * N + n0 + bcol;

    for (int k0 = 0; k0 < K; k0 += 16) {
        float4 a0 = make_float4(0.f, 0.f, 0.f, 0.f);
        float4 a1 = make_float4(0.f, 0.f, 0.f, 0.f);
        if (avalid) {
            a0 = *(const float4*)(Aptr + k0);
            a1 = *(const float4*)(Aptr + k0 + 4);
        }
        As[(ak + 0) * 132 + arow] = a0.x;
        As[(ak + 1) * 132 + arow] = a0.y;
        As[(ak + 2) * 132 + arow] = a0.z;
        As[(ak + 3) * 132 + arow] = a0.w;
        As[(ak + 4) * 132 + arow] = a1.x;
        As[(ak + 5) * 132 + arow] = a1.y;
        As[(ak + 6) * 132 + arow] = a1.z;
        As[(ak + 7) * 132 + arow] = a1.w;
        *(float4*)(Bs + brow * 64 + bcol) = *(const float4*)(Bptr + (long)k0 * N);
        __syncthreads();
#pragma unroll
        for (int kk = 0; kk < 16; ++kk) {
            float4 x0 = *(const float4*)(As + kk * 132 + ty * 8);
            float4 x1 = *(const float4*)(As + kk * 132 + ty * 8 + 4);
            float4 y = *(const float4*)(Bs + kk * 64 + tx * 4);
            float a[8] = {x0.x, x0.y, x0.z, x0.w, x1.x, x1.y, x1.z, x1.w};
            float b[4] = {y.x, y.y, y.z, y.w};
#pragma unroll
            for (int i = 0; i < 8; ++i)
#pragma unroll
                for (int j = 0; j < 4; ++j) acc[i][j] += a[i] * b[j];
        }
        __syncthreads();
    }

    float4 bv = *(const float4*)(bias + n0 + tx * 4);
    float bb[4] = {bv.x, bv.y, bv.z, bv.w};
#pragma unroll
    for (int i = 0; i < 8; ++i) {
        int m = m0 + ty * 8 + i;
        if (m < M) {
            float4 out;
            out.x = acc[i][0] + bb[0];
            out.y = acc[i][1] + bb[1];
            out.z = acc[i][2] + bb[2];
            out.w = acc[i][3] + bb[3];
            *(float4*)(C + (long)m * N + n0 + tx * 4) = out;
        }
    }
}

// ---------------- RMSNorm + fp16 hi/lo split, zero-pad rows >= nvalid ----------------
__global__ __launch_bounds__(256)
void rmsnorm_split(const float* __restrict__ X, const float* __restrict__ g, float scale,
                   h16* __restrict__ H, h16* __restrict__ L, int nvalid) {
    const int r = blockIdx.x;
    const int tid = threadIdx.x;
    if (r >= nvalid) {
#pragma unroll
        for (int i = 0; i < 6; ++i) {
            H[(long)r * DIM + tid + i * 256] = __float2half(0.f);
            L[(long)r * DIM + tid + i * 256] = __float2half(0.f);
        }
        return;
    }
    const float* x = X + (long)r * DIM;
    float v[6];
    float ss = 0.f;
#pragma unroll
    for (int i = 0; i < 6; ++i) {
        v[i] = x[tid + i * 256];
        ss += v[i] * v[i];
    }
#pragma unroll
    for (int off = 16; off >= 1; off >>= 1)
        ss += __shfl_xor_sync(0xffffffffu, ss, off);
    __shared__ float red[8];
    if ((tid & 31) == 0) red[tid >> 5] = ss;
    __syncthreads();
    float tot = 0.f;
#pragma unroll
    for (int i = 0; i < 8; ++i) tot += red[i];
    const float rms = rsqrtf(tot * (1.f / (float)DIM) + 1e-6f);
#pragma unroll
    for (int i = 0; i < 6; ++i) {
        float val = v[i] * rms * g[tid + i * 256] * scale;
        h16 h = __float2half(val);
        h16 l = __float2half(val - __half2float(h));
        H[(long)r * DIM + tid + i * 256] = h;
        L[(long)r * DIM + tid + i * 256] = l;
    }
}

// ---------------- fp16 (single) row convert with zero-pad ----------------
__global__ __launch_bounds__(256)
void tohalf_pad(const float* __restrict__ X, h16* __restrict__ H, int nvalid) {
    const int r = blockIdx.x;
    const int tid = threadIdx.x;
#pragma unroll
    for (int i = 0; i < 6; ++i) {
        float val = (r < nvalid) ? X[(long)r * DIM + tid + i * 256] : 0.f;
        H[(long)r * DIM + tid + i * 256] = __float2half(val);
    }
}

// ---------------- HMMA flash attention ----------------
// QK fp16x3 (Q hi/lo x K hi/lo); PV fp16x2 (P hi/lo x V single). KV double-buffered.
#define AST 272            // smem row stride bytes (128 fp16 + 16B pad)
#define KVROW (64 * AST)   // one 64-row array
#define KVST (3 * KVROW)   // Kh, Kl, Vh per stage

__global__ __launch_bounds__(256, 1)
void attn_mma(int qb0) {
    extern __shared__ char smem[];
    const uint32_t sQh = s2u(smem);
    const uint32_t sQl = sQh + 128 * AST;
    const uint32_t sKV = sQl + 128 * AST;   // 2 stages of KVST

    const int tid = threadIdx.x, lane = tid & 31, wid = tid >> 5;
    const int qb = blockIdx.x + qb0, h = blockIdx.y;
    const long qrow0 = (long)qb * 128;

    // Q load (its own commit group)
    {
        const h16* Qhg = g_Qh + qrow0 * DIM + h * HD;
        const h16* Qlg = g_Ql + qrow0 * DIM + h * HD;
#pragma unroll
        for (int t = 0; t < 8; ++t) {
            int c = tid + t * 256;
            int r = c >> 4, cb = c & 15;
            cp16(sQh + r * AST + cb * 16, Qhg + (long)r * DIM + cb * 8);
            cp16(sQl + r * AST + cb * 16, Qlg + (long)r * DIM + cb * 8);
        }
        cp_commit();
    }

    const uint32_t qoff = (uint32_t)((wid * 16 + (lane & 15)) * AST + (lane >> 4) * 16);
    const uint32_t koff = (uint32_t)((((lane >> 4) << 3) + (lane & 7)) * AST + ((lane >> 3) & 1) * 16);
    const uint32_t voff = (uint32_t)(((((lane >> 3) & 1) << 3) + (lane & 7)) * AST + (lane >> 4) * 16);

    const int r0 = lane >> 2;
    const int colb = (lane & 3) * 2;

#pragma unroll 1
    for (int seg = 0; seg < 2; ++seg) {
        const h16 *Khg, *Klg, *Vhg;
        int len, ntiles;
        if (seg == 0) {
            Khg = g_Kh; Klg = g_Kl; Vhg = g_Vh;
            len = TXT; ntiles = TXT / 64;
        } else {
            Khg = g_Kih; Klg = g_Kil; Vhg = g_Vih;
            len = IMG; ntiles = IMGP / 64;
        }

        auto load_kv = [&](int stage, int t) {
            const uint32_t sb = sKV + stage * KVST;
            const long kvbase = (long)t * 64 * DIM + h * HD;
            const h16* arrs[3] = {Khg, Klg, Vhg};
#pragma unroll
            for (int tt = 0; tt < 12; ++tt) {
                int c = tid + tt * 256;       // 3072 chunks
                int arr = c >> 10;
                int idx = c & 1023;
                int r = idx >> 4, cb = idx & 15;
                cp16(sb + arr * KVROW + r * AST + cb * 16,
                     arrs[arr] + kvbase + (long)r * DIM + cb * 8);
            }
            cp_commit();
        };

        load_kv(0, 0);  // prologue

        float mrow0 = -1e30f, mrow1 = -1e30f, lsum0 = 0.f, lsum1 = 0.f;
        float O[16][4];
#pragma unroll
        for (int j = 0; j < 16; ++j)
#pragma unroll
            for (int e = 0; e < 4; ++e) O[j][e] = 0.f;

#pragma unroll 1
        for (int t = 0; t < ntiles; ++t) {
            __syncthreads();   // all warps finished reading buffer (t+1)&1 (from iter t-1)
            if (t + 1 < ntiles) {
                load_kv((t + 1) & 1, t + 1);
                cp_wait<1>();
            } else {
                cp_wait<0>();
            }
            __syncthreads();   // buffer t&1 visible to all

            const uint32_t sb = sKV + (t & 1) * KVST;
            const uint32_t sKh_ = sb, sKl_ = sb + KVROW, sVh_ = sb + 2 * KVROW;

            // ---- S = Q K^T (fp16x3) ----
            float S[8][4];
#pragma unroll
            for (int j = 0; j < 8; ++j)
#pragma unroll
                for (int e = 0; e < 4; ++e) S[j][e] = 0.f;
#pragma unroll
            for (int k16 = 0; k16 < 8; ++k16) {
                uint32_t ah[4], al[4];
                ldsm4(ah, sQh + qoff + k16 * 32);
                ldsm4(al, sQl + qoff + k16 * 32);
#pragma unroll
                for (int nt2 = 0; nt2 < 4; ++nt2) {
                    uint32_t bh[4], bl[4];
                    ldsm4(bh, sKh_ + koff + nt2 * 16 * AST + k16 * 32);
                    ldsm4(bl, sKl_ + koff + nt2 * 16 * AST + k16 * 32);
                    mma16816(S[2 * nt2], ah, bh);
                    mma16816(S[2 * nt2], ah, bl);
                    mma16816(S[2 * nt2], al, bh);
                    mma16816(S[2 * nt2 + 1], ah, bh + 2);
                    mma16816(S[2 * nt2 + 1], ah, bl + 2);
                    mma16816(S[2 * nt2 + 1], al, bh + 2);
                }
            }

            // ---- online softmax ----
            const int t0 = t * 64;
            if (t0 + 64 > len) {
#pragma unroll
                for (int j = 0; j < 8; ++j) {
#pragma unroll
                    for (int e = 0; e < 2; ++e) {
                        if (t0 + j * 8 + colb + e >= len) {
                            S[j][e] = -1e30f;
                            S[j][2 + e] = -1e30f;
                        }
                    }
                }
            }
            float mx0 = -1e30f, mx1 = -1e30f;
#pragma unroll
            for (int j = 0; j < 8; ++j) {
                mx0 = fmaxf(mx0, fmaxf(S[j][0], S[j][1]));
                mx1 = fmaxf(mx1, fmaxf(S[j][2], S[j][3]));
            }
            mx0 = fmaxf(mx0, __shfl_xor_sync(0xffffffffu, mx0, 1));
            mx0 = fmaxf(mx0, __shfl_xor_sync(0xffffffffu, mx0, 2));
            mx1 = fmaxf(mx1, __shfl_xor_sync(0xffffffffu, mx1, 1));
            mx1 = fmaxf(mx1, __shfl_xor_sync(0xffffffffu, mx1, 2));
            const float nm0 = fmaxf(mrow0, mx0);
            const float nm1 = fmaxf(mrow1, mx1);
            const float sc0 = __expf(mrow0 - nm0);
            const float sc1 = __expf(mrow1 - nm1);
            mrow0 = nm0; mrow1 = nm1;

            uint32_t Ph[8][2], Pl[8][2];
            float rs0 = 0.f, rs1 = 0.f;
#pragma unroll
            for (int j = 0; j < 8; ++j) {
                float p0 = __expf(S[j][0] - nm0);
                float p1 = __expf(S[j][1] - nm0);
                float p2 = __expf(S[j][2] - nm1);
                float p3 = __expf(S[j][3] - nm1);
                rs0 += p0 + p1;
                rs1 += p2 + p3;
                Ph[j][0] = packh(p0, p1);
                Ph[j][1] = packh(p2, p3);
                __half2 h01 = *(__half2*)&Ph[j][0];
                __half2 h23 = *(__half2*)&Ph[j][1];
                Pl[j][0] = packh(p0 - __half2float(h01.x), p1 - __half2float(h01.y));
                Pl[j][1] = packh(p2 - __half2float(h23.x), p3 - __half2float(h23.y));
            }
            rs0 += __shfl_xor_sync(0xffffffffu, rs0, 1);
            rs0 += __shfl_xor_sync(0xffffffffu, rs0, 2);
            rs1 += __shfl_xor_sync(0xffffffffu, rs1, 1);
            rs1 += __shfl_xor_sync(0xffffffffu, rs1, 2);
            lsum0 = lsum0 * sc0 + rs0;
            lsum1 = lsum1 * sc1 + rs1;
#pragma unroll
            for (int j = 0; j < 16; ++j) {
                O[j][0] *= sc0; O[j][1] *= sc0;
                O[j][2] *= sc1; O[j][3] *= sc1;
            }

            // ---- O += P V (fp16x2: (Ph+Pl) x Vh) ----
#pragma unroll
            for (int s = 0; s < 4; ++s) {
                uint32_t pah[4] = {Ph[2 * s][0], Ph[2 * s][1], Ph[2 * s + 1][0], Ph[2 * s + 1][1]};
                uint32_t pal[4] = {Pl[2 * s][0], Pl[2 * s][1], Pl[2 * s + 1][0], Pl[2 * s + 1][1]};
#pragma unroll
                for (int d2 = 0; d2 < 8; ++d2) {
                    uint32_t vh[4];
                    ldsm4t(vh, sVh_ + voff + s * 16 * AST + d2 * 32);
                    mma16816(O[2 * d2], pah, vh);
                    mma16816(O[2 * d2], pal, vh);
                    mma16816(O[2 * d2 + 1], pah, vh + 2);
                    mma16816(O[2 * d2 + 1], pal, vh + 2);
                }
            }
        }

        const float inv0 = 1.f / lsum0;
        const float inv1 = 1.f / lsum1;
        const long grow0 = qrow0 + wid * 16 + r0;
        const long grow1 = grow0 + 8;
        if (seg == 0) {
#pragma unroll
            for (int j = 0; j < 16; ++j) {
                const int d = h * HD + j * 8 + colb;
                *(float2*)(g_O + grow0 * DIM + d) = make_float2(O[j][0] * inv0, O[j][1] * inv0);
                *(float2*)(g_O + grow1 * DIM + d) = make_float2(O[j][2] * inv1, O[j][3] * inv1);
            }
        } else {
#pragma unroll
            for (int j = 0; j < 16; ++j) {
                const int d = h * HD + j * 8 + colb;
                float2 p0 = *(float2*)(g_O + grow0 * DIM + d);
                float2 p1 = *(float2*)(g_O + grow1 * DIM + d);
                float v0 = p0.x + O[j][0] * inv0;
                float v1 = p0.y + O[j][1] * inv0;
                float v2 = p1.x + O[j][2] * inv1;
                float v3 = p1.y + O[j][3] * inv1;
                h16 h0 = __float2half(v0), h1 = __float2half(v1);
                h16 h2 = __float2half(v2), h3 = __float2half(v3);
                *(__half2*)(g_Oh + grow0 * DIM + d) = __half2(h0, h1);
                *(__half2*)(g_Oh + grow1 * DIM + d) = __half2(h2, h3);
                *(__half2*)(g_Ol + grow0 * DIM + d) =
                    __half2(__float2half(v0 - __half2float(h0)),
                            __float2half(v1 - __half2float(h1)));
                *(__half2*)(g_Ol + grow1 * DIM + d) =
                    __half2(__float2half(v2 - __half2float(h2)),
                            __float2half(v3 - __half2float(h3)));
            }
        }
    }
}

// ---------------- launch ----------------
extern "C" void kernel_launch(void* const* d_in, const int* in_sizes, int n_in,
                              void* d_out, int out_size) {
    const float* x       = (const float*)d_in[0];
    const float* context = (const float*)d_in[1];
    const float* Wq  = (const float*)d_in[3];
    const float* bq  = (const float*)d_in[4];
    const float* Wk  = (const float*)d_in[5];
    const float* bk  = (const float*)d_in[6];
    const float* Wv  = (const float*)d_in[7];
    const float* bv  = (const float*)d_in[8];
    const float* Wak = (const float*)d_in[9];
    const float* bak = (const float*)d_in[10];
    const float* Wav = (const float*)d_in[11];
    const float* bav = (const float*)d_in[12];
    const float* Wo  = (const float*)d_in[13];
    const float* bo  = (const float*)d_in[14];
    const float* gq  = (const float*)d_in[15];
    const float* gk  = (const float*)d_in[16];
    const float* gak = (const float*)d_in[17];
    float* out = (float*)d_out;

    float *Qp, *Kp, *Vp, *Kip, *Vip;
    h16 *xh, *xl, *Oh, *Ol, *WqT, *WoT;
    h16 *Qh, *Ql, *Kh, *Kl, *Vh, *Kih, *Kil, *Vih;
    cudaGetSymbolAddress((void**)&Qp, g_Q);
    cudaGetSymbolAddress((void**)&Kp, g_K);
    cudaGetSymbolAddress((void**)&Vp, g_V);
    cudaGetSymbolAddress((void**)&Kip, g_Ki);
    cudaGetSymbolAddress((void**)&Vip, g_Vi);
    cudaGetSymbolAddress((void**)&xh, g_xh);
    cudaGetSymbolAddress((void**)&xl, g_xl);
    cudaGetSymbolAddress((void**)&Oh, g_Oh);
    cudaGetSymbolAddress((void**)&Ol, g_Ol);
    cudaGetSymbolAddress((void**)&WqT, g_WqT);
    cudaGetSymbolAddress((void**)&WoT, g_WoT);
    cudaGetSymbolAddress((void**)&Qh, g_Qh);
    cudaGetSymbolAddress((void**)&Ql, g_Ql);
    cudaGetSymbolAddress((void**)&Kh, g_Kh);
    cudaGetSymbolAddress((void**)&Kl, g_Kl);
    cudaGetSymbolAddress((void**)&Vh, g_Vh);
    cudaGetSymbolAddress((void**)&Kih, g_Kih);
    cudaGetSymbolAddress((void**)&Kil, g_Kil);
    cudaGetSymbolAddress((void**)&Vih, g_Vih);

    const float* ctx_img = context;
    const float* ctx_txt = context + (long)IMG * DIM;

    static cudaStream_t s1 = nullptr, s2 = nullptr;
    static cudaEvent_t evFork = nullptr, evKV = nullptr, evA = nullptr, evS1 = nullptr;
    if (s1 == nullptr) {
        cudaStreamCreateWithFlags(&s1, cudaStreamNonBlocking);
        cudaStreamCreateWithFlags(&s2, cudaStreamNonBlocking);
        cudaEventCreateWithFlags(&evFork, cudaEventDisableTiming);
        cudaEventCreateWithFlags(&evKV, cudaEventDisableTiming);
        cudaEventCreateWithFlags(&evA, cudaEventDisableTiming);
        cudaEventCreateWithFlags(&evS1, cudaEventDisableTiming);
    }

    const float scale = 0.08838834764831843f;
    const int gemm_smem = NSTAGE * STAGE_B;
    cudaFuncSetAttribute(gemm_mma_f16x2, cudaFuncAttributeMaxDynamicSharedMemorySize, gemm_smem);
    const int attn_smem = 2 * 128 * AST + 2 * KVST;
    cudaFuncSetAttribute(attn_mma, cudaFuncAttributeMaxDynamicSharedMemorySize, attn_smem);

    // ---- fork ----
    cudaEventRecord(evFork, 0);
    cudaStreamWaitEvent(s1, evFork, 0);
    cudaStreamWaitEvent(s2, evFork, 0);

    // s2: KV chain + Wo prep
    SmallJobs jobs;
    jobs.A[0] = ctx_txt; jobs.W[0] = Wk;  jobs.b[0] = bk;  jobs.C[0] = Kp;  jobs.M[0] = TXT;
    jobs.A[1] = ctx_txt; jobs.W[1] = Wv;  jobs.b[1] = bv;  jobs.C[1] = Vp;  jobs.M[1] = TXT;
    jobs.A[2] = ctx_img; jobs.W[2] = Wak; jobs.b[2] = bak; jobs.C[2] = Kip; jobs.M[2] = IMG;
    jobs.A[3] = ctx_img; jobs.W[3] = Wav; jobs.b[3] = bav; jobs.C[3] = Vip; jobs.M[3] = IMG;
    sgemm_small<<<dim3(DIM / 64, 4, 4), 256, 0, s2>>>(jobs);
    rmsnorm_split<<<TXT, 256, 0, s2>>>(Kp, gk, 1.f, Kh, Kl, TXT);
    rmsnorm_split<<<IMGP, 256, 0, s2>>>(Kip, gak, 1.f, Kih, Kil, IMG);
    tohalf_pad<<<TXT, 256, 0, s2>>>(Vp, Vh, TXT);
    tohalf_pad<<<IMGP, 256, 0, s2>>>(Vip, Vih, IMG);
    wT_kernel<<<dim3(DIM / 32, DIM / 32), dim3(32, 8), 0, s2>>>(Wo, WoT);
    cudaEventRecord(evKV, s2);

    // main: input conversions + Q projection half 0
    long n4 = (long)NQ * DIM / 4;
    split_kernel<<<(unsigned)((n4 + 255) / 256), 256>>>(x, xh, xl, n4);
    wT_kernel<<<dim3(DIM / 32, DIM / 32), dim3(32, 8)>>>(Wq, WqT);
    gemm_mma_f16x2<<<dim3(DIM / 128, HALF / 128), 256, gemm_smem>>>(xh, xl, WqT, bq, Qp);
    cudaEventRecord(evA, 0);

    // s1: half-0 tail — rmsnorm(h0) -> attn(h0) -> outproj(h0)
    cudaStreamWaitEvent(s1, evA, 0);
    rmsnorm_split<<<HALF, 256, 0, s1>>>(Qp, gq, scale, Qh, Ql, HALF);
    cudaStreamWaitEvent(s1, evKV, 0);
    attn_mma<<<dim3(HALF / 128, HEADS), 256, attn_smem, s1>>>(0);
    gemm_mma_f16x2<<<dim3(DIM / 128, HALF / 128), 256, gemm_smem, s1>>>(Oh, Ol, WoT, bo, out);
    cudaEventRecord(evS1, s1);

    // main: half-1 chain
    gemm_mma_f16x2<<<dim3(DIM / 128, HALF / 128), 256, gemm_smem>>>(
        xh + (long)HALF * DIM, xl + (long)HALF * DIM, WqT, bq, Qp + (long)HALF * DIM);
    rmsnorm_split<<<HALF, 256>>>(Qp + (long)HALF * DIM, gq, scale,
                                 Qh + (long)HALF * DIM, Ql + (long)HALF * DIM, HALF);
    cudaStreamWaitEvent(0, evKV, 0);
    attn_mma<<<dim3(HALF / 128, HEADS), 256, attn_smem>>>(HALF / 128);
    gemm_mma_f16x2<<<dim3(DIM / 128, HALF / 128), 256, gemm_smem>>>(
        Oh + (long)HALF * DIM, Ol + (long)HALF * DIM, WoT, bo, out + (long)HALF * DIM);

    // join
    cudaStreamWaitEvent(0, evS1, 0);
}

// round 11
// speedup vs baseline: 6.2683x; 1.4392x over previous
#include <cuda_runtime.h>
#include <cuda_fp16.h>
#include <cstdint>

#define DIM 1536
#define HEADS 12
#define HD 128
#define NQ 16384
#define HALF (NQ / 2)
#define IMG 257
#define TXT 512
#define IMGP 320   // img rows padded to multiple of 64

typedef __half h16;

// ---------------- scratch (no allocations allowed) ----------------
__device__ float g_Q[(long)NQ * DIM];
__device__ float g_O[(long)NQ * DIM];          // attention partial (txt segment)
__device__ float g_K[(long)TXT * DIM];
__device__ float g_V[(long)TXT * DIM];
__device__ float g_Ki[(long)IMG * DIM];
__device__ float g_Vi[(long)IMG * DIM];
__device__ h16 g_xh[(long)NQ * DIM];
__device__ h16 g_Qh[(long)NQ * DIM];
__device__ h16 g_Ql[(long)NQ * DIM];
__device__ h16 g_Oh[(long)NQ * DIM];
__device__ h16 g_Kh[(long)TXT * DIM];
__device__ h16 g_Vh[(long)TXT * DIM];
__device__ h16 g_Kih[(long)IMGP * DIM];
__device__ h16 g_Vih[(long)IMGP * DIM];
__device__ h16 g_WqT[(long)DIM * DIM];
__device__ h16 g_WoT[(long)DIM * DIM];

// ---------------- PTX helpers ----------------
__device__ __forceinline__ uint32_t s2u(const void* p) {
    return (uint32_t)__cvta_generic_to_shared(p);
}
__device__ __forceinline__ void cp16(uint32_t s, const void* g) {
    asm volatile("cp.async.cg.shared.global [%0], [%1], 16;\n" :: "r"(s), "l"(g) : "memory");
}
__device__ __forceinline__ void cp_commit() {
    asm volatile("cp.async.commit_group;\n" ::: "memory");
}
template <int N>
__device__ __forceinline__ void cp_wait() {
    asm volatile("cp.async.wait_group %0;\n" :: "n"(N) : "memory");
}
__device__ __forceinline__ void ldsm4(uint32_t* r, uint32_t a) {
    asm volatile("ldmatrix.sync.aligned.m8n8.x4.shared.b16 {%0,%1,%2,%3}, [%4];"
                 : "=r"(r[0]), "=r"(r[1]), "=r"(r[2]), "=r"(r[3]) : "r"(a));
}
__device__ __forceinline__ void ldsm4t(uint32_t* r, uint32_t a) {
    asm volatile("ldmatrix.sync.aligned.m8n8.x4.trans.shared.b16 {%0,%1,%2,%3}, [%4];"
                 : "=r"(r[0]), "=r"(r[1]), "=r"(r[2]), "=r"(r[3]) : "r"(a));
}
__device__ __forceinline__ void mma16816(float* c, const uint32_t* a, const uint32_t* b) {
    asm volatile(
        "mma.sync.aligned.m16n8k16.row.col.f32.f16.f16.f32 "
        "{%0,%1,%2,%3}, {%4,%5,%6,%7}, {%8,%9}, {%0,%1,%2,%3};"
        : "+f"(c[0]), "+f"(c[1]), "+f"(c[2]), "+f"(c[3])
        : "r"(a[0]), "r"(a[1]), "r"(a[2]), "r"(a[3]), "r"(b[0]), "r"(b[1]));
}
__device__ __forceinline__ uint32_t packh(float a, float b) {
    __half2 t = __floats2half2_rn(a, b);
    return *(uint32_t*)&t;
}

// ---------------- single-pass fp16 HMMA GEMM: C = A @ BT^T + bias ----------------
#define GSTRIDE 80
#define TILE_B (128 * GSTRIDE)
#define STAGE_B (2 * TILE_B)   // A, B
#define NSTAGE 4

__global__ __launch_bounds__(256, 2)
void gemm_mma_f16(const h16* __restrict__ A, const h16* __restrict__ BT,
                  const float* __restrict__ bias, float* __restrict__ C) {
    extern __shared__ char dynsm[];
    const uint32_t smem0 = s2u(dynsm);
    const int tid = threadIdx.x;
    const int lane = tid & 31;
    const int wid = tid >> 5;
    const int wm = wid & 3;
    const int wn = wid >> 2;
    const int m0 = blockIdx.y * 128;
    const int n0 = blockIdx.x * 128;

    const h16* srcs[2] = {A, BT};
    const int bases[2] = {m0, n0};

    auto load_stage = [&](int slot, int k0) {
        const uint32_t sb = smem0 + slot * STAGE_B;
#pragma unroll
        for (int t = 0; t < 4; ++t) {
            const int ch = tid + t * 256;      // 1024 chunks
            const int tile = ch >> 9;
            const int idx = ch & 511;
            const int row = idx >> 2;
            const int cb = idx & 3;
            const uint32_t so = sb + tile * TILE_B + row * GSTRIDE + cb * 16;
            const h16* g = srcs[tile] + (size_t)(bases[tile] + row) * DIM + k0 + cb * 8;
            cp16(so, g);
        }
        cp_commit();
    };

    for (int s = 0; s < NSTAGE; ++s) load_stage(s, s * 32);

    float acc[2][8][4];
#pragma unroll
    for (int mi = 0; mi < 2; ++mi)
#pragma unroll
        for (int nj = 0; nj < 8; ++nj)
#pragma unroll
            for (int r = 0; r < 4; ++r) acc[mi][nj][r] = 0.f;

    const int rowA = wm * 32 + (lane & 15);
    const int acol = (lane >> 4) * 16;
    const int rowB = wn * 64 + (lane >> 4) * 8 + (lane & 7);
    const int bcol = ((lane >> 3) & 1) * 16;

    constexpr int NKC = DIM / 32;
    for (int i = 0; i < NKC; ++i) {
        const int slot = i % NSTAGE;
        const uint32_t sb = smem0 + slot * STAGE_B;
        cp_wait<NSTAGE - 1>();
        __syncthreads();

        const uint32_t aA = sb + rowA * GSTRIDE + acol;
        const uint32_t aB = sb + TILE_B + rowB * GSTRIDE + bcol;

#pragma unroll
        for (int k16 = 0; k16 < 2; ++k16) {
            const uint32_t ko = k16 * 32;
            uint32_t ah[2][4], bh[4][4];
#pragma unroll
            for (int mi = 0; mi < 2; ++mi)
                ldsm4(ah[mi], aA + mi * 16 * GSTRIDE + ko);
#pragma unroll
            for (int ni = 0; ni < 4; ++ni)
                ldsm4(bh[ni], aB + ni * 16 * GSTRIDE + ko);
#pragma unroll
            for (int mi = 0; mi < 2; ++mi)
#pragma unroll
                for (int nj = 0; nj < 8; ++nj)
                    mma16816(acc[mi][nj], ah[mi], &bh[nj >> 1][(nj & 1) * 2]);
        }
        __syncthreads();
        if (i + NSTAGE < NKC) load_stage(slot, (i + NSTAGE) * 32);
        else cp_commit();
    }

    const int crow0 = m0 + wm * 32 + (lane >> 2);
    const int ccol0 = n0 + wn * 64 + (lane & 3) * 2;
#pragma unroll
    for (int nj = 0; nj < 8; ++nj) {
        const int col = ccol0 + nj * 8;
        const float b0 = bias[col], b1 = bias[col + 1];
#pragma unroll
        for (int mi = 0; mi < 2; ++mi) {
            float* c0 = C + (size_t)(crow0 + mi * 16) * DIM + col;
            float* c1 = c0 + 8 * DIM;
            *(float2*)c0 = make_float2(acc[mi][nj][0] + b0, acc[mi][nj][1] + b1);
            *(float2*)c1 = make_float2(acc[mi][nj][2] + b0, acc[mi][nj][3] + b1);
        }
    }
}

// ---------------- flat fp32 -> fp16 convert ----------------
__global__ __launch_bounds__(256)
void tohalf_flat(const float* __restrict__ X, h16* __restrict__ H, long n4) {
    long i = ((long)blockIdx.x * 256 + threadIdx.x);
    if (i >= n4) return;
    float4 v = *((const float4*)X + i);
    __half2* Hp = (__half2*)H + i * 2;
    Hp[0] = __floats2half2_rn(v.x, v.y);
    Hp[1] = __floats2half2_rn(v.z, v.w);
}

// ---------------- transpose weights to single fp16 ----------------
__global__ __launch_bounds__(256)
void wT_kernel(const float* __restrict__ W, h16* __restrict__ Ht) {
    __shared__ float t[32][33];
    const int k0 = blockIdx.y * 32, n0 = blockIdx.x * 32;
    const int tx = threadIdx.x, ty = threadIdx.y;
#pragma unroll
    for (int j = 0; j < 4; ++j)
        t[ty + j * 8][tx] = W[(size_t)(k0 + ty + j * 8) * DIM + n0 + tx];
    __syncthreads();
#pragma unroll
    for (int j = 0; j < 4; ++j)
        Ht[(size_t)(n0 + ty + j * 8) * DIM + k0 + tx] = __float2half(t[tx][ty + j * 8]);
}

// ---------------- small fused SGEMM ----------------
struct SmallJobs {
    const float* A[4];
    const float* W[4];
    const float* b[4];
    float* C[4];
    int M[4];
};

__global__ __launch_bounds__(256)
void sgemm_small(SmallJobs jobs) {
    const int z = blockIdx.z;
    const float* A = jobs.A[z];
    const float* B = jobs.W[z];
    const float* bias = jobs.b[z];
    float* C = jobs.C[z];
    const int M = jobs.M[z];
    const int N = DIM, K = DIM;

    const int m0 = blockIdx.y * 128;
    if (m0 >= M) return;
    const int n0 = blockIdx.x * 64;

    __shared__ float As[16 * 132];
    __shared__ float Bs[16 * 64];
    const int tid = threadIdx.x;
    const int tx = tid & 15;
    const int ty = tid >> 4;
    const int arow = tid >> 1;
    const int ak = (tid & 1) * 8;
    const int brow = tid >> 4;
    const int bcol = (tid & 15) * 4;

    float acc[8][4];
#pragma unroll
    for (int i = 0; i < 8; ++i)
#pragma unroll
        for (int j = 0; j < 4; ++j) acc[i][j] = 0.f;

    const bool avalid = (m0 + arow) < M;
    const float* Aptr = A + (long)(m0 + arow) * K + ak;
    const float* Bptr = B + (long)brow * N + n0 + bcol;

    for (int k0 = 0; k0 < K; k0 += 16) {
        float4 a0 = make_float4(0.f, 0.f, 0.f, 0.f);
        float4 a1 = make_float4(0.f, 0.f, 0.f, 0.f);
        if (avalid) {
            a0 = *(const float4*)(Aptr + k0);
            a1 = *(const float4*)(Aptr + k0 + 4);
        }
        As[(ak + 0) * 132 + arow] = a0.x;
        As[(ak + 1) * 132 + arow] = a0.y;
        As[(ak + 2) * 132 + arow] = a0.z;
        As[(ak + 3) * 132 + arow] = a0.w;
        As[(ak + 4) * 132 + arow] = a1.x;
        As[(ak + 5) * 132 + arow] = a1.y;
        As[(ak + 6) * 132 + arow] = a1.z;
        As[(ak + 7) * 132 + arow] = a1.w;
        *(float4*)(Bs + brow * 64 + bcol) = *(const float4*)(Bptr + (long)k0 * N);
        __syncthreads();
#pragma unroll
        for (int kk = 0; kk < 16; ++kk) {
            float4 x0 = *(const float4*)(As + kk * 132 + ty * 8);
            float4 x1 = *(const float4*)(As + kk * 132 + ty * 8 + 4);
            float4 y = *(const float4*)(Bs + kk * 64 + tx * 4);
            float a[8] = {x0.x, x0.y, x0.z, x0.w, x1.x, x1.y, x1.z, x1.w};
            float b[4] = {y.x, y.y, y.z, y.w};
#pragma unroll
            for (int i = 0; i < 8; ++i)
#pragma unroll
                for (int j = 0; j < 4; ++j) acc[i][j] += a[i] * b[j];
        }
        __syncthreads();
    }

    float4 bv = *(const float4*)(bias + n0 + tx * 4);
    float bb[4] = {bv.x, bv.y, bv.z, bv.w};
#pragma unroll
    for (int i = 0; i < 8; ++i) {
        int m = m0 + ty * 8 + i;
        if (m < M) {
            float4 out;
            out.x = acc[i][0] + bb[0];
            out.y = acc[i][1] + bb[1];
            out.z = acc[i][2] + bb[2];
            out.w = acc[i][3] + bb[3];
            *(float4*)(C + (long)m * N + n0 + tx * 4) = out;
        }
    }
}

// ---------------- RMSNorm + fp16 hi/lo split (Q path) ----------------
__global__ __launch_bounds__(256)
void rmsnorm_split(const float* __restrict__ X, const float* __restrict__ g, float scale,
                   h16* __restrict__ H, h16* __restrict__ L, int nvalid) {
    const int r = blockIdx.x;
    const int tid = threadIdx.x;
    if (r >= nvalid) {
#pragma unroll
        for (int i = 0; i < 6; ++i) {
            H[(long)r * DIM + tid + i * 256] = __float2half(0.f);
            L[(long)r * DIM + tid + i * 256] = __float2half(0.f);
        }
        return;
    }
    const float* x = X + (long)r * DIM;
    float v[6];
    float ss = 0.f;
#pragma unroll
    for (int i = 0; i < 6; ++i) {
        v[i] = x[tid + i * 256];
        ss += v[i] * v[i];
    }
#pragma unroll
    for (int off = 16; off >= 1; off >>= 1)
        ss += __shfl_xor_sync(0xffffffffu, ss, off);
    __shared__ float red[8];
    if ((tid & 31) == 0) red[tid >> 5] = ss;
    __syncthreads();
    float tot = 0.f;
#pragma unroll
    for (int i = 0; i < 8; ++i) tot += red[i];
    const float rms = rsqrtf(tot * (1.f / (float)DIM) + 1e-6f);
#pragma unroll
    for (int i = 0; i < 6; ++i) {
        float val = v[i] * rms * g[tid + i * 256] * scale;
        h16 h = __float2half(val);
        h16 l = __float2half(val - __half2float(h));
        H[(long)r * DIM + tid + i * 256] = h;
        L[(long)r * DIM + tid + i * 256] = l;
    }
}

// ---------------- RMSNorm -> single fp16, zero-pad (K path) ----------------
__global__ __launch_bounds__(256)
void rmsnorm_single(const float* __restrict__ X, const float* __restrict__ g,
                    h16* __restrict__ H, int nvalid) {
    const int r = blockIdx.x;
    const int tid = threadIdx.x;
    if (r >= nvalid) {
#pragma unroll
        for (int i = 0; i < 6; ++i)
            H[(long)r * DIM + tid + i * 256] = __float2half(0.f);
        return;
    }
    const float* x = X + (long)r * DIM;
    float v[6];
    float ss = 0.f;
#pragma unroll
    for (int i = 0; i < 6; ++i) {
        v[i] = x[tid + i * 256];
        ss += v[i] * v[i];
    }
#pragma unroll
    for (int off = 16; off >= 1; off >>= 1)
        ss += __shfl_xor_sync(0xffffffffu, ss, off);
    __shared__ float red[8];
    if ((tid & 31) == 0) red[tid >> 5] = ss;
    __syncthreads();
    float tot = 0.f;
#pragma unroll
    for (int i = 0; i < 8; ++i) tot += red[i];
    const float rms = rsqrtf(tot * (1.f / (float)DIM) + 1e-6f);
#pragma unroll
    for (int i = 0; i < 6; ++i)
        H[(long)r * DIM + tid + i * 256] = __float2half(v[i] * rms * g[tid + i * 256]);
}

// ---------------- fp16 (single) row convert with zero-pad ----------------
__global__ __launch_bounds__(256)
void tohalf_pad(const float* __restrict__ X, h16* __restrict__ H, int nvalid) {
    const int r = blockIdx.x;
    const int tid = threadIdx.x;
#pragma unroll
    for (int i = 0; i < 6; ++i) {
        float val = (r < nvalid) ? X[(long)r * DIM + tid + i * 256] : 0.f;
        H[(long)r * DIM + tid + i * 256] = __float2half(val);
    }
}

// ---------------- HMMA flash attention ----------------
// QK fp16x2 ((Qh+Ql) x K single); PV single pass (P x V). KV double-buffered.
#define AST 272            // smem row stride bytes (128 fp16 + 16B pad)
#define KVROW (64 * AST)
#define KVST (2 * KVROW)   // Kh, Vh per stage

__global__ __launch_bounds__(256, 1)
void attn_mma(int qb0) {
    extern __shared__ char smem[];
    const uint32_t sQh = s2u(smem);
    const uint32_t sQl = sQh + 128 * AST;
    const uint32_t sKV = sQl + 128 * AST;   // 2 stages of KVST

    const int tid = threadIdx.x, lane = tid & 31, wid = tid >> 5;
    const int qb = blockIdx.x + qb0, h = blockIdx.y;
    const long qrow0 = (long)qb * 128;

    // Q load (its own commit group)
    {
        const h16* Qhg = g_Qh + qrow0 * DIM + h * HD;
        const h16* Qlg = g_Ql + qrow0 * DIM + h * HD;
#pragma unroll
        for (int t = 0; t < 8; ++t) {
            int c = tid + t * 256;
            int r = c >> 4, cb = c & 15;
            cp16(sQh + r * AST + cb * 16, Qhg + (long)r * DIM + cb * 8);
            cp16(sQl + r * AST + cb * 16, Qlg + (long)r * DIM + cb * 8);
        }
        cp_commit();
    }

    const uint32_t qoff = (uint32_t)((wid * 16 + (lane & 15)) * AST + (lane >> 4) * 16);
    const uint32_t koff = (uint32_t)((((lane >> 4) << 3) + (lane & 7)) * AST + ((lane >> 3) & 1) * 16);
    const uint32_t voff = (uint32_t)(((((lane >> 3) & 1) << 3) + (lane & 7)) * AST + (lane >> 4) * 16);

    const int r0 = lane >> 2;
    const int colb = (lane & 3) * 2;

#pragma unroll 1
    for (int seg = 0; seg < 2; ++seg) {
        const h16 *Khg, *Vhg;
        int len, ntiles;
        if (seg == 0) {
            Khg = g_Kh; Vhg = g_Vh;
            len = TXT; ntiles = TXT / 64;
        } else {
            Khg = g_Kih; Vhg = g_Vih;
            len = IMG; ntiles = IMGP / 64;
        }

        auto load_kv = [&](int stage, int t) {
            const uint32_t sb = sKV + stage * KVST;
            const long kvbase = (long)t * 64 * DIM + h * HD;
            const h16* arrs[2] = {Khg, Vhg};
#pragma unroll
            for (int tt = 0; tt < 8; ++tt) {
                int c = tid + tt * 256;       // 2048 chunks
                int arr = c >> 10;
                int idx = c & 1023;
                int r = idx >> 4, cb = idx & 15;
                cp16(sb + arr * KVROW + r * AST + cb * 16,
                     arrs[arr] + kvbase + (long)r * DIM + cb * 8);
            }
            cp_commit();
        };

        load_kv(0, 0);  // prologue

        float mrow0 = -1e30f, mrow1 = -1e30f, lsum0 = 0.f, lsum1 = 0.f;
        float O[16][4];
#pragma unroll
        for (int j = 0; j < 16; ++j)
#pragma unroll
            for (int e = 0; e < 4; ++e) O[j][e] = 0.f;

#pragma unroll 1
        for (int t = 0; t < ntiles; ++t) {
            __syncthreads();   // all warps finished reading buffer (t+1)&1 (from iter t-1)
            if (t + 1 < ntiles) {
                load_kv((t + 1) & 1, t + 1);
                cp_wait<1>();
            } else {
                cp_wait<0>();
            }
            __syncthreads();   // buffer t&1 visible to all

            const uint32_t sb = sKV + (t & 1) * KVST;
            const uint32_t sKh_ = sb, sVh_ = sb + KVROW;

            // ---- S = Q K^T (fp16x2: (Qh+Ql) x Kh) ----
            float S[8][4];
#pragma unroll
            for (int j = 0; j < 8; ++j)
#pragma unroll
                for (int e = 0; e < 4; ++e) S[j][e] = 0.f;
#pragma unroll
            for (int k16 = 0; k16 < 8; ++k16) {
                uint32_t ah[4], al[4];
                ldsm4(ah, sQh + qoff + k16 * 32);
                ldsm4(al, sQl + qoff + k16 * 32);
#pragma unroll
                for (int nt2 = 0; nt2 < 4; ++nt2) {
                    uint32_t bh[4];
                    ldsm4(bh, sKh_ + koff + nt2 * 16 * AST + k16 * 32);
                    mma16816(S[2 * nt2], ah, bh);
                    mma16816(S[2 * nt2], al, bh);
                    mma16816(S[2 * nt2 + 1], ah, bh + 2);
                    mma16816(S[2 * nt2 + 1], al, bh + 2);
                }
            }

            // ---- online softmax ----
            const int t0 = t * 64;
            if (t0 + 64 > len) {
#pragma unroll
                for (int j = 0; j < 8; ++j) {
#pragma unroll
                    for (int e = 0; e < 2; ++e) {
                        if (t0 + j * 8 + colb + e >= len) {
                            S[j][e] = -1e30f;
                            S[j][2 + e] = -1e30f;
                        }
                    }
                }
            }
            float mx0 = -1e30f, mx1 = -1e30f;
#pragma unroll
            for (int j = 0; j < 8; ++j) {
                mx0 = fmaxf(mx0, fmaxf(S[j][0], S[j][1]));
                mx1 = fmaxf(mx1, fmaxf(S[j][2], S[j][3]));
            }
            mx0 = fmaxf(mx0, __shfl_xor_sync(0xffffffffu, mx0, 1));
            mx0 = fmaxf(mx0, __shfl_xor_sync(0xffffffffu, mx0, 2));
            mx1 = fmaxf(mx1, __shfl_xor_sync(0xffffffffu, mx1, 1));
            mx1 = fmaxf(mx1, __shfl_xor_sync(0xffffffffu, mx1, 2));
            const float nm0 = fmaxf(mrow0, mx0);
            const float nm1 = fmaxf(mrow1, mx1);
            const float sc0 = __expf(mrow0 - nm0);
            const float sc1 = __expf(mrow1 - nm1);
            mrow0 = nm0; mrow1 = nm1;

            uint32_t Ph[8][2];
            float rs0 = 0.f, rs1 = 0.f;
#pragma unroll
            for (int j = 0; j < 8; ++j) {
                float p0 = __expf(S[j][0] - nm0);
                float p1 = __expf(S[j][1] - nm0);
                float p2 = __expf(S[j][2] - nm1);
                float p3 = __expf(S[j][3] - nm1);
                rs0 += p0 + p1;
                rs1 += p2 + p3;
                Ph[j][0] = packh(p0, p1);
                Ph[j][1] = packh(p2, p3);
            }
            rs0 += __shfl_xor_sync(0xffffffffu, rs0, 1);
            rs0 += __shfl_xor_sync(0xffffffffu, rs0, 2);
            rs1 += __shfl_xor_sync(0xffffffffu, rs1, 1);
            rs1 += __shfl_xor_sync(0xffffffffu, rs1, 2);
            lsum0 = lsum0 * sc0 + rs0;
            lsum1 = lsum1 * sc1 + rs1;
#pragma unroll
            for (int j = 0; j < 16; ++j) {
                O[j][0] *= sc0; O[j][1] *= sc0;
                O[j][2] *= sc1; O[j][3] *= sc1;
            }

            // ---- O += P V (single pass) ----
#pragma unroll
            for (int s = 0; s < 4; ++s) {
                uint32_t pah[4] = {Ph[2 * s][0], Ph[2 * s][1], Ph[2 * s + 1][0], Ph[2 * s + 1][1]};
#pragma unroll
                for (int d2 = 0; d2 < 8; ++d2) {
                    uint32_t vh[4];
                    ldsm4t(vh, sVh_ + voff + s * 16 * AST + d2 * 32);
                    mma16816(O[2 * d2], pah, vh);
                    mma16816(O[2 * d2 + 1], pah, vh + 2);
                }
            }
        }

        const float inv0 = 1.f / lsum0;
        const float inv1 = 1.f / lsum1;
        const long grow0 = qrow0 + wid * 16 + r0;
        const long grow1 = grow0 + 8;
        if (seg == 0) {
#pragma unroll
            for (int j = 0; j < 16; ++j) {
                const int d = h * HD + j * 8 + colb;
                *(float2*)(g_O + grow0 * DIM + d) = make_float2(O[j][0] * inv0, O[j][1] * inv0);
                *(float2*)(g_O + grow1 * DIM + d) = make_float2(O[j][2] * inv1, O[j][3] * inv1);
            }
        } else {
#pragma unroll
            for (int j = 0; j < 16; ++j) {
                const int d = h * HD + j * 8 + colb;
                float2 p0 = *(float2*)(g_O + grow0 * DIM + d);
                float2 p1 = *(float2*)(g_O + grow1 * DIM + d);
                *(__half2*)(g_Oh + grow0 * DIM + d) =
                    __floats2half2_rn(p0.x + O[j][0] * inv0, p0.y + O[j][1] * inv0);
                *(__half2*)(g_Oh + grow1 * DIM + d) =
                    __floats2half2_rn(p1.x + O[j][2] * inv1, p1.y + O[j][3] * inv1);
            }
        }
    }
}

// ---------------- launch ----------------
extern "C" void kernel_launch(void* const* d_in, const int* in_sizes, int n_in,
                              void* d_out, int out_size) {
    const float* x       = (const float*)d_in[0];
    const float* context = (const float*)d_in[1];
    const float* Wq  = (const float*)d_in[3];
    const float* bq  = (const float*)d_in[4];
    const float* Wk  = (const float*)d_in[5];
    const float* bk  = (const float*)d_in[6];
    const float* Wv  = (const float*)d_in[7];
    const float* bv  = (const float*)d_in[8];
    const float* Wak = (const float*)d_in[9];
    const float* bak = (const float*)d_in[10];
    const float* Wav = (const float*)d_in[11];
    const float* bav = (const float*)d_in[12];
    const float* Wo  = (const float*)d_in[13];
    const float* bo  = (const float*)d_in[14];
    const float* gq  = (const float*)d_in[15];
    const float* gk  = (const float*)d_in[16];
    const float* gak = (const float*)d_in[17];
    float* out = (float*)d_out;

    float *Qp, *Kp, *Vp, *Kip, *Vip;
    h16 *xh, *Oh, *WqT, *WoT;
    h16 *Qh, *Ql, *Kh, *Vh, *Kih, *Vih;
    cudaGetSymbolAddress((void**)&Qp, g_Q);
    cudaGetSymbolAddress((void**)&Kp, g_K);
    cudaGetSymbolAddress((void**)&Vp, g_V);
    cudaGetSymbolAddress((void**)&Kip, g_Ki);
    cudaGetSymbolAddress((void**)&Vip, g_Vi);
    cudaGetSymbolAddress((void**)&xh, g_xh);
    cudaGetSymbolAddress((void**)&Oh, g_Oh);
    cudaGetSymbolAddress((void**)&WqT, g_WqT);
    cudaGetSymbolAddress((void**)&WoT, g_WoT);
    cudaGetSymbolAddress((void**)&Qh, g_Qh);
    cudaGetSymbolAddress((void**)&Ql, g_Ql);
    cudaGetSymbolAddress((void**)&Kh, g_Kh);
    cudaGetSymbolAddress((void**)&Vh, g_Vh);
    cudaGetSymbolAddress((void**)&Kih, g_Kih);
    cudaGetSymbolAddress((void**)&Vih, g_Vih);

    const float* ctx_img = context;
    const float* ctx_txt = context + (long)IMG * DIM;

    static cudaStream_t s1 = nullptr, s2 = nullptr;
    static cudaEvent_t evFork = nullptr, evKV = nullptr, evA = nullptr, evS1 = nullptr;
    if (s1 == nullptr) {
        cudaStreamCreateWithFlags(&s1, cudaStreamNonBlocking);
        cudaStreamCreateWithFlags(&s2, cudaStreamNonBlocking);
        cudaEventCreateWithFlags(&evFork, cudaEventDisableTiming);
        cudaEventCreateWithFlags(&evKV, cudaEventDisableTiming);
        cudaEventCreateWithFlags(&evA, cudaEventDisableTiming);
        cudaEventCreateWithFlags(&evS1, cudaEventDisableTiming);
    }

    const float scale = 0.08838834764831843f;
    const int gemm_smem = NSTAGE * STAGE_B;
    cudaFuncSetAttribute(gemm_mma_f16, cudaFuncAttributeMaxDynamicSharedMemorySize, gemm_smem);
    const int attn_smem = 2 * 128 * AST + 2 * KVST;
    cudaFuncSetAttribute(attn_mma, cudaFuncAttributeMaxDynamicSharedMemorySize, attn_smem);

    // ---- fork ----
    cudaEventRecord(evFork, 0);
    cudaStreamWaitEvent(s1, evFork, 0);
    cudaStreamWaitEvent(s2, evFork, 0);

    // s2: KV chain + Wo prep
    SmallJobs jobs;
    jobs.A[0] = ctx_txt; jobs.W[0] = Wk;  jobs.b[0] = bk;  jobs.C[0] = Kp;  jobs.M[0] = TXT;
    jobs.A[1] = ctx_txt; jobs.W[1] = Wv;  jobs.b[1] = bv;  jobs.C[1] = Vp;  jobs.M[1] = TXT;
    jobs.A[2] = ctx_img; jobs.W[2] = Wak; jobs.b[2] = bak; jobs.C[2] = Kip; jobs.M[2] = IMG;
    jobs.A[3] = ctx_img; jobs.W[3] = Wav; jobs.b[3] = bav; jobs.C[3] = Vip; jobs.M[3] = IMG;
    sgemm_small<<<dim3(DIM / 64, 4, 4), 256, 0, s2>>>(jobs);
    rmsnorm_single<<<TXT, 256, 0, s2>>>(Kp, gk, Kh, TXT);
    rmsnorm_single<<<IMGP, 256, 0, s2>>>(Kip, gak, Kih, IMG);
    tohalf_pad<<<TXT, 256, 0, s2>>>(Vp, Vh, TXT);
    tohalf_pad<<<IMGP, 256, 0, s2>>>(Vip, Vih, IMG);
    wT_kernel<<<dim3(DIM / 32, DIM / 32), dim3(32, 8), 0, s2>>>(Wo, WoT);
    cudaEventRecord(evKV, s2);

    // main: input conversions + Q projection half 0
    long n4 = (long)NQ * DIM / 4;
    tohalf_flat<<<(unsigned)((n4 + 255) / 256), 256>>>(x, xh, n4);
    wT_kernel<<<dim3(DIM / 32, DIM / 32), dim3(32, 8)>>>(Wq, WqT);
    gemm_mma_f16<<<dim3(DIM / 128, HALF / 128), 256, gemm_smem>>>(xh, WqT, bq, Qp);
    cudaEventRecord(evA, 0);

    // s1: half-0 tail — rmsnorm(h0) -> attn(h0) -> outproj(h0)
    cudaStreamWaitEvent(s1, evA, 0);
    rmsnorm_split<<<HALF, 256, 0, s1>>>(Qp, gq, scale, Qh, Ql, HALF);
    cudaStreamWaitEvent(s1, evKV, 0);
    attn_mma<<<dim3(HALF / 128, HEADS), 256, attn_smem, s1>>>(0);
    gemm_mma_f16<<<dim3(DIM / 128, HALF / 128), 256, gemm_smem, s1>>>(Oh, WoT, bo, out);
    cudaEventRecord(evS1, s1);

    // main: half-1 chain
    gemm_mma_f16<<<dim3(DIM / 128, HALF / 128), 256, gemm_smem>>>(
        xh + (long)HALF * DIM, WqT, bq, Qp + (long)HALF * DIM);
    rmsnorm_split<<<HALF, 256>>>(Qp + (long)HALF * DIM, gq, scale,
                                 Qh + (long)HALF * DIM, Ql + (long)HALF * DIM, HALF);
    cudaStreamWaitEvent(0, evKV, 0);
    attn_mma<<<dim3(HALF / 128, HEADS), 256, attn_smem>>>(HALF / 128);
    gemm_mma_f16<<<dim3(DIM / 128, HALF / 128), 256, gemm_smem>>>(
        Oh + (long)HALF * DIM, WoT, bo, out + (long)HALF * DIM);

    // join
    cudaStreamWaitEvent(0, evS1, 0);
}

// round 12
// speedup vs baseline: 6.8801x; 1.0976x over previous
#include <cuda_runtime.h>
#include <cuda_fp16.h>
#include <cstdint>

#define DIM 1536
#define HEADS 12
#define HD 128
#define NQ 16384
#define HALF (NQ / 2)
#define IMG 257
#define TXT 512
#define IMGP 320   // img rows padded to multiple of 64

typedef __half h16;

// ---------------- scratch (no allocations allowed) ----------------
__device__ float g_Q[(long)NQ * DIM];
__device__ float g_O[(long)NQ * DIM];          // attention partial (txt segment)
__device__ float g_K[(long)TXT * DIM];
__device__ float g_V[(long)TXT * DIM];
__device__ float g_Ki[(long)IMG * DIM];
__device__ float g_Vi[(long)IMG * DIM];
__device__ h16 g_xh[(long)NQ * DIM];
__device__ h16 g_Qh[(long)NQ * DIM];
__device__ h16 g_Oh[(long)NQ * DIM];
__device__ h16 g_Kh[(long)TXT * DIM];
__device__ h16 g_Vh[(long)TXT * DIM];
__device__ h16 g_Kih[(long)IMGP * DIM];
__device__ h16 g_Vih[(long)IMGP * DIM];
__device__ h16 g_WqT[(long)DIM * DIM];
__device__ h16 g_WoT[(long)DIM * DIM];

// ---------------- PTX helpers ----------------
__device__ __forceinline__ uint32_t s2u(const void* p) {
    return (uint32_t)__cvta_generic_to_shared(p);
}
__device__ __forceinline__ void cp16(uint32_t s, const void* g) {
    asm volatile("cp.async.cg.shared.global [%0], [%1], 16;\n" :: "r"(s), "l"(g) : "memory");
}
__device__ __forceinline__ void cp_commit() {
    asm volatile("cp.async.commit_group;\n" ::: "memory");
}
template <int N>
__device__ __forceinline__ void cp_wait() {
    asm volatile("cp.async.wait_group %0;\n" :: "n"(N) : "memory");
}
__device__ __forceinline__ void ldsm4(uint32_t* r, uint32_t a) {
    asm volatile("ldmatrix.sync.aligned.m8n8.x4.shared.b16 {%0,%1,%2,%3}, [%4];"
                 : "=r"(r[0]), "=r"(r[1]), "=r"(r[2]), "=r"(r[3]) : "r"(a));
}
__device__ __forceinline__ void ldsm4t(uint32_t* r, uint32_t a) {
    asm volatile("ldmatrix.sync.aligned.m8n8.x4.trans.shared.b16 {%0,%1,%2,%3}, [%4];"
                 : "=r"(r[0]), "=r"(r[1]), "=r"(r[2]), "=r"(r[3]) : "r"(a));
}
__device__ __forceinline__ void mma16816(float* c, const uint32_t* a, const uint32_t* b) {
    asm volatile(
        "mma.sync.aligned.m16n8k16.row.col.f32.f16.f16.f32 "
        "{%0,%1,%2,%3}, {%4,%5,%6,%7}, {%8,%9}, {%0,%1,%2,%3};"
        : "+f"(c[0]), "+f"(c[1]), "+f"(c[2]), "+f"(c[3])
        : "r"(a[0]), "r"(a[1]), "r"(a[2]), "r"(a[3]), "r"(b[0]), "r"(b[1]));
}
__device__ __forceinline__ uint32_t packh(float a, float b) {
    __half2 t = __floats2half2_rn(a, b);
    return *(uint32_t*)&t;
}

// ---------------- single-pass fp16 HMMA GEMM: C = A @ BT^T + bias ----------------
#define GSTRIDE 80
#define TILE_B (128 * GSTRIDE)
#define STAGE_B (2 * TILE_B)   // A, B
#define NSTAGE 4

__global__ __launch_bounds__(256, 2)
void gemm_mma_f16(const h16* __restrict__ A, const h16* __restrict__ BT,
                  const float* __restrict__ bias, float* __restrict__ C) {
    extern __shared__ char dynsm[];
    const uint32_t smem0 = s2u(dynsm);
    const int tid = threadIdx.x;
    const int lane = tid & 31;
    const int wid = tid >> 5;
    const int wm = wid & 3;
    const int wn = wid >> 2;
    const int m0 = blockIdx.y * 128;
    const int n0 = blockIdx.x * 128;

    const h16* srcs[2] = {A, BT};
    const int bases[2] = {m0, n0};

    auto load_stage = [&](int slot, int k0) {
        const uint32_t sb = smem0 + slot * STAGE_B;
#pragma unroll
        for (int t = 0; t < 4; ++t) {
            const int ch = tid + t * 256;      // 1024 chunks
            const int tile = ch >> 9;
            const int idx = ch & 511;
            const int row = idx >> 2;
            const int cb = idx & 3;
            const uint32_t so = sb + tile * TILE_B + row * GSTRIDE + cb * 16;
            const h16* g = srcs[tile] + (size_t)(bases[tile] + row) * DIM + k0 + cb * 8;
            cp16(so, g);
        }
        cp_commit();
    };

    for (int s = 0; s < NSTAGE; ++s) load_stage(s, s * 32);

    float acc[2][8][4];
#pragma unroll
    for (int mi = 0; mi < 2; ++mi)
#pragma unroll
        for (int nj = 0; nj < 8; ++nj)
#pragma unroll
            for (int r = 0; r < 4; ++r) acc[mi][nj][r] = 0.f;

    const int rowA = wm * 32 + (lane & 15);
    const int acol = (lane >> 4) * 16;
    const int rowB = wn * 64 + (lane >> 4) * 8 + (lane & 7);
    const int bcol = ((lane >> 3) & 1) * 16;

    constexpr int NKC = DIM / 32;
    for (int i = 0; i < NKC; ++i) {
        const int slot = i % NSTAGE;
        const uint32_t sb = smem0 + slot * STAGE_B;
        cp_wait<NSTAGE - 1>();
        __syncthreads();

        const uint32_t aA = sb + rowA * GSTRIDE + acol;
        const uint32_t aB = sb + TILE_B + rowB * GSTRIDE + bcol;

#pragma unroll
        for (int k16 = 0; k16 < 2; ++k16) {
            const uint32_t ko = k16 * 32;
            uint32_t ah[2][4], bh[4][4];
#pragma unroll
            for (int mi = 0; mi < 2; ++mi)
                ldsm4(ah[mi], aA + mi * 16 * GSTRIDE + ko);
#pragma unroll
            for (int ni = 0; ni < 4; ++ni)
                ldsm4(bh[ni], aB + ni * 16 * GSTRIDE + ko);
#pragma unroll
            for (int mi = 0; mi < 2; ++mi)
#pragma unroll
                for (int nj = 0; nj < 8; ++nj)
                    mma16816(acc[mi][nj], ah[mi], &bh[nj >> 1][(nj & 1) * 2]);
        }
        __syncthreads();
        if (i + NSTAGE < NKC) load_stage(slot, (i + NSTAGE) * 32);
        else cp_commit();
    }

    const int crow0 = m0 + wm * 32 + (lane >> 2);
    const int ccol0 = n0 + wn * 64 + (lane & 3) * 2;
#pragma unroll
    for (int nj = 0; nj < 8; ++nj) {
        const int col = ccol0 + nj * 8;
        const float b0 = bias[col], b1 = bias[col + 1];
#pragma unroll
        for (int mi = 0; mi < 2; ++mi) {
            float* c0 = C + (size_t)(crow0 + mi * 16) * DIM + col;
            float* c1 = c0 + 8 * DIM;
            *(float2*)c0 = make_float2(acc[mi][nj][0] + b0, acc[mi][nj][1] + b1);
            *(float2*)c1 = make_float2(acc[mi][nj][2] + b0, acc[mi][nj][3] + b1);
        }
    }
}

// ---------------- flat fp32 -> fp16 convert ----------------
__global__ __launch_bounds__(256)
void tohalf_flat(const float* __restrict__ X, h16* __restrict__ H, long n4) {
    long i = ((long)blockIdx.x * 256 + threadIdx.x);
    if (i >= n4) return;
    float4 v = *((const float4*)X + i);
    __half2* Hp = (__half2*)H + i * 2;
    Hp[0] = __floats2half2_rn(v.x, v.y);
    Hp[1] = __floats2half2_rn(v.z, v.w);
}

// ---------------- transpose weights to single fp16 ----------------
__global__ __launch_bounds__(256)
void wT_kernel(const float* __restrict__ W, h16* __restrict__ Ht) {
    __shared__ float t[32][33];
    const int k0 = blockIdx.y * 32, n0 = blockIdx.x * 32;
    const int tx = threadIdx.x, ty = threadIdx.y;
#pragma unroll
    for (int j = 0; j < 4; ++j)
        t[ty + j * 8][tx] = W[(size_t)(k0 + ty + j * 8) * DIM + n0 + tx];
    __syncthreads();
#pragma unroll
    for (int j = 0; j < 4; ++j)
        Ht[(size_t)(n0 + ty + j * 8) * DIM + k0 + tx] = __float2half(t[tx][ty + j * 8]);
}

// ---------------- small fused SGEMM ----------------
struct SmallJobs {
    const float* A[4];
    const float* W[4];
    const float* b[4];
    float* C[4];
    int M[4];
};

__global__ __launch_bounds__(256)
void sgemm_small(SmallJobs jobs) {
    const int z = blockIdx.z;
    const float* A = jobs.A[z];
    const float* B = jobs.W[z];
    const float* bias = jobs.b[z];
    float* C = jobs.C[z];
    const int M = jobs.M[z];
    const int N = DIM, K = DIM;

    const int m0 = blockIdx.y * 128;
    if (m0 >= M) return;
    const int n0 = blockIdx.x * 64;

    __shared__ float As[16 * 132];
    __shared__ float Bs[16 * 64];
    const int tid = threadIdx.x;
    const int tx = tid & 15;
    const int ty = tid >> 4;
    const int arow = tid >> 1;
    const int ak = (tid & 1) * 8;
    const int brow = tid >> 4;
    const int bcol = (tid & 15) * 4;

    float acc[8][4];
#pragma unroll
    for (int i = 0; i < 8; ++i)
#pragma unroll
        for (int j = 0; j < 4; ++j) acc[i][j] = 0.f;

    const bool avalid = (m0 + arow) < M;
    const float* Aptr = A + (long)(m0 + arow) * K + ak;
    const float* Bptr = B + (long)brow * N + n0 + bcol;

    for (int k0 = 0; k0 < K; k0 += 16) {
        float4 a0 = make_float4(0.f, 0.f, 0.f, 0.f);
        float4 a1 = make_float4(0.f, 0.f, 0.f, 0.f);
        if (avalid) {
            a0 = *(const float4*)(Aptr + k0);
            a1 = *(const float4*)(Aptr + k0 + 4);
        }
        As[(ak + 0) * 132 + arow] = a0.x;
        As[(ak + 1) * 132 + arow] = a0.y;
        As[(ak + 2) * 132 + arow] = a0.z;
        As[(ak + 3) * 132 + arow] = a0.w;
        As[(ak + 4) * 132 + arow] = a1.x;
        As[(ak + 5) * 132 + arow] = a1.y;
        As[(ak + 6) * 132 + arow] = a1.z;
        As[(ak + 7) * 132 + arow] = a1.w;
        *(float4*)(Bs + brow * 64 + bcol) = *(const float4*)(Bptr + (long)k0 * N);
        __syncthreads();
#pragma unroll
        for (int kk = 0; kk < 16; ++kk) {
            float4 x0 = *(const float4*)(As + kk * 132 + ty * 8);
            float4 x1 = *(const float4*)(As + kk * 132 + ty * 8 + 4);
            float4 y = *(const float4*)(Bs + kk * 64 + tx * 4);
            float a[8] = {x0.x, x0.y, x0.z, x0.w, x1.x, x1.y, x1.z, x1.w};
            float b[4] = {y.x, y.y, y.z, y.w};
#pragma unroll
            for (int i = 0; i < 8; ++i)
#pragma unroll
                for (int j = 0; j < 4; ++j) acc[i][j] += a[i] * b[j];
        }
        __syncthreads();
    }

    float4 bv = *(const float4*)(bias + n0 + tx * 4);
    float bb[4] = {bv.x, bv.y, bv.z, bv.w};
#pragma unroll
    for (int i = 0; i < 8; ++i) {
        int m = m0 + ty * 8 + i;
        if (m < M) {
            float4 out;
            out.x = acc[i][0] + bb[0];
            out.y = acc[i][1] + bb[1];
            out.z = acc[i][2] + bb[2];
            out.w = acc[i][3] + bb[3];
            *(float4*)(C + (long)m * N + n0 + tx * 4) = out;
        }
    }
}

// ---------------- RMSNorm -> single fp16 (optional scale), zero-pad ----------------
__global__ __launch_bounds__(256)
void rmsnorm_single(const float* __restrict__ X, const float* __restrict__ g, float scale,
                    h16* __restrict__ H, int nvalid) {
    const int r = blockIdx.x;
    const int tid = threadIdx.x;
    if (r >= nvalid) {
#pragma unroll
        for (int i = 0; i < 6; ++i)
            H[(long)r * DIM + tid + i * 256] = __float2half(0.f);
        return;
    }
    const float* x = X + (long)r * DIM;
    float v[6];
    float ss = 0.f;
#pragma unroll
    for (int i = 0; i < 6; ++i) {
        v[i] = x[tid + i * 256];
        ss += v[i] * v[i];
    }
#pragma unroll
    for (int off = 16; off >= 1; off >>= 1)
        ss += __shfl_xor_sync(0xffffffffu, ss, off);
    __shared__ float red[8];
    if ((tid & 31) == 0) red[tid >> 5] = ss;
    __syncthreads();
    float tot = 0.f;
#pragma unroll
    for (int i = 0; i < 8; ++i) tot += red[i];
    const float rms = rsqrtf(tot * (1.f / (float)DIM) + 1e-6f);
#pragma unroll
    for (int i = 0; i < 6; ++i)
        H[(long)r * DIM + tid + i * 256] = __float2half(v[i] * rms * g[tid + i * 256] * scale);
}

// ---------------- fp16 (single) row convert with zero-pad ----------------
__global__ __launch_bounds__(256)
void tohalf_pad(const float* __restrict__ X, h16* __restrict__ H, int nvalid) {
    const int r = blockIdx.x;
    const int tid = threadIdx.x;
#pragma unroll
    for (int i = 0; i < 6; ++i) {
        float val = (r < nvalid) ? X[(long)r * DIM + tid + i * 256] : 0.f;
        H[(long)r * DIM + tid + i * 256] = __float2half(val);
    }
}

// ---------------- HMMA flash attention ----------------
// Single-pass fp16 QK and PV; KV double-buffered; 2 CTAs/SM.
#define AST 272            // smem row stride bytes (128 fp16 + 16B pad)
#define KVROW (64 * AST)
#define KVST (2 * KVROW)   // Kh, Vh per stage

__global__ __launch_bounds__(256, 2)
void attn_mma(int qb0) {
    extern __shared__ char smem[];
    const uint32_t sQh = s2u(smem);
    const uint32_t sKV = sQh + 128 * AST;   // 2 stages of KVST

    const int tid = threadIdx.x, lane = tid & 31, wid = tid >> 5;
    const int qb = blockIdx.x + qb0, h = blockIdx.y;
    const long qrow0 = (long)qb * 128;

    // Q load (its own commit group)
    {
        const h16* Qhg = g_Qh + qrow0 * DIM + h * HD;
#pragma unroll
        for (int t = 0; t < 8; ++t) {
            int c = tid + t * 256;
            int r = c >> 4, cb = c & 15;
            cp16(sQh + r * AST + cb * 16, Qhg + (long)r * DIM + cb * 8);
        }
        cp_commit();
    }

    const uint32_t qoff = (uint32_t)((wid * 16 + (lane & 15)) * AST + (lane >> 4) * 16);
    const uint32_t koff = (uint32_t)((((lane >> 4) << 3) + (lane & 7)) * AST + ((lane >> 3) & 1) * 16);
    const uint32_t voff = (uint32_t)(((((lane >> 3) & 1) << 3) + (lane & 7)) * AST + (lane >> 4) * 16);

    const int r0 = lane >> 2;
    const int colb = (lane & 3) * 2;

#pragma unroll 1
    for (int seg = 0; seg < 2; ++seg) {
        const h16 *Khg, *Vhg;
        int len, ntiles;
        if (seg == 0) {
            Khg = g_Kh; Vhg = g_Vh;
            len = TXT; ntiles = TXT / 64;
        } else {
            Khg = g_Kih; Vhg = g_Vih;
            len = IMG; ntiles = IMGP / 64;
        }

        auto load_kv = [&](int stage, int t) {
            const uint32_t sb = sKV + stage * KVST;
            const long kvbase = (long)t * 64 * DIM + h * HD;
            const h16* arrs[2] = {Khg, Vhg};
#pragma unroll
            for (int tt = 0; tt < 8; ++tt) {
                int c = tid + tt * 256;       // 2048 chunks
                int arr = c >> 10;
                int idx = c & 1023;
                int r = idx >> 4, cb = idx & 15;
                cp16(sb + arr * KVROW + r * AST + cb * 16,
                     arrs[arr] + kvbase + (long)r * DIM + cb * 8);
            }
            cp_commit();
        };

        load_kv(0, 0);  // prologue

        float mrow0 = -1e30f, mrow1 = -1e30f, lsum0 = 0.f, lsum1 = 0.f;
        float O[16][4];
#pragma unroll
        for (int j = 0; j < 16; ++j)
#pragma unroll
            for (int e = 0; e < 4; ++e) O[j][e] = 0.f;

#pragma unroll 1
        for (int t = 0; t < ntiles; ++t) {
            __syncthreads();   // all warps finished reading buffer (t+1)&1 (from iter t-1)
            if (t + 1 < ntiles) {
                load_kv((t + 1) & 1, t + 1);
                cp_wait<1>();
            } else {
                cp_wait<0>();
            }
            __syncthreads();   // buffer t&1 visible to all

            const uint32_t sb = sKV + (t & 1) * KVST;
            const uint32_t sKh_ = sb, sVh_ = sb + KVROW;

            // ---- S = Q K^T (single fp16 pass) ----
            float S[8][4];
#pragma unroll
            for (int j = 0; j < 8; ++j)
#pragma unroll
                for (int e = 0; e < 4; ++e) S[j][e] = 0.f;
#pragma unroll
            for (int k16 = 0; k16 < 8; ++k16) {
                uint32_t ah[4];
                ldsm4(ah, sQh + qoff + k16 * 32);
#pragma unroll
                for (int nt2 = 0; nt2 < 4; ++nt2) {
                    uint32_t bh[4];
                    ldsm4(bh, sKh_ + koff + nt2 * 16 * AST + k16 * 32);
                    mma16816(S[2 * nt2], ah, bh);
                    mma16816(S[2 * nt2 + 1], ah, bh + 2);
                }
            }

            // ---- online softmax ----
            const int t0 = t * 64;
            if (t0 + 64 > len) {
#pragma unroll
                for (int j = 0; j < 8; ++j) {
#pragma unroll
                    for (int e = 0; e < 2; ++e) {
                        if (t0 + j * 8 + colb + e >= len) {
                            S[j][e] = -1e30f;
                            S[j][2 + e] = -1e30f;
                        }
                    }
                }
            }
            float mx0 = -1e30f, mx1 = -1e30f;
#pragma unroll
            for (int j = 0; j < 8; ++j) {
                mx0 = fmaxf(mx0, fmaxf(S[j][0], S[j][1]));
                mx1 = fmaxf(mx1, fmaxf(S[j][2], S[j][3]));
            }
            mx0 = fmaxf(mx0, __shfl_xor_sync(0xffffffffu, mx0, 1));
            mx0 = fmaxf(mx0, __shfl_xor_sync(0xffffffffu, mx0, 2));
            mx1 = fmaxf(mx1, __shfl_xor_sync(0xffffffffu, mx1, 1));
            mx1 = fmaxf(mx1, __shfl_xor_sync(0xffffffffu, mx1, 2));
            const float nm0 = fmaxf(mrow0, mx0);
            const float nm1 = fmaxf(mrow1, mx1);
            const float sc0 = __expf(mrow0 - nm0);
            const float sc1 = __expf(mrow1 - nm1);
            mrow0 = nm0; mrow1 = nm1;

            uint32_t Ph[8][2];
            float rs0 = 0.f, rs1 = 0.f;
#pragma unroll
            for (int j = 0; j < 8; ++j) {
                float p0 = __expf(S[j][0] - nm0);
                float p1 = __expf(S[j][1] - nm0);
                float p2 = __expf(S[j][2] - nm1);
                float p3 = __expf(S[j][3] - nm1);
                rs0 += p0 + p1;
                rs1 += p2 + p3;
                Ph[j][0] = packh(p0, p1);
                Ph[j][1] = packh(p2, p3);
            }
            rs0 += __shfl_xor_sync(0xffffffffu, rs0, 1);
            rs0 += __shfl_xor_sync(0xffffffffu, rs0, 2);
            rs1 += __shfl_xor_sync(0xffffffffu, rs1, 1);
            rs1 += __shfl_xor_sync(0xffffffffu, rs1, 2);
            lsum0 = lsum0 * sc0 + rs0;
            lsum1 = lsum1 * sc1 + rs1;
#pragma unroll
            for (int j = 0; j < 16; ++j) {
                O[j][0] *= sc0; O[j][1] *= sc0;
                O[j][2] *= sc1; O[j][3] *= sc1;
            }

            // ---- O += P V (single pass) ----
#pragma unroll
            for (int s = 0; s < 4; ++s) {
                uint32_t pah[4] = {Ph[2 * s][0], Ph[2 * s][1], Ph[2 * s + 1][0], Ph[2 * s + 1][1]};
#pragma unroll
                for (int d2 = 0; d2 < 8; ++d2) {
                    uint32_t vh[4];
                    ldsm4t(vh, sVh_ + voff + s * 16 * AST + d2 * 32);
                    mma16816(O[2 * d2], pah, vh);
                    mma16816(O[2 * d2 + 1], pah, vh + 2);
                }
            }
        }

        const float inv0 = 1.f / lsum0;
        const float inv1 = 1.f / lsum1;
        const long grow0 = qrow0 + wid * 16 + r0;
        const long grow1 = grow0 + 8;
        if (seg == 0) {
#pragma unroll
            for (int j = 0; j < 16; ++j) {
                const int d = h * HD + j * 8 + colb;
                *(float2*)(g_O + grow0 * DIM + d) = make_float2(O[j][0] * inv0, O[j][1] * inv0);
                *(float2*)(g_O + grow1 * DIM + d) = make_float2(O[j][2] * inv1, O[j][3] * inv1);
            }
        } else {
#pragma unroll
            for (int j = 0; j < 16; ++j) {
                const int d = h * HD + j * 8 + colb;
                float2 p0 = *(float2*)(g_O + grow0 * DIM + d);
                float2 p1 = *(float2*)(g_O + grow1 * DIM + d);
                *(__half2*)(g_Oh + grow0 * DIM + d) =
                    __floats2half2_rn(p0.x + O[j][0] * inv0, p0.y + O[j][1] * inv0);
                *(__half2*)(g_Oh + grow1 * DIM + d) =
                    __floats2half2_rn(p1.x + O[j][2] * inv1, p1.y + O[j][3] * inv1);
            }
        }
    }
}

// ---------------- launch ----------------
extern "C" void kernel_launch(void* const* d_in, const int* in_sizes, int n_in,
                              void* d_out, int out_size) {
    const float* x       = (const float*)d_in[0];
    const float* context = (const float*)d_in[1];
    const float* Wq  = (const float*)d_in[3];
    const float* bq  = (const float*)d_in[4];
    const float* Wk  = (const float*)d_in[5];
    const float* bk  = (const float*)d_in[6];
    const float* Wv  = (const float*)d_in[7];
    const float* bv  = (const float*)d_in[8];
    const float* Wak = (const float*)d_in[9];
    const float* bak = (const float*)d_in[10];
    const float* Wav = (const float*)d_in[11];
    const float* bav = (const float*)d_in[12];
    const float* Wo  = (const float*)d_in[13];
    const float* bo  = (const float*)d_in[14];
    const float* gq  = (const float*)d_in[15];
    const float* gk  = (const float*)d_in[16];
    const float* gak = (const float*)d_in[17];
    float* out = (float*)d_out;

    float *Qp, *Kp, *Vp, *Kip, *Vip;
    h16 *xh, *Oh, *WqT, *WoT;
    h16 *Qh, *Kh, *Vh, *Kih, *Vih;
    cudaGetSymbolAddress((void**)&Qp, g_Q);
    cudaGetSymbolAddress((void**)&Kp, g_K);
    cudaGetSymbolAddress((void**)&Vp, g_V);
    cudaGetSymbolAddress((void**)&Kip, g_Ki);
    cudaGetSymbolAddress((void**)&Vip, g_Vi);
    cudaGetSymbolAddress((void**)&xh, g_xh);
    cudaGetSymbolAddress((void**)&Oh, g_Oh);
    cudaGetSymbolAddress((void**)&WqT, g_WqT);
    cudaGetSymbolAddress((void**)&WoT, g_WoT);
    cudaGetSymbolAddress((void**)&Qh, g_Qh);
    cudaGetSymbolAddress((void**)&Kh, g_Kh);
    cudaGetSymbolAddress((void**)&Vh, g_Vh);
    cudaGetSymbolAddress((void**)&Kih, g_Kih);
    cudaGetSymbolAddress((void**)&Vih, g_Vih);

    const float* ctx_img = context;
    const float* ctx_txt = context + (long)IMG * DIM;

    static cudaStream_t s1 = nullptr, s2 = nullptr;
    static cudaEvent_t evFork = nullptr, evKV = nullptr, evA = nullptr, evS1 = nullptr;
    if (s1 == nullptr) {
        cudaStreamCreateWithFlags(&s1, cudaStreamNonBlocking);
        cudaStreamCreateWithFlags(&s2, cudaStreamNonBlocking);
        cudaEventCreateWithFlags(&evFork, cudaEventDisableTiming);
        cudaEventCreateWithFlags(&evKV, cudaEventDisableTiming);
        cudaEventCreateWithFlags(&evA, cudaEventDisableTiming);
        cudaEventCreateWithFlags(&evS1, cudaEventDisableTiming);
    }

    const float scale = 0.08838834764831843f;
    const int gemm_smem = NSTAGE * STAGE_B;
    cudaFuncSetAttribute(gemm_mma_f16, cudaFuncAttributeMaxDynamicSharedMemorySize, gemm_smem);
    const int attn_smem = 128 * AST + 2 * KVST;
    cudaFuncSetAttribute(attn_mma, cudaFuncAttributeMaxDynamicSharedMemorySize, attn_smem);

    // ---- fork ----
    cudaEventRecord(evFork, 0);
    cudaStreamWaitEvent(s1, evFork, 0);
    cudaStreamWaitEvent(s2, evFork, 0);

    // s2: KV chain + Wo prep
    SmallJobs jobs;
    jobs.A[0] = ctx_txt; jobs.W[0] = Wk;  jobs.b[0] = bk;  jobs.C[0] = Kp;  jobs.M[0] = TXT;
    jobs.A[1] = ctx_txt; jobs.W[1] = Wv;  jobs.b[1] = bv;  jobs.C[1] = Vp;  jobs.M[1] = TXT;
    jobs.A[2] = ctx_img; jobs.W[2] = Wak; jobs.b[2] = bak; jobs.C[2] = Kip; jobs.M[2] = IMG;
    jobs.A[3] = ctx_img; jobs.W[3] = Wav; jobs.b[3] = bav; jobs.C[3] = Vip; jobs.M[3] = IMG;
    sgemm_small<<<dim3(DIM / 64, 4, 4), 256, 0, s2>>>(jobs);
    rmsnorm_single<<<TXT, 256, 0, s2>>>(Kp, gk, 1.f, Kh, TXT);
    rmsnorm_single<<<IMGP, 256, 0, s2>>>(Kip, gak, 1.f, Kih, IMG);
    tohalf_pad<<<TXT, 256, 0, s2>>>(Vp, Vh, TXT);
    tohalf_pad<<<IMGP, 256, 0, s2>>>(Vip, Vih, IMG);
    wT_kernel<<<dim3(DIM / 32, DIM / 32), dim3(32, 8), 0, s2>>>(Wo, WoT);
    cudaEventRecord(evKV, s2);

    // main: input conversions + Q projection half 0
    long n4 = (long)NQ * DIM / 4;
    tohalf_flat<<<(unsigned)((n4 + 255) / 256), 256>>>(x, xh, n4);
    wT_kernel<<<dim3(DIM / 32, DIM / 32), dim3(32, 8)>>>(Wq, WqT);
    gemm_mma_f16<<<dim3(DIM / 128, HALF / 128), 256, gemm_smem>>>(xh, WqT, bq, Qp);
    cudaEventRecord(evA, 0);

    // s1: half-0 tail — rmsnorm(h0) -> attn(h0) -> outproj(h0)
    cudaStreamWaitEvent(s1, evA, 0);
    rmsnorm_single<<<HALF, 256, 0, s1>>>(Qp, gq, scale, Qh, HALF);
    cudaStreamWaitEvent(s1, evKV, 0);
    attn_mma<<<dim3(HALF / 128, HEADS), 256, attn_smem, s1>>>(0);
    gemm_mma_f16<<<dim3(DIM / 128, HALF / 128), 256, gemm_smem, s1>>>(Oh, WoT, bo, out);
    cudaEventRecord(evS1, s1);

    // main: half-1 chain
    gemm_mma_f16<<<dim3(DIM / 128, HALF / 128), 256, gemm_smem>>>(
        xh + (long)HALF * DIM, WqT, bq, Qp + (long)HALF * DIM);
    rmsnorm_single<<<HALF, 256>>>(Qp + (long)HALF * DIM, gq, scale, Qh + (long)HALF * DIM, HALF);
    cudaStreamWaitEvent(0, evKV, 0);
    attn_mma<<<dim3(HALF / 128, HEADS), 256, attn_smem>>>(HALF / 128);
    gemm_mma_f16<<<dim3(DIM / 128, HALF / 128), 256, gemm_smem>>>(
        Oh + (long)HALF * DIM, WoT, bo, out + (long)HALF * DIM);

    // join
    cudaStreamWaitEvent(0, evS1, 0);
}